// round 3
// baseline (speedup 1.0000x reference)
#include <cuda_runtime.h>
#include <math.h>

// Problem constants
#define Bsz 4
#define Ssz 2048
#define Dsz 1024
#define Hh  16
#define DKk 64   // Dsz / Hh

// Scratch (device globals: allocation-free per harness rules)
__device__ float g_Q[(long long)Bsz * Ssz * Dsz];
__device__ float g_K[(long long)Bsz * Ssz * Dsz];
__device__ float g_V[(long long)Bsz * Ssz * Dsz];
__device__ float g_CTX[(long long)Bsz * Ssz * Dsz];

// ---------------------------------------------------------------------------
// Tiled NT GEMM: C[m,n] = sum_k A[m,k] * W[n,k]  (+ bias[n])
// Block computes a 64x64 tile of C. BK=16. 256 threads, 4x4 microtile each.
// Global loads for slab k+1 are issued before consuming slab k (register
// prefetch) so L2/DRAM latency overlaps the FFMA block.
// ---------------------------------------------------------------------------
__device__ __forceinline__ void gemm64(const float* __restrict__ A,
                                       const float* __restrict__ W,
                                       float* __restrict__ C,
                                       const float* __restrict__ bias,
                                       int K, int N) {
    __shared__ float As[16][64];
    __shared__ float Ws[16][64];

    const int tid = threadIdx.x;
    const int ty = tid >> 4;          // 0..15
    const int tx = tid & 15;          // 0..15
    const int lr = tid >> 2;          // 0..63  (tile row for loads)
    const int lc = (tid & 3) * 4;     // 0,4,8,12 (k offset for loads)
    const int bm = blockIdx.y * 64;
    const int bn = blockIdx.x * 64;

    const float* Aptr = A + (long long)(bm + lr) * K + lc;
    const float* Wptr = W + (long long)(bn + lr) * K + lc;

    float acc[4][4] = {};

    float4 a = *(const float4*)(Aptr);
    float4 w = *(const float4*)(Wptr);

    for (int k0 = 0; k0 < K; k0 += 16) {
        As[lc + 0][lr] = a.x; As[lc + 1][lr] = a.y;
        As[lc + 2][lr] = a.z; As[lc + 3][lr] = a.w;
        Ws[lc + 0][lr] = w.x; Ws[lc + 1][lr] = w.y;
        Ws[lc + 2][lr] = w.z; Ws[lc + 3][lr] = w.w;
        __syncthreads();

        // Prefetch next slab while computing on this one
        if (k0 + 16 < K) {
            a = *(const float4*)(Aptr + k0 + 16);
            w = *(const float4*)(Wptr + k0 + 16);
        }

#pragma unroll
        for (int kk = 0; kk < 16; kk++) {
            float4 av = *(const float4*)&As[kk][ty * 4];
            float4 wv = *(const float4*)&Ws[kk][tx * 4];
            float aa[4] = {av.x, av.y, av.z, av.w};
            float ww[4] = {wv.x, wv.y, wv.z, wv.w};
#pragma unroll
            for (int i = 0; i < 4; i++)
#pragma unroll
                for (int j = 0; j < 4; j++)
                    acc[i][j] += aa[i] * ww[j];
        }
        __syncthreads();
    }

#pragma unroll
    for (int i = 0; i < 4; i++) {
        float* crow = C + (long long)(bm + ty * 4 + i) * N + bn + tx * 4;
#pragma unroll
        for (int j = 0; j < 4; j++) {
            float v = acc[i][j];
            if (bias) v += bias[bn + tx * 4 + j];
            crow[j] = v;
        }
    }
}

// One launch computes Q, K, V via blockIdx.z
__global__ __launch_bounds__(256)
void qkv_gemm_kernel(const float* __restrict__ x,
                     const float* __restrict__ wq,
                     const float* __restrict__ wk,
                     const float* __restrict__ wv) {
    const float* W;
    float* C;
    if (blockIdx.z == 0)      { W = wq; C = g_Q; }
    else if (blockIdx.z == 1) { W = wk; C = g_K; }
    else                      { W = wv; C = g_V; }
    gemm64(x, W, C, nullptr, Dsz, Dsz);
}

__global__ __launch_bounds__(256)
void out_gemm_kernel(const float* __restrict__ wo,
                     const float* __restrict__ bo,
                     float* __restrict__ out) {
    gemm64(g_CTX, wo, out, bo, Dsz, Dsz);
}

// ---------------------------------------------------------------------------
// Flash attention, fp32, causal. Block = 64 queries of one (b,h).
// Q/K stored transposed in smem ([d][row]) so the score GEMM reads are
// conflict-free; P stored [q][k] (contiguous float4 stores) for the PV GEMM.
// Online softmax state (m,l) replicated across the 16 lanes of each row group
// via xor-shuffles (offsets 1,2,4,8 stay inside the 16-lane group).
// ---------------------------------------------------------------------------
__global__ __launch_bounds__(256)
void attn_kernel() {
    __shared__ float Qs[64][64];    // [d][q]
    __shared__ float KPs[64][64];   // phase 1: K as [d][k]; phase 2: P as [q][k]
    __shared__ float Vs[64][64];    // [k][d]

    const int tid = threadIdx.x;
    const int ty = tid >> 4;        // 0..15 -> 4 query rows
    const int tx = tid & 15;        // 0..15 -> 4 key cols / 4 d cols
    const int rr = tid >> 4;        // load row base
    const int cc = (tid & 15) * 4;  // load col (d) offset

    const int bh = blockIdx.y;
    const int b = bh >> 4;          // H = 16
    const int h = bh & 15;
    const int q0 = blockIdx.x * 64;

    const float* Qp = g_Q + (long long)b * Ssz * Dsz + h * DKk;
    const float* Kp = g_K + (long long)b * Ssz * Dsz + h * DKk;
    const float* Vp = g_V + (long long)b * Ssz * Dsz + h * DKk;

    // Load Q tile transposed: Qs[d][q]
#pragma unroll
    for (int ch = 0; ch < 4; ch++) {
        int row = rr + ch * 16;
        float4 v = *(const float4*)(Qp + (long long)(q0 + row) * Dsz + cc);
        Qs[cc + 0][row] = v.x; Qs[cc + 1][row] = v.y;
        Qs[cc + 2][row] = v.z; Qs[cc + 3][row] = v.w;
    }

    float o[4][4] = {};
    float m[4], l[4];
#pragma unroll
    for (int i = 0; i < 4; i++) { m[i] = -1e30f; l[i] = 0.0f; }

    const unsigned FULL = 0xffffffffu;
    const int ktiles = blockIdx.x + 1;   // causal: skip tiles fully above diag

    for (int kt = 0; kt < ktiles; kt++) {
        // Load K (transposed) and V (direct) tiles
#pragma unroll
        for (int ch = 0; ch < 4; ch++) {
            int row = rr + ch * 16;
            const float* kr = Kp + (long long)(kt * 64 + row) * Dsz + cc;
            float4 kv = *(const float4*)kr;
            KPs[cc + 0][row] = kv.x; KPs[cc + 1][row] = kv.y;
            KPs[cc + 2][row] = kv.z; KPs[cc + 3][row] = kv.w;
            const float* vr = Vp + (long long)(kt * 64 + row) * Dsz + cc;
            *(float4*)&Vs[row][cc] = *(const float4*)vr;
        }
        __syncthreads();

        // Scores: S[q][k] = sum_d Qs[d][q] * KPs[d][k]
        float s[4][4] = {};
#pragma unroll 16
        for (int kk = 0; kk < 64; kk++) {
            float4 qv = *(const float4*)&Qs[kk][ty * 4];
            float4 kv = *(const float4*)&KPs[kk][tx * 4];
            float qa[4] = {qv.x, qv.y, qv.z, qv.w};
            float ka[4] = {kv.x, kv.y, kv.z, kv.w};
#pragma unroll
            for (int i = 0; i < 4; i++)
#pragma unroll
                for (int j = 0; j < 4; j++)
                    s[i][j] += qa[i] * ka[j];
        }

        // Scale + causal mask (only the diagonal tile needs masking)
        const bool diag = (kt == (int)blockIdx.x);
#pragma unroll
        for (int i = 0; i < 4; i++)
#pragma unroll
            for (int j = 0; j < 4; j++) {
                float v = s[i][j] * 0.125f;  // 1/sqrt(64)
                if (diag && (tx * 4 + j) > (ty * 4 + i)) v = -1e30f;
                s[i][j] = v;
            }

        // Online softmax per query row (rows owned by the 16 lanes sharing ty)
#pragma unroll
        for (int i = 0; i < 4; i++) {
            float rm = fmaxf(fmaxf(s[i][0], s[i][1]), fmaxf(s[i][2], s[i][3]));
#pragma unroll
            for (int off = 8; off > 0; off >>= 1)
                rm = fmaxf(rm, __shfl_xor_sync(FULL, rm, off));
            float mn = fmaxf(m[i], rm);
            float alpha = __expf(m[i] - mn);
            float rs = 0.0f;
#pragma unroll
            for (int j = 0; j < 4; j++) {
                s[i][j] = __expf(s[i][j] - mn);
                rs += s[i][j];
            }
#pragma unroll
            for (int off = 8; off > 0; off >>= 1)
                rs += __shfl_xor_sync(FULL, rs, off);
            m[i] = mn;
            l[i] = l[i] * alpha + rs;
#pragma unroll
            for (int j = 0; j < 4; j++) o[i][j] *= alpha;
        }
        __syncthreads();   // all done reading K from KPs

        // Store P as [q][k] (contiguous float4 per thread: conflict-free)
#pragma unroll
        for (int i = 0; i < 4; i++) {
            float4 pv = make_float4(s[i][0], s[i][1], s[i][2], s[i][3]);
            *(float4*)&KPs[ty * 4 + i][tx * 4] = pv;
        }
        __syncthreads();

        // O[q][d] += sum_k P[q][k] * V[k][d]
#pragma unroll
        for (int kk = 0; kk < 64; kk += 4) {
            float4 p0 = *(const float4*)&KPs[ty * 4 + 0][kk];
            float4 p1 = *(const float4*)&KPs[ty * 4 + 1][kk];
            float4 p2 = *(const float4*)&KPs[ty * 4 + 2][kk];
            float4 p3 = *(const float4*)&KPs[ty * 4 + 3][kk];
            float4 v0 = *(const float4*)&Vs[kk + 0][tx * 4];
            float4 v1 = *(const float4*)&Vs[kk + 1][tx * 4];
            float4 v2 = *(const float4*)&Vs[kk + 2][tx * 4];
            float4 v3 = *(const float4*)&Vs[kk + 3][tx * 4];
            float pr[4][4] = {{p0.x, p0.y, p0.z, p0.w},
                              {p1.x, p1.y, p1.z, p1.w},
                              {p2.x, p2.y, p2.z, p2.w},
                              {p3.x, p3.y, p3.z, p3.w}};
            float vr[4][4] = {{v0.x, v0.y, v0.z, v0.w},
                              {v1.x, v1.y, v1.z, v1.w},
                              {v2.x, v2.y, v2.z, v2.w},
                              {v3.x, v3.y, v3.z, v3.w}};
#pragma unroll
            for (int i = 0; i < 4; i++)
#pragma unroll
                for (int j = 0; j < 4; j++) {
                    o[i][j] += pr[i][0] * vr[0][j];
                    o[i][j] += pr[i][1] * vr[1][j];
                    o[i][j] += pr[i][2] * vr[2][j];
                    o[i][j] += pr[i][3] * vr[3][j];
                }
        }
        __syncthreads();   // done reading P/V before next tile's loads
    }

    // Normalize and write ctx in [B,S,D] layout (implicit head transpose-back)
    float* Cp = g_CTX + (long long)b * Ssz * Dsz + h * DKk;
#pragma unroll
    for (int i = 0; i < 4; i++) {
        float inv = 1.0f / l[i];
        float* row = Cp + (long long)(q0 + ty * 4 + i) * Dsz + tx * 4;
#pragma unroll
        for (int j = 0; j < 4; j++) row[j] = o[i][j] * inv;
    }
}

// ---------------------------------------------------------------------------
extern "C" void kernel_launch(void* const* d_in, const int* in_sizes, int n_in,
                              void* d_out, int out_size) {
    const float* x  = (const float*)d_in[0];
    const float* wq = (const float*)d_in[1];
    const float* wk = (const float*)d_in[2];
    const float* wv = (const float*)d_in[3];
    const float* wo = (const float*)d_in[4];
    const float* bo = (const float*)d_in[5];
    float* out = (float*)d_out;

    dim3 blk(256);
    dim3 g1(Dsz / 64, (Bsz * Ssz) / 64, 3);
    qkv_gemm_kernel<<<g1, blk>>>(x, wq, wk, wv);

    dim3 g2(Ssz / 64, Bsz * Hh);
    attn_kernel<<<g2, blk>>>();

    dim3 g3(Dsz / 64, (Bsz * Ssz) / 64);
    out_gemm_kernel<<<g3, blk>>>(wo, bo, out);
}

// round 5
// speedup vs baseline: 1.7293x; 1.7293x over previous
#include <cuda_runtime.h>
#include <cuda_bf16.h>
#include <math.h>
#include <cstdint>

// Problem constants
#define Bsz 4
#define Ssz 2048
#define Dsz 1024
#define Hh  16
#define DKk 64   // Dsz / Hh
#define Mrows (Bsz * Ssz)   // 8192

// ---------------------------------------------------------------------------
// Scratch (device globals: allocation-free per harness rules)
// ---------------------------------------------------------------------------
__device__ float g_Q[(long long)Bsz * Ssz * Dsz];
__device__ float g_K[(long long)Bsz * Ssz * Dsz];
__device__ float g_V[(long long)Bsz * Ssz * Dsz];
__device__ float g_CTX[(long long)Bsz * Ssz * Dsz];

// split-bf16 operands
__device__ unsigned short g_xhi[(long long)Mrows * Dsz];
__device__ unsigned short g_xlo[(long long)Mrows * Dsz];
__device__ unsigned short g_chi[(long long)Mrows * Dsz];
__device__ unsigned short g_clo[(long long)Mrows * Dsz];
__device__ unsigned short g_whi[4ll * Dsz * Dsz];   // wq,wk,wv,wo
__device__ unsigned short g_wlo[4ll * Dsz * Dsz];

// ---------------------------------------------------------------------------
// PTX helpers (portable ISA only: ldmatrix + mma.sync, sm_80+)
// ---------------------------------------------------------------------------
__device__ __forceinline__ uint32_t smem_to_u32(const void* p) {
    uint32_t a;
    asm("{ .reg .u64 t; cvta.to.shared.u64 t, %1; cvt.u32.u64 %0, t; }"
        : "=r"(a) : "l"(p));
    return a;
}

__device__ __forceinline__ void ldsm4(uint32_t* r, uint32_t addr) {
    asm volatile("ldmatrix.sync.aligned.m8n8.x4.shared.b16 {%0,%1,%2,%3}, [%4];"
                 : "=r"(r[0]), "=r"(r[1]), "=r"(r[2]), "=r"(r[3]) : "r"(addr));
}

__device__ __forceinline__ void mma16816(float* d, const uint32_t* a,
                                         const uint32_t* b) {
    asm volatile(
        "mma.sync.aligned.m16n8k16.row.col.f32.bf16.bf16.f32 "
        "{%0,%1,%2,%3}, {%4,%5,%6,%7}, {%8,%9}, {%0,%1,%2,%3};"
        : "+f"(d[0]), "+f"(d[1]), "+f"(d[2]), "+f"(d[3])
        : "r"(a[0]), "r"(a[1]), "r"(a[2]), "r"(a[3]), "r"(b[0]), "r"(b[1]));
}

// ---------------------------------------------------------------------------
// fp32 -> (bf16 hi, bf16 lo) split conversion
// ---------------------------------------------------------------------------
__device__ __forceinline__ unsigned short f2bf_raw(float f) {
    __nv_bfloat16 b = __float2bfloat16(f);
    return *reinterpret_cast<unsigned short*>(&b);
}
__global__ __launch_bounds__(256)
void convert_split_kernel(const float4* __restrict__ src,
                          uint2* __restrict__ hi, uint2* __restrict__ lo, int n4) {
    int i = blockIdx.x * blockDim.x + threadIdx.x;
    if (i >= n4) return;
    float4 v = src[i];
    unsigned short h0 = f2bf_raw(v.x), h1 = f2bf_raw(v.y);
    unsigned short h2 = f2bf_raw(v.z), h3 = f2bf_raw(v.w);
    __nv_bfloat16 b0 = *reinterpret_cast<__nv_bfloat16*>(&h0);
    __nv_bfloat16 b1 = *reinterpret_cast<__nv_bfloat16*>(&h1);
    __nv_bfloat16 b2 = *reinterpret_cast<__nv_bfloat16*>(&h2);
    __nv_bfloat16 b3 = *reinterpret_cast<__nv_bfloat16*>(&h3);
    unsigned short l0 = f2bf_raw(v.x - __bfloat162float(b0));
    unsigned short l1 = f2bf_raw(v.y - __bfloat162float(b1));
    unsigned short l2 = f2bf_raw(v.z - __bfloat162float(b2));
    unsigned short l3 = f2bf_raw(v.w - __bfloat162float(b3));
    hi[i] = make_uint2((uint32_t)h0 | ((uint32_t)h1 << 16),
                       (uint32_t)h2 | ((uint32_t)h3 << 16));
    lo[i] = make_uint2((uint32_t)l0 | ((uint32_t)l1 << 16),
                       (uint32_t)l2 | ((uint32_t)l3 << 16));
}

// ---------------------------------------------------------------------------
// Split-bf16 NT GEMM on mma.sync: C[m,n] = A[m,:] . W[n,:]  (+bias)
// CTA 128x128, BK=32, 8 warps (4m x 2n), warp tile 32x64.
// smem rows: 32 bf16 + 16B pad = 80B (conflict-free ldmatrix phases).
// Per k16 step: 3 MMAs per (m,n) microtile (hi*hi + hi*lo + lo*hi).
// ---------------------------------------------------------------------------
#define ROWB 80
#define MATB (128 * ROWB)         // 10240 B per operand tile
#define GEMM_SMEM_TOTAL (2 * 4 * MATB)   // 81920 B
#define NCHUNK (Dsz / 32)         // 32

__device__ __forceinline__ void gemm_mma(const unsigned short* __restrict__ Ahi,
                                         const unsigned short* __restrict__ Alo,
                                         const unsigned short* __restrict__ Whi,
                                         const unsigned short* __restrict__ Wlo,
                                         float* __restrict__ C,
                                         const float* __restrict__ bias) {
    extern __shared__ char smem[];
    const uint32_t sbase = smem_to_u32(smem);
    const int tid = threadIdx.x;
    const int wid = tid >> 5;
    const int lane = tid & 31;
    const int wm = wid & 3;         // warp m index (0..3) -> m offset wm*32
    const int wn = wid >> 2;        // warp n index (0..1) -> n offset wn*64
    const int bm = blockIdx.y * 128;
    const int bn = blockIdx.x * 128;

    // global load geometry: 512 16B segments per operand tile, 2 per thread
    const int s0 = tid;             // seg id: row = s>>2, segcol = s&3
    const int s1 = tid + 256;
    const int r0g = s0 >> 2, c0g = (s0 & 3) * 8;
    const int r1g = s1 >> 2, c1g = (s1 & 3) * 8;

    const unsigned short* gp[4] = {Ahi, Alo, Whi, Wlo};
    const long long rowbase[4] = {
        (long long)(bm + r0g) * Dsz, (long long)(bm + r0g) * Dsz,
        (long long)(bn + r0g) * Dsz, (long long)(bn + r0g) * Dsz};
    const long long rowbase1[4] = {
        (long long)(bm + r1g) * Dsz, (long long)(bm + r1g) * Dsz,
        (long long)(bn + r1g) * Dsz, (long long)(bn + r1g) * Dsz};

    float acc[2][8][4] = {};
    uint4 pf[8];

    auto load_regs = [&](int c) {
        const int k0 = c * 32;
#pragma unroll
        for (int m = 0; m < 4; m++) {
            pf[m * 2 + 0] = *(const uint4*)(gp[m] + rowbase[m] + k0 + c0g);
            pf[m * 2 + 1] = *(const uint4*)(gp[m] + rowbase1[m] + k0 + c1g);
        }
    };
    auto store_smem = [&](int buf) {
        char* b = smem + buf * 4 * MATB;
#pragma unroll
        for (int m = 0; m < 4; m++) {
            *(uint4*)(b + m * MATB + r0g * ROWB + (s0 & 3) * 16) = pf[m * 2 + 0];
            *(uint4*)(b + m * MATB + r1g * ROWB + (s1 & 3) * 16) = pf[m * 2 + 1];
        }
    };

    // ldmatrix lane geometry
    const int mtx = lane >> 3;      // which 8x8 matrix this lane addresses
    const int r8 = lane & 7;
    // A: mtx0 rows0-7/kseg0, mtx1 rows8-15/kseg0, mtx2 rows0-7/kseg1, mtx3 rows8-15/kseg1
    const int a_rowoff = (mtx & 1) * 8 + r8;
    const int a_segoff = (mtx >> 1);
    // B: mtx0 n0-7/kseg0, mtx1 n0-7/kseg1, mtx2 n8-15/kseg0, mtx3 n8-15/kseg1
    const int b_rowoff = (mtx >> 1) * 8 + r8;
    const int b_segoff = (mtx & 1);

    auto compute = [&](int buf) {
        const uint32_t ahb = sbase + buf * 4 * MATB;
        const uint32_t alb = ahb + MATB;
        const uint32_t bhb = ahb + 2 * MATB;
        const uint32_t blb = ahb + 3 * MATB;
#pragma unroll
        for (int ks = 0; ks < 2; ks++) {
            uint32_t ah[2][4], al[2][4];
#pragma unroll
            for (int mt = 0; mt < 2; mt++) {
                uint32_t ao = (uint32_t)(wm * 32 + mt * 16 + a_rowoff) * ROWB +
                              (uint32_t)(ks * 2 + a_segoff) * 16;
                ldsm4(ah[mt], ahb + ao);
                ldsm4(al[mt], alb + ao);
            }
#pragma unroll
            for (int np = 0; np < 4; np++) {
                uint32_t bo = (uint32_t)(wn * 64 + np * 16 + b_rowoff) * ROWB +
                              (uint32_t)(ks * 2 + b_segoff) * 16;
                uint32_t bh[4], bl[4];
                ldsm4(bh, bhb + bo);
                ldsm4(bl, blb + bo);
#pragma unroll
                for (int half = 0; half < 2; half++) {
                    const int nt = np * 2 + half;
#pragma unroll
                    for (int mt = 0; mt < 2; mt++) {
                        mma16816(acc[mt][nt], ah[mt], &bh[half * 2]);
                        mma16816(acc[mt][nt], ah[mt], &bl[half * 2]);
                        mma16816(acc[mt][nt], al[mt], &bh[half * 2]);
                    }
                }
            }
        }
    };

    load_regs(0);
    store_smem(0);
    __syncthreads();
    for (int c = 0; c < NCHUNK; c++) {
        if (c + 1 < NCHUNK) load_regs(c + 1);
        compute(c & 1);
        if (c + 1 < NCHUNK) {
            store_smem((c + 1) & 1);
            __syncthreads();
        }
    }

    // Epilogue: C frag m16n8 -> lane(g,t): {c0,c1}=C[g][2t,2t+1], {c2,c3}=C[g+8]
    const int g = lane >> 2, t = lane & 3;
#pragma unroll
    for (int mt = 0; mt < 2; mt++) {
#pragma unroll
        for (int nt = 0; nt < 8; nt++) {
            const int col = bn + wn * 64 + nt * 8 + t * 2;
            const int row0 = bm + wm * 32 + mt * 16 + g;
            float2 v0 = make_float2(acc[mt][nt][0], acc[mt][nt][1]);
            float2 v1 = make_float2(acc[mt][nt][2], acc[mt][nt][3]);
            if (bias) {
                float2 bb = *(const float2*)(bias + col);
                v0.x += bb.x; v0.y += bb.y;
                v1.x += bb.x; v1.y += bb.y;
            }
            *(float2*)(C + (long long)row0 * Dsz + col) = v0;
            *(float2*)(C + (long long)(row0 + 8) * Dsz + col) = v1;
        }
    }
}

__global__ __launch_bounds__(256, 1)
void qkv_mma_kernel() {
    const unsigned short* Whi = g_whi + (long long)blockIdx.z * Dsz * Dsz;
    const unsigned short* Wlo = g_wlo + (long long)blockIdx.z * Dsz * Dsz;
    float* C = (blockIdx.z == 0) ? g_Q : (blockIdx.z == 1) ? g_K : g_V;
    gemm_mma(g_xhi, g_xlo, Whi, Wlo, C, nullptr);
}

__global__ __launch_bounds__(256, 1)
void out_mma_kernel(const float* __restrict__ bo, float* __restrict__ out) {
    const unsigned short* Whi = g_whi + 3ll * Dsz * Dsz;
    const unsigned short* Wlo = g_wlo + 3ll * Dsz * Dsz;
    gemm_mma(g_chi, g_clo, Whi, Wlo, out, bo);
}

// ---------------------------------------------------------------------------
// Flash attention, fp32, causal (unchanged from passing baseline).
// ---------------------------------------------------------------------------
__global__ __launch_bounds__(256)
void attn_kernel() {
    __shared__ float Qs[64][64];
    __shared__ float KPs[64][64];
    __shared__ float Vs[64][64];

    const int tid = threadIdx.x;
    const int ty = tid >> 4;
    const int tx = tid & 15;
    const int rr = tid >> 4;
    const int cc = (tid & 15) * 4;

    const int bh = blockIdx.y;
    const int b = bh >> 4;
    const int h = bh & 15;
    const int q0 = blockIdx.x * 64;

    const float* Qp = g_Q + (long long)b * Ssz * Dsz + h * DKk;
    const float* Kp = g_K + (long long)b * Ssz * Dsz + h * DKk;
    const float* Vp = g_V + (long long)b * Ssz * Dsz + h * DKk;

#pragma unroll
    for (int ch = 0; ch < 4; ch++) {
        int row = rr + ch * 16;
        float4 v = *(const float4*)(Qp + (long long)(q0 + row) * Dsz + cc);
        Qs[cc + 0][row] = v.x; Qs[cc + 1][row] = v.y;
        Qs[cc + 2][row] = v.z; Qs[cc + 3][row] = v.w;
    }

    float o[4][4] = {};
    float m[4], l[4];
#pragma unroll
    for (int i = 0; i < 4; i++) { m[i] = -1e30f; l[i] = 0.0f; }

    const unsigned FULL = 0xffffffffu;
    const int ktiles = blockIdx.x + 1;

    for (int kt = 0; kt < ktiles; kt++) {
#pragma unroll
        for (int ch = 0; ch < 4; ch++) {
            int row = rr + ch * 16;
            const float* kr = Kp + (long long)(kt * 64 + row) * Dsz + cc;
            float4 kv = *(const float4*)kr;
            KPs[cc + 0][row] = kv.x; KPs[cc + 1][row] = kv.y;
            KPs[cc + 2][row] = kv.z; KPs[cc + 3][row] = kv.w;
            const float* vr = Vp + (long long)(kt * 64 + row) * Dsz + cc;
            *(float4*)&Vs[row][cc] = *(const float4*)vr;
        }
        __syncthreads();

        float s[4][4] = {};
#pragma unroll 16
        for (int kk = 0; kk < 64; kk++) {
            float4 qv = *(const float4*)&Qs[kk][ty * 4];
            float4 kv = *(const float4*)&KPs[kk][tx * 4];
            float qa[4] = {qv.x, qv.y, qv.z, qv.w};
            float ka[4] = {kv.x, kv.y, kv.z, kv.w};
#pragma unroll
            for (int i = 0; i < 4; i++)
#pragma unroll
                for (int j = 0; j < 4; j++)
                    s[i][j] += qa[i] * ka[j];
        }

        const bool diag = (kt == (int)blockIdx.x);
#pragma unroll
        for (int i = 0; i < 4; i++)
#pragma unroll
            for (int j = 0; j < 4; j++) {
                float v = s[i][j] * 0.125f;
                if (diag && (tx * 4 + j) > (ty * 4 + i)) v = -1e30f;
                s[i][j] = v;
            }

#pragma unroll
        for (int i = 0; i < 4; i++) {
            float rm = fmaxf(fmaxf(s[i][0], s[i][1]), fmaxf(s[i][2], s[i][3]));
#pragma unroll
            for (int off = 8; off > 0; off >>= 1)
                rm = fmaxf(rm, __shfl_xor_sync(FULL, rm, off));
            float mn = fmaxf(m[i], rm);
            float alpha = __expf(m[i] - mn);
            float rs = 0.0f;
#pragma unroll
            for (int j = 0; j < 4; j++) {
                s[i][j] = __expf(s[i][j] - mn);
                rs += s[i][j];
            }
#pragma unroll
            for (int off = 8; off > 0; off >>= 1)
                rs += __shfl_xor_sync(FULL, rs, off);
            m[i] = mn;
            l[i] = l[i] * alpha + rs;
#pragma unroll
            for (int j = 0; j < 4; j++) o[i][j] *= alpha;
        }
        __syncthreads();

#pragma unroll
        for (int i = 0; i < 4; i++) {
            float4 pv = make_float4(s[i][0], s[i][1], s[i][2], s[i][3]);
            *(float4*)&KPs[ty * 4 + i][tx * 4] = pv;
        }
        __syncthreads();

#pragma unroll
        for (int kk = 0; kk < 64; kk += 4) {
            float4 p0 = *(const float4*)&KPs[ty * 4 + 0][kk];
            float4 p1 = *(const float4*)&KPs[ty * 4 + 1][kk];
            float4 p2 = *(const float4*)&KPs[ty * 4 + 2][kk];
            float4 p3 = *(const float4*)&KPs[ty * 4 + 3][kk];
            float4 v0 = *(const float4*)&Vs[kk + 0][tx * 4];
            float4 v1 = *(const float4*)&Vs[kk + 1][tx * 4];
            float4 v2 = *(const float4*)&Vs[kk + 2][tx * 4];
            float4 v3 = *(const float4*)&Vs[kk + 3][tx * 4];
            float pr[4][4] = {{p0.x, p0.y, p0.z, p0.w},
                              {p1.x, p1.y, p1.z, p1.w},
                              {p2.x, p2.y, p2.z, p2.w},
                              {p3.x, p3.y, p3.z, p3.w}};
            float vr[4][4] = {{v0.x, v0.y, v0.z, v0.w},
                              {v1.x, v1.y, v1.z, v1.w},
                              {v2.x, v2.y, v2.z, v2.w},
                              {v3.x, v3.y, v3.z, v3.w}};
#pragma unroll
            for (int i = 0; i < 4; i++)
#pragma unroll
                for (int j = 0; j < 4; j++) {
                    o[i][j] += pr[i][0] * vr[0][j];
                    o[i][j] += pr[i][1] * vr[1][j];
                    o[i][j] += pr[i][2] * vr[2][j];
                    o[i][j] += pr[i][3] * vr[3][j];
                }
        }
        __syncthreads();
    }

    float* Cp = g_CTX + (long long)b * Ssz * Dsz + h * DKk;
#pragma unroll
    for (int i = 0; i < 4; i++) {
        float inv = 1.0f / l[i];
        float* row = Cp + (long long)(q0 + ty * 4 + i) * Dsz + tx * 4;
#pragma unroll
        for (int j = 0; j < 4; j++) row[j] = o[i][j] * inv;
    }
}

// ---------------------------------------------------------------------------
extern "C" void kernel_launch(void* const* d_in, const int* in_sizes, int n_in,
                              void* d_out, int out_size) {
    const float* x  = (const float*)d_in[0];
    const float* wq = (const float*)d_in[1];
    const float* wk = (const float*)d_in[2];
    const float* wv = (const float*)d_in[3];
    const float* wo = (const float*)d_in[4];
    const float* bo = (const float*)d_in[5];
    float* out = (float*)d_out;

    cudaFuncSetAttribute(qkv_mma_kernel,
                         cudaFuncAttributeMaxDynamicSharedMemorySize, GEMM_SMEM_TOTAL);
    cudaFuncSetAttribute(out_mma_kernel,
                         cudaFuncAttributeMaxDynamicSharedMemorySize, GEMM_SMEM_TOTAL);

    unsigned short *xhi, *xlo, *chi, *clo, *whi, *wlo;
    float* ctx;
    cudaGetSymbolAddress((void**)&xhi, g_xhi);
    cudaGetSymbolAddress((void**)&xlo, g_xlo);
    cudaGetSymbolAddress((void**)&chi, g_chi);
    cudaGetSymbolAddress((void**)&clo, g_clo);
    cudaGetSymbolAddress((void**)&whi, g_whi);
    cudaGetSymbolAddress((void**)&wlo, g_wlo);
    cudaGetSymbolAddress((void**)&ctx, g_CTX);

    const int n4x = Mrows * Dsz / 4;
    const int n4w = Dsz * Dsz / 4;

    convert_split_kernel<<<(n4x + 255) / 256, 256>>>(
        (const float4*)x, (uint2*)xhi, (uint2*)xlo, n4x);
    convert_split_kernel<<<(n4w + 255) / 256, 256>>>(
        (const float4*)wq, (uint2*)(whi + 0ll * Dsz * Dsz), (uint2*)(wlo + 0ll * Dsz * Dsz), n4w);
    convert_split_kernel<<<(n4w + 255) / 256, 256>>>(
        (const float4*)wk, (uint2*)(whi + 1ll * Dsz * Dsz), (uint2*)(wlo + 1ll * Dsz * Dsz), n4w);
    convert_split_kernel<<<(n4w + 255) / 256, 256>>>(
        (const float4*)wv, (uint2*)(whi + 2ll * Dsz * Dsz), (uint2*)(wlo + 2ll * Dsz * Dsz), n4w);
    convert_split_kernel<<<(n4w + 255) / 256, 256>>>(
        (const float4*)wo, (uint2*)(whi + 3ll * Dsz * Dsz), (uint2*)(wlo + 3ll * Dsz * Dsz), n4w);

    dim3 g1(Dsz / 128, Mrows / 128, 3);
    qkv_mma_kernel<<<g1, 256, GEMM_SMEM_TOTAL>>>();

    dim3 g2(Ssz / 64, Bsz * Hh);
    attn_kernel<<<g2, 256>>>();

    convert_split_kernel<<<(n4x + 255) / 256, 256>>>(
        (const float4*)ctx, (uint2*)chi, (uint2*)clo, n4x);
    dim3 g3(Dsz / 128, Mrows / 128);
    out_mma_kernel<<<g3, 256, GEMM_SMEM_TOTAL>>>(bo, out);
}

// round 7
// speedup vs baseline: 3.0948x; 1.7896x over previous
#include <cuda_runtime.h>
#include <cuda_bf16.h>
#include <math.h>
#include <cstdint>

// Problem constants
#define Bsz 4
#define Ssz 2048
#define Dsz 1024
#define Hh  16
#define DKk 64
#define Mrows (Bsz * Ssz)   // 8192

// ---------------------------------------------------------------------------
// Scratch (device globals)
// ---------------------------------------------------------------------------
__device__ unsigned short g_xhi[(long long)Mrows * Dsz];
__device__ unsigned short g_xlo[(long long)Mrows * Dsz];
__device__ unsigned short g_chi[(long long)Mrows * Dsz];
__device__ unsigned short g_clo[(long long)Mrows * Dsz];
__device__ unsigned short g_whi[4ll * Dsz * Dsz];
__device__ unsigned short g_wlo[4ll * Dsz * Dsz];
// Q/K/V split-bf16 in [b,h,s,dk] layout
__device__ unsigned short g_Qhi[(long long)Mrows * Dsz];
__device__ unsigned short g_Qlo[(long long)Mrows * Dsz];
__device__ unsigned short g_Khi[(long long)Mrows * Dsz];
__device__ unsigned short g_Klo[(long long)Mrows * Dsz];
__device__ unsigned short g_Vhi[(long long)Mrows * Dsz];
__device__ unsigned short g_Vlo[(long long)Mrows * Dsz];

// ---------------------------------------------------------------------------
// PTX helpers (portable ISA: ldmatrix / mma.sync / cp.async, sm_80+)
// ---------------------------------------------------------------------------
__device__ __forceinline__ uint32_t smem_to_u32(const void* p) {
    uint32_t a;
    asm("{ .reg .u64 t; cvta.to.shared.u64 t, %1; cvt.u32.u64 %0, t; }"
        : "=r"(a) : "l"(p));
    return a;
}
__device__ __forceinline__ void ldsm4(uint32_t* r, uint32_t addr) {
    asm volatile("ldmatrix.sync.aligned.m8n8.x4.shared.b16 {%0,%1,%2,%3}, [%4];"
                 : "=r"(r[0]), "=r"(r[1]), "=r"(r[2]), "=r"(r[3]) : "r"(addr));
}
__device__ __forceinline__ void ldsm4t(uint32_t* r, uint32_t addr) {
    asm volatile("ldmatrix.sync.aligned.m8n8.x4.trans.shared.b16 {%0,%1,%2,%3}, [%4];"
                 : "=r"(r[0]), "=r"(r[1]), "=r"(r[2]), "=r"(r[3]) : "r"(addr));
}
__device__ __forceinline__ void mma16816(float* d, const uint32_t* a,
                                         const uint32_t* b) {
    asm volatile(
        "mma.sync.aligned.m16n8k16.row.col.f32.bf16.bf16.f32 "
        "{%0,%1,%2,%3}, {%4,%5,%6,%7}, {%8,%9}, {%0,%1,%2,%3};"
        : "+f"(d[0]), "+f"(d[1]), "+f"(d[2]), "+f"(d[3])
        : "r"(a[0]), "r"(a[1]), "r"(a[2]), "r"(a[3]), "r"(b[0]), "r"(b[1]));
}
__device__ __forceinline__ void cp_async16(uint32_t saddr, const void* g) {
    asm volatile("cp.async.cg.shared.global [%0], [%1], 16;"
                 :: "r"(saddr), "l"(g));
}
#define CP_COMMIT() asm volatile("cp.async.commit_group;" ::: "memory")
#define CP_WAIT0()  asm volatile("cp.async.wait_group 0;" ::: "memory")

__device__ __forceinline__ uint32_t packbf(float lo, float hi) {
    uint32_t r;
    asm("cvt.rn.bf16x2.f32 %0, %1, %2;" : "=r"(r) : "f"(hi), "f"(lo));
    return r;
}
__device__ __forceinline__ float bf_round(float v) {
    return __bfloat162float(__float2bfloat16(v));
}
__device__ __forceinline__ void split2(float v0, float v1,
                                       uint32_t& hi, uint32_t& lo) {
    hi = packbf(v0, v1);
    lo = packbf(v0 - bf_round(v0), v1 - bf_round(v1));
}

// ---------------------------------------------------------------------------
// fp32 -> (bf16 hi, bf16 lo) split conversion
// ---------------------------------------------------------------------------
__global__ __launch_bounds__(256)
void convert_split_kernel(const float4* __restrict__ src,
                          uint2* __restrict__ hi, uint2* __restrict__ lo, int n4) {
    int i = blockIdx.x * blockDim.x + threadIdx.x;
    if (i >= n4) return;
    float4 v = src[i];
    uint32_t h01, l01, h23, l23;
    split2(v.x, v.y, h01, l01);
    split2(v.z, v.w, h23, l23);
    hi[i] = make_uint2(h01, h23);
    lo[i] = make_uint2(l01, l23);
}

// ---------------------------------------------------------------------------
// Split-bf16 NT GEMM (CTA 128x128, BK=32, 8 warps 4m x 2n)
// ---------------------------------------------------------------------------
#define ROWB 80
#define MATB (128 * ROWB)
#define GEMM_SMEM_TOTAL (2 * 4 * MATB)   // 81920 B
#define NCHUNK (Dsz / 32)

__device__ __forceinline__ void gemm_mma(const unsigned short* __restrict__ Ahi,
                                         const unsigned short* __restrict__ Alo,
                                         const unsigned short* __restrict__ Whi,
                                         const unsigned short* __restrict__ Wlo,
                                         float* __restrict__ C,
                                         const float* __restrict__ bias,
                                         unsigned short* __restrict__ Dhi,
                                         unsigned short* __restrict__ Dlo) {
    extern __shared__ char smem[];
    const uint32_t sbase = smem_to_u32(smem);
    const int tid = threadIdx.x;
    const int wid = tid >> 5;
    const int lane = tid & 31;
    const int wm = wid & 3;
    const int wn = wid >> 2;
    const int bm = blockIdx.y * 128;
    const int bn = blockIdx.x * 128;

    const int s0 = tid, s1 = tid + 256;
    const int r0g = s0 >> 2, c0g = (s0 & 3) * 8;
    const int r1g = s1 >> 2, c1g = (s1 & 3) * 8;

    const unsigned short* gp[4] = {Ahi, Alo, Whi, Wlo};
    const long long rowbase[4] = {
        (long long)(bm + r0g) * Dsz, (long long)(bm + r0g) * Dsz,
        (long long)(bn + r0g) * Dsz, (long long)(bn + r0g) * Dsz};
    const long long rowbase1[4] = {
        (long long)(bm + r1g) * Dsz, (long long)(bm + r1g) * Dsz,
        (long long)(bn + r1g) * Dsz, (long long)(bn + r1g) * Dsz};

    float acc[2][8][4] = {};
    uint4 pf[8];

    auto load_regs = [&](int c) {
        const int k0 = c * 32;
#pragma unroll
        for (int m = 0; m < 4; m++) {
            pf[m * 2 + 0] = *(const uint4*)(gp[m] + rowbase[m] + k0 + c0g);
            pf[m * 2 + 1] = *(const uint4*)(gp[m] + rowbase1[m] + k0 + c1g);
        }
    };
    auto store_smem = [&](int buf) {
        char* b = smem + buf * 4 * MATB;
#pragma unroll
        for (int m = 0; m < 4; m++) {
            *(uint4*)(b + m * MATB + r0g * ROWB + (s0 & 3) * 16) = pf[m * 2 + 0];
            *(uint4*)(b + m * MATB + r1g * ROWB + (s1 & 3) * 16) = pf[m * 2 + 1];
        }
    };

    const int mtx = lane >> 3;
    const int r8 = lane & 7;
    const int a_rowoff = (mtx & 1) * 8 + r8;
    const int a_segoff = (mtx >> 1);
    const int b_rowoff = (mtx >> 1) * 8 + r8;
    const int b_segoff = (mtx & 1);

    auto compute = [&](int buf) {
        const uint32_t ahb = sbase + buf * 4 * MATB;
        const uint32_t alb = ahb + MATB;
        const uint32_t bhb = ahb + 2 * MATB;
        const uint32_t blb = ahb + 3 * MATB;
#pragma unroll
        for (int ks = 0; ks < 2; ks++) {
            uint32_t ah[2][4], al[2][4];
#pragma unroll
            for (int mt = 0; mt < 2; mt++) {
                uint32_t ao = (uint32_t)(wm * 32 + mt * 16 + a_rowoff) * ROWB +
                              (uint32_t)(ks * 2 + a_segoff) * 16;
                ldsm4(ah[mt], ahb + ao);
                ldsm4(al[mt], alb + ao);
            }
#pragma unroll
            for (int np = 0; np < 4; np++) {
                uint32_t bo = (uint32_t)(wn * 64 + np * 16 + b_rowoff) * ROWB +
                              (uint32_t)(ks * 2 + b_segoff) * 16;
                uint32_t bh[4], bl[4];
                ldsm4(bh, bhb + bo);
                ldsm4(bl, blb + bo);
#pragma unroll
                for (int half = 0; half < 2; half++) {
                    const int nt = np * 2 + half;
#pragma unroll
                    for (int mt = 0; mt < 2; mt++) {
                        mma16816(acc[mt][nt], ah[mt], &bh[half * 2]);
                        mma16816(acc[mt][nt], ah[mt], &bl[half * 2]);
                        mma16816(acc[mt][nt], al[mt], &bh[half * 2]);
                    }
                }
            }
        }
    };

    load_regs(0);
    store_smem(0);
    __syncthreads();
    for (int c = 0; c < NCHUNK; c++) {
        if (c + 1 < NCHUNK) load_regs(c + 1);
        compute(c & 1);
        if (c + 1 < NCHUNK) {
            store_smem((c + 1) & 1);
            __syncthreads();
        }
    }

    const int g = lane >> 2, t = lane & 3;
    if (Dhi) {
#pragma unroll
        for (int mt = 0; mt < 2; mt++) {
#pragma unroll
            for (int nt = 0; nt < 8; nt++) {
                const int col = bn + wn * 64 + nt * 8 + t * 2;
                const int hd = col >> 6, d = col & 63;
#pragma unroll
                for (int hh = 0; hh < 2; hh++) {
                    const int row = bm + wm * 32 + mt * 16 + hh * 8 + g;
                    const int b = row >> 11, s = row & 2047;
                    const long long idx =
                        ((long long)(b * Hh + hd) * Ssz + s) * DKk + d;
                    uint32_t hiw, low;
                    split2(acc[mt][nt][hh * 2 + 0], acc[mt][nt][hh * 2 + 1],
                           hiw, low);
                    *(uint32_t*)(Dhi + idx) = hiw;
                    *(uint32_t*)(Dlo + idx) = low;
                }
            }
        }
    } else {
#pragma unroll
        for (int mt = 0; mt < 2; mt++) {
#pragma unroll
            for (int nt = 0; nt < 8; nt++) {
                const int col = bn + wn * 64 + nt * 8 + t * 2;
                const int row0 = bm + wm * 32 + mt * 16 + g;
                float2 v0 = make_float2(acc[mt][nt][0], acc[mt][nt][1]);
                float2 v1 = make_float2(acc[mt][nt][2], acc[mt][nt][3]);
                if (bias) {
                    float2 bb = *(const float2*)(bias + col);
                    v0.x += bb.x; v0.y += bb.y;
                    v1.x += bb.x; v1.y += bb.y;
                }
                *(float2*)(C + (long long)row0 * Dsz + col) = v0;
                *(float2*)(C + (long long)(row0 + 8) * Dsz + col) = v1;
            }
        }
    }
}

__global__ __launch_bounds__(256, 1)
void qkv_mma_kernel() {
    const unsigned short* Whi = g_whi + (long long)blockIdx.z * Dsz * Dsz;
    const unsigned short* Wlo = g_wlo + (long long)blockIdx.z * Dsz * Dsz;
    unsigned short* Dhi = (blockIdx.z == 0) ? g_Qhi : (blockIdx.z == 1) ? g_Khi : g_Vhi;
    unsigned short* Dlo = (blockIdx.z == 0) ? g_Qlo : (blockIdx.z == 1) ? g_Klo : g_Vlo;
    gemm_mma(g_xhi, g_xlo, Whi, Wlo, nullptr, nullptr, Dhi, Dlo);
}

__global__ __launch_bounds__(256, 1)
void out_mma_kernel(const float* __restrict__ bo, float* __restrict__ out) {
    const unsigned short* Whi = g_whi + 3ll * Dsz * Dsz;
    const unsigned short* Wlo = g_wlo + 3ll * Dsz * Dsz;
    gemm_mma(g_chi, g_clo, Whi, Wlo, out, bo, nullptr, nullptr);
}

// ---------------------------------------------------------------------------
// Tensor-core flash attention (split-bf16), causal.
// CTA: 128 queries of one (b,h); 8 warps = 4m x 2n (warp: m32 x keys64).
// PV now covers ALL 64 d columns (dp 0..3 -> 8 n-tiles).  <-- Round 6 fix
// ---------------------------------------------------------------------------
#define AP 144
#define AMAT (128 * AP)
#define SM_Q 0
#define SM_KV 36864
#define KVBUF (4 * AMAT)
#define SM_STATM (SM_KV + 2 * KVBUF)
#define SM_STATS (SM_STATM + 1024)
#define ATT_SMEM (SM_STATS + 1024)

__global__ __launch_bounds__(256)
void attn_mma_kernel() {
    extern __shared__ char smem[];
    const uint32_t sb = smem_to_u32(smem);
    const int tid = threadIdx.x;
    const int wid = tid >> 5;
    const int lane = tid & 31;
    const int wm = wid & 3;
    const int wn = wid >> 2;
    const int g = lane >> 2, t = lane & 3;
    const int mtx = lane >> 3, r8 = lane & 7;
    const int a_rowoff = (mtx & 1) * 8 + r8;
    const int a_segoff = (mtx >> 1);
    const int b_rowoff = (mtx >> 1) * 8 + r8;
    const int b_segoff = (mtx & 1);

    const int qb = (Ssz / 128 - 1) - blockIdx.x;
    const int q0 = qb * 128;
    const int bh = blockIdx.y;
    const int b = bh >> 4, h = bh & 15;
    const long long base = (long long)bh * Ssz * DKk;

    for (int i = tid; i < 1024; i += 256) {
        int r = i >> 3, c = i & 7;
        *(uint4*)(smem + SM_Q + r * AP + c * 16) =
            *(const uint4*)(g_Qhi + base + (long long)(q0 + r) * DKk + c * 8);
        *(uint4*)(smem + SM_Q + AMAT + r * AP + c * 16) =
            *(const uint4*)(g_Qlo + base + (long long)(q0 + r) * DKk + c * 8);
    }

    auto kv_load = [&](int kt, int buf) {
        const long long rb = base + (long long)kt * 128 * DKk;
        const unsigned short* srcs[4] = {g_Khi, g_Klo, g_Vhi, g_Vlo};
#pragma unroll
        for (int m = 0; m < 4; m++) {
            for (int i = tid; i < 1024; i += 256) {
                int r = i >> 3, c = i & 7;
                cp_async16(sb + SM_KV + buf * KVBUF + m * AMAT + r * AP + c * 16,
                           srcs[m] + rb + r * DKk + c * 8);
            }
        }
        CP_COMMIT();
    };
    kv_load(0, 0);

    float oacc[2][8][4] = {};
    float mrow[4], lrow[4];
#pragma unroll
    for (int r = 0; r < 4; r++) { mrow[r] = -1e30f; lrow[r] = 0.0f; }

    float* statm = (float*)(smem + SM_STATM);
    float* stats = (float*)(smem + SM_STATS);

    const int nkt = qb + 1;
    for (int kt = 0; kt < nkt; kt++) {
        CP_WAIT0();
        __syncthreads();
        if (kt + 1 < nkt) kv_load(kt + 1, (kt + 1) & 1);

        const uint32_t kb = sb + SM_KV + (kt & 1) * KVBUF;
        const uint32_t qh_b = sb + SM_Q;
        const uint32_t ql_b = qh_b + AMAT;

        // ---- S = Q K^T (split) ----
        float sacc[2][8][4] = {};
#pragma unroll
        for (int ks = 0; ks < 4; ks++) {
            uint32_t ah[2][4], al[2][4];
#pragma unroll
            for (int mt = 0; mt < 2; mt++) {
                uint32_t ao = (uint32_t)(wm * 32 + mt * 16 + a_rowoff) * AP +
                              (uint32_t)(ks * 2 + a_segoff) * 16;
                ldsm4(ah[mt], qh_b + ao);
                ldsm4(al[mt], ql_b + ao);
            }
#pragma unroll
            for (int np = 0; np < 4; np++) {
                uint32_t bo = (uint32_t)(wn * 64 + np * 16 + b_rowoff) * AP +
                              (uint32_t)(ks * 2 + b_segoff) * 16;
                uint32_t kh[4], kl[4];
                ldsm4(kh, kb + bo);
                ldsm4(kl, kb + AMAT + bo);
#pragma unroll
                for (int half = 0; half < 2; half++) {
                    const int nt = np * 2 + half;
#pragma unroll
                    for (int mt = 0; mt < 2; mt++) {
                        mma16816(sacc[mt][nt], ah[mt], &kh[half * 2]);
                        mma16816(sacc[mt][nt], ah[mt], &kl[half * 2]);
                        mma16816(sacc[mt][nt], al[mt], &kh[half * 2]);
                    }
                }
            }
        }

        // ---- scale + causal mask ----
        const bool diag = (kt == qb);
#pragma unroll
        for (int mt = 0; mt < 2; mt++)
#pragma unroll
            for (int nt = 0; nt < 8; nt++)
#pragma unroll
                for (int c = 0; c < 4; c++) {
                    float v = sacc[mt][nt][c] * 0.125f;
                    if (diag) {
                        int kidx = wn * 64 + nt * 8 + t * 2 + (c & 1);
                        int qidx = wm * 32 + mt * 16 + (c >> 1) * 8 + g;
                        if (kidx > qidx) v = -1e30f;
                    }
                    sacc[mt][nt][c] = v;
                }

        // ---- online softmax (cross-warp over wn pair) ----
        float pm[4];
#pragma unroll
        for (int r = 0; r < 4; r++) pm[r] = -1e30f;
#pragma unroll
        for (int mt = 0; mt < 2; mt++)
#pragma unroll
            for (int nt = 0; nt < 8; nt++) {
                pm[mt * 2 + 0] = fmaxf(pm[mt * 2 + 0],
                                       fmaxf(sacc[mt][nt][0], sacc[mt][nt][1]));
                pm[mt * 2 + 1] = fmaxf(pm[mt * 2 + 1],
                                       fmaxf(sacc[mt][nt][2], sacc[mt][nt][3]));
            }
#pragma unroll
        for (int r = 0; r < 4; r++) {
            pm[r] = fmaxf(pm[r], __shfl_xor_sync(0xffffffffu, pm[r], 1));
            pm[r] = fmaxf(pm[r], __shfl_xor_sync(0xffffffffu, pm[r], 2));
        }
        if (t == 0) {
#pragma unroll
            for (int r = 0; r < 4; r++) {
                int rowid = wm * 32 + (r >> 1) * 16 + (r & 1) * 8 + g;
                statm[wn * 128 + rowid] = pm[r];
            }
        }
        __syncthreads();
        float alpha[4];
#pragma unroll
        for (int r = 0; r < 4; r++) {
            int rowid = wm * 32 + (r >> 1) * 16 + (r & 1) * 8 + g;
            float rm = fmaxf(pm[r], statm[(wn ^ 1) * 128 + rowid]);
            float mn = fmaxf(mrow[r], rm);
            alpha[r] = __expf(mrow[r] - mn);
            mrow[r] = mn;
        }
        float psum[4] = {0.f, 0.f, 0.f, 0.f};
#pragma unroll
        for (int mt = 0; mt < 2; mt++)
#pragma unroll
            for (int nt = 0; nt < 8; nt++)
#pragma unroll
                for (int c = 0; c < 4; c++) {
                    int r = mt * 2 + (c >> 1);
                    float p = __expf(sacc[mt][nt][c] - mrow[r]);
                    sacc[mt][nt][c] = p;
                    psum[r] += p;
                }
#pragma unroll
        for (int r = 0; r < 4; r++) {
            psum[r] += __shfl_xor_sync(0xffffffffu, psum[r], 1);
            psum[r] += __shfl_xor_sync(0xffffffffu, psum[r], 2);
        }
        if (t == 0) {
#pragma unroll
            for (int r = 0; r < 4; r++) {
                int rowid = wm * 32 + (r >> 1) * 16 + (r & 1) * 8 + g;
                stats[wn * 128 + rowid] = psum[r];
            }
        }
        __syncthreads();
#pragma unroll
        for (int r = 0; r < 4; r++) {
            int rowid = wm * 32 + (r >> 1) * 16 + (r & 1) * 8 + g;
            float tot = psum[r] + stats[(wn ^ 1) * 128 + rowid];
            lrow[r] = lrow[r] * alpha[r] + tot;
        }
#pragma unroll
        for (int mt = 0; mt < 2; mt++)
#pragma unroll
            for (int nt = 0; nt < 8; nt++)
#pragma unroll
                for (int c = 0; c < 4; c++)
                    oacc[mt][nt][c] *= alpha[mt * 2 + (c >> 1)];

        // ---- O += P V (split), warp's 64 keys, FULL d range ----
        const uint32_t vh_b = kb + 2 * AMAT;
        const uint32_t vl_b = kb + 3 * AMAT;
#pragma unroll
        for (int ks = 0; ks < 4; ks++) {
            uint32_t ph[2][4], pl[2][4];
#pragma unroll
            for (int mt = 0; mt < 2; mt++) {
                const float* s0 = sacc[mt][2 * ks];
                const float* s1 = sacc[mt][2 * ks + 1];
                split2(s0[0], s0[1], ph[mt][0], pl[mt][0]);
                split2(s0[2], s0[3], ph[mt][1], pl[mt][1]);
                split2(s1[0], s1[1], ph[mt][2], pl[mt][2]);
                split2(s1[2], s1[3], ph[mt][3], pl[mt][3]);
            }
#pragma unroll
            for (int dp = 0; dp < 4; dp++) {      // FIX: 4 d-pairs -> d 0..63
                uint32_t vo = (uint32_t)(wn * 64 + ks * 16 + (mtx & 1) * 8 + r8) * AP +
                              (uint32_t)(dp * 16 + (mtx >> 1) * 8) * 2;
                uint32_t vh[4], vl[4];
                ldsm4t(vh, vh_b + vo);
                ldsm4t(vl, vl_b + vo);
#pragma unroll
                for (int half = 0; half < 2; half++) {
                    const int nt = dp * 2 + half;
#pragma unroll
                    for (int mt = 0; mt < 2; mt++) {
                        mma16816(oacc[mt][nt], ph[mt], &vh[half * 2]);
                        mma16816(oacc[mt][nt], ph[mt], &vl[half * 2]);
                        mma16816(oacc[mt][nt], pl[mt], &vh[half * 2]);
                    }
                }
            }
        }
    }

    // ---- epilogue: sum partial O across wn pair, normalize, write ctx ----
    __syncthreads();
    float* Oex = (float*)smem;   // [128][64] = 32 KB (fits in Q region)
    if (wn == 1) {
#pragma unroll
        for (int mt = 0; mt < 2; mt++)
#pragma unroll
            for (int nt = 0; nt < 8; nt++)
#pragma unroll
                for (int c = 0; c < 4; c++) {
                    int row = wm * 32 + mt * 16 + (c >> 1) * 8 + g;
                    int col = nt * 8 + t * 2 + (c & 1);
                    Oex[row * 64 + col] = oacc[mt][nt][c];
                }
    }
    __syncthreads();
    if (wn == 0) {
        float inv[4];
#pragma unroll
        for (int r = 0; r < 4; r++) inv[r] = 1.0f / lrow[r];
#pragma unroll
        for (int mt = 0; mt < 2; mt++)
#pragma unroll
            for (int nt = 0; nt < 8; nt++)
#pragma unroll
                for (int hh = 0; hh < 2; hh++) {
                    int row = wm * 32 + mt * 16 + hh * 8 + g;
                    int col = nt * 8 + t * 2;
                    float v0 = (oacc[mt][nt][hh * 2 + 0] + Oex[row * 64 + col]) *
                               inv[mt * 2 + hh];
                    float v1 = (oacc[mt][nt][hh * 2 + 1] + Oex[row * 64 + col + 1]) *
                               inv[mt * 2 + hh];
                    long long dst = ((long long)(b * Ssz + q0 + row)) * Dsz +
                                    h * DKk + col;
                    uint32_t hiw, low;
                    split2(v0, v1, hiw, low);
                    *(uint32_t*)(g_chi + dst) = hiw;
                    *(uint32_t*)(g_clo + dst) = low;
                }
    }
}

// ---------------------------------------------------------------------------
extern "C" void kernel_launch(void* const* d_in, const int* in_sizes, int n_in,
                              void* d_out, int out_size) {
    const float* x  = (const float*)d_in[0];
    const float* wq = (const float*)d_in[1];
    const float* wk = (const float*)d_in[2];
    const float* wv = (const float*)d_in[3];
    const float* wo = (const float*)d_in[4];
    const float* bo = (const float*)d_in[5];
    float* out = (float*)d_out;

    cudaFuncSetAttribute(qkv_mma_kernel,
                         cudaFuncAttributeMaxDynamicSharedMemorySize, GEMM_SMEM_TOTAL);
    cudaFuncSetAttribute(out_mma_kernel,
                         cudaFuncAttributeMaxDynamicSharedMemorySize, GEMM_SMEM_TOTAL);
    cudaFuncSetAttribute(attn_mma_kernel,
                         cudaFuncAttributeMaxDynamicSharedMemorySize, ATT_SMEM);

    unsigned short *xhi, *xlo, *whi, *wlo;
    cudaGetSymbolAddress((void**)&xhi, g_xhi);
    cudaGetSymbolAddress((void**)&xlo, g_xlo);
    cudaGetSymbolAddress((void**)&whi, g_whi);
    cudaGetSymbolAddress((void**)&wlo, g_wlo);

    const int n4x = Mrows * Dsz / 4;
    const int n4w = Dsz * Dsz / 4;

    convert_split_kernel<<<(n4x + 255) / 256, 256>>>(
        (const float4*)x, (uint2*)xhi, (uint2*)xlo, n4x);
    convert_split_kernel<<<(n4w + 255) / 256, 256>>>(
        (const float4*)wq, (uint2*)(whi + 0ll * Dsz * Dsz), (uint2*)(wlo + 0ll * Dsz * Dsz), n4w);
    convert_split_kernel<<<(n4w + 255) / 256, 256>>>(
        (const float4*)wk, (uint2*)(whi + 1ll * Dsz * Dsz), (uint2*)(wlo + 1ll * Dsz * Dsz), n4w);
    convert_split_kernel<<<(n4w + 255) / 256, 256>>>(
        (const float4*)wv, (uint2*)(whi + 2ll * Dsz * Dsz), (uint2*)(wlo + 2ll * Dsz * Dsz), n4w);
    convert_split_kernel<<<(n4w + 255) / 256, 256>>>(
        (const float4*)wo, (uint2*)(whi + 3ll * Dsz * Dsz), (uint2*)(wlo + 3ll * Dsz * Dsz), n4w);

    dim3 g1(Dsz / 128, Mrows / 128, 3);
    qkv_mma_kernel<<<g1, 256, GEMM_SMEM_TOTAL>>>();

    dim3 g2(Ssz / 128, Bsz * Hh);
    attn_mma_kernel<<<g2, 256, ATT_SMEM>>>();

    dim3 g3(Dsz / 128, Mrows / 128);
    out_mma_kernel<<<g3, 256, GEMM_SMEM_TOTAL>>>(bo, out);
}

// round 8
// speedup vs baseline: 3.2480x; 1.0495x over previous
#include <cuda_runtime.h>
#include <cuda_bf16.h>
#include <math.h>
#include <cstdint>

// Problem constants
#define Bsz 4
#define Ssz 2048
#define Dsz 1024
#define Hh  16
#define DKk 64
#define Mrows (Bsz * Ssz)   // 8192

// ---------------------------------------------------------------------------
// Scratch (device globals)
// ---------------------------------------------------------------------------
__device__ unsigned short g_xhi[(long long)Mrows * Dsz];
__device__ unsigned short g_xlo[(long long)Mrows * Dsz];
__device__ unsigned short g_chi[(long long)Mrows * Dsz];
__device__ unsigned short g_clo[(long long)Mrows * Dsz];
__device__ unsigned short g_whi[4ll * Dsz * Dsz];
__device__ unsigned short g_wlo[4ll * Dsz * Dsz];
// Q/K/V split-bf16 in [b,h,s,dk] layout
__device__ unsigned short g_Qhi[(long long)Mrows * Dsz];
__device__ unsigned short g_Qlo[(long long)Mrows * Dsz];
__device__ unsigned short g_Khi[(long long)Mrows * Dsz];
__device__ unsigned short g_Klo[(long long)Mrows * Dsz];
__device__ unsigned short g_Vhi[(long long)Mrows * Dsz];
__device__ unsigned short g_Vlo[(long long)Mrows * Dsz];

// ---------------------------------------------------------------------------
// PTX helpers (portable ISA: ldmatrix / mma.sync / cp.async, sm_80+)
// ---------------------------------------------------------------------------
__device__ __forceinline__ uint32_t smem_to_u32(const void* p) {
    uint32_t a;
    asm("{ .reg .u64 t; cvta.to.shared.u64 t, %1; cvt.u32.u64 %0, t; }"
        : "=r"(a) : "l"(p));
    return a;
}
__device__ __forceinline__ void ldsm4(uint32_t* r, uint32_t addr) {
    asm volatile("ldmatrix.sync.aligned.m8n8.x4.shared.b16 {%0,%1,%2,%3}, [%4];"
                 : "=r"(r[0]), "=r"(r[1]), "=r"(r[2]), "=r"(r[3]) : "r"(addr));
}
__device__ __forceinline__ void ldsm4t(uint32_t* r, uint32_t addr) {
    asm volatile("ldmatrix.sync.aligned.m8n8.x4.trans.shared.b16 {%0,%1,%2,%3}, [%4];"
                 : "=r"(r[0]), "=r"(r[1]), "=r"(r[2]), "=r"(r[3]) : "r"(addr));
}
__device__ __forceinline__ void mma16816(float* d, const uint32_t* a,
                                         const uint32_t* b) {
    asm volatile(
        "mma.sync.aligned.m16n8k16.row.col.f32.bf16.bf16.f32 "
        "{%0,%1,%2,%3}, {%4,%5,%6,%7}, {%8,%9}, {%0,%1,%2,%3};"
        : "+f"(d[0]), "+f"(d[1]), "+f"(d[2]), "+f"(d[3])
        : "r"(a[0]), "r"(a[1]), "r"(a[2]), "r"(a[3]), "r"(b[0]), "r"(b[1]));
}
__device__ __forceinline__ void cp_async16(uint32_t saddr, const void* g) {
    asm volatile("cp.async.cg.shared.global [%0], [%1], 16;"
                 :: "r"(saddr), "l"(g));
}
#define CP_COMMIT() asm volatile("cp.async.commit_group;" ::: "memory")
#define CP_WAIT0()  asm volatile("cp.async.wait_group 0;" ::: "memory")

__device__ __forceinline__ uint32_t packbf(float lo, float hi) {
    uint32_t r;
    asm("cvt.rn.bf16x2.f32 %0, %1, %2;" : "=r"(r) : "f"(hi), "f"(lo));
    return r;
}
__device__ __forceinline__ float bf_round(float v) {
    return __bfloat162float(__float2bfloat16(v));
}
__device__ __forceinline__ void split2(float v0, float v1,
                                       uint32_t& hi, uint32_t& lo) {
    hi = packbf(v0, v1);
    lo = packbf(v0 - bf_round(v0), v1 - bf_round(v1));
}

// ---------------------------------------------------------------------------
// fp32 -> (bf16 hi, bf16 lo) split conversion
// ---------------------------------------------------------------------------
__global__ __launch_bounds__(256)
void convert_split_kernel(const float4* __restrict__ src,
                          uint2* __restrict__ hi, uint2* __restrict__ lo, int n4) {
    int i = blockIdx.x * blockDim.x + threadIdx.x;
    if (i >= n4) return;
    float4 v = src[i];
    uint32_t h01, l01, h23, l23;
    split2(v.x, v.y, h01, l01);
    split2(v.z, v.w, h23, l23);
    hi[i] = make_uint2(h01, h23);
    lo[i] = make_uint2(l01, l23);
}

// ---------------------------------------------------------------------------
// Split-bf16 NT GEMM (CTA 128x128, BK=32, 8 warps 4m x 2n)
// Round 8: cp.async loader (no register staging) + 2 CTAs/SM.
// ---------------------------------------------------------------------------
#define ROWB 80
#define MATB (128 * ROWB)
#define GEMM_SMEM_TOTAL (2 * 4 * MATB)   // 81920 B
#define NCHUNK (Dsz / 32)

__device__ __forceinline__ void gemm_mma(const unsigned short* __restrict__ Ahi,
                                         const unsigned short* __restrict__ Alo,
                                         const unsigned short* __restrict__ Whi,
                                         const unsigned short* __restrict__ Wlo,
                                         float* __restrict__ C,
                                         const float* __restrict__ bias,
                                         unsigned short* __restrict__ Dhi,
                                         unsigned short* __restrict__ Dlo) {
    extern __shared__ char smem[];
    const uint32_t sbase = smem_to_u32(smem);
    const int tid = threadIdx.x;
    const int wid = tid >> 5;
    const int lane = tid & 31;
    const int wm = wid & 3;
    const int wn = wid >> 2;
    const int bm = blockIdx.y * 128;
    const int bn = blockIdx.x * 128;

    const int s0 = tid, s1 = tid + 256;
    const int r0g = s0 >> 2, c0g = (s0 & 3) * 8;
    const int r1g = s1 >> 2, c1g = (s1 & 3) * 8;

    const unsigned short* gp[4] = {Ahi, Alo, Whi, Wlo};
    const long long rowbase[4] = {
        (long long)(bm + r0g) * Dsz, (long long)(bm + r0g) * Dsz,
        (long long)(bn + r0g) * Dsz, (long long)(bn + r0g) * Dsz};
    const long long rowbase1[4] = {
        (long long)(bm + r1g) * Dsz, (long long)(bm + r1g) * Dsz,
        (long long)(bn + r1g) * Dsz, (long long)(bn + r1g) * Dsz};

    float acc[2][8][4] = {};

    // cp.async loader: 512 16B segments per matrix, 2 per thread per matrix
    auto load_chunk = [&](int c, int buf) {
        const int k0 = c * 32;
        const uint32_t b = sbase + buf * 4 * MATB;
#pragma unroll
        for (int m = 0; m < 4; m++) {
            cp_async16(b + m * MATB + r0g * ROWB + (s0 & 3) * 16,
                       gp[m] + rowbase[m] + k0 + c0g);
            cp_async16(b + m * MATB + r1g * ROWB + (s1 & 3) * 16,
                       gp[m] + rowbase1[m] + k0 + c1g);
        }
        CP_COMMIT();
    };

    const int mtx = lane >> 3;
    const int r8 = lane & 7;
    const int a_rowoff = (mtx & 1) * 8 + r8;
    const int a_segoff = (mtx >> 1);
    const int b_rowoff = (mtx >> 1) * 8 + r8;
    const int b_segoff = (mtx & 1);

    auto compute = [&](int buf) {
        const uint32_t ahb = sbase + buf * 4 * MATB;
        const uint32_t alb = ahb + MATB;
        const uint32_t bhb = ahb + 2 * MATB;
        const uint32_t blb = ahb + 3 * MATB;
#pragma unroll
        for (int ks = 0; ks < 2; ks++) {
            uint32_t ah[2][4], al[2][4];
#pragma unroll
            for (int mt = 0; mt < 2; mt++) {
                uint32_t ao = (uint32_t)(wm * 32 + mt * 16 + a_rowoff) * ROWB +
                              (uint32_t)(ks * 2 + a_segoff) * 16;
                ldsm4(ah[mt], ahb + ao);
                ldsm4(al[mt], alb + ao);
            }
#pragma unroll
            for (int np = 0; np < 4; np++) {
                uint32_t bo = (uint32_t)(wn * 64 + np * 16 + b_rowoff) * ROWB +
                              (uint32_t)(ks * 2 + b_segoff) * 16;
                uint32_t bh[4], bl[4];
                ldsm4(bh, bhb + bo);
                ldsm4(bl, blb + bo);
#pragma unroll
                for (int half = 0; half < 2; half++) {
                    const int nt = np * 2 + half;
#pragma unroll
                    for (int mt = 0; mt < 2; mt++) {
                        mma16816(acc[mt][nt], ah[mt], &bh[half * 2]);
                        mma16816(acc[mt][nt], ah[mt], &bl[half * 2]);
                        mma16816(acc[mt][nt], al[mt], &bh[half * 2]);
                    }
                }
            }
        }
    };

    load_chunk(0, 0);
    for (int c = 0; c < NCHUNK; c++) {
        CP_WAIT0();
        __syncthreads();
        if (c + 1 < NCHUNK) load_chunk(c + 1, (c + 1) & 1);
        compute(c & 1);
    }

    const int g = lane >> 2, t = lane & 3;
    if (Dhi) {
#pragma unroll
        for (int mt = 0; mt < 2; mt++) {
#pragma unroll
            for (int nt = 0; nt < 8; nt++) {
                const int col = bn + wn * 64 + nt * 8 + t * 2;
                const int hd = col >> 6, d = col & 63;
#pragma unroll
                for (int hh = 0; hh < 2; hh++) {
                    const int row = bm + wm * 32 + mt * 16 + hh * 8 + g;
                    const int b = row >> 11, s = row & 2047;
                    const long long idx =
                        ((long long)(b * Hh + hd) * Ssz + s) * DKk + d;
                    uint32_t hiw, low;
                    split2(acc[mt][nt][hh * 2 + 0], acc[mt][nt][hh * 2 + 1],
                           hiw, low);
                    *(uint32_t*)(Dhi + idx) = hiw;
                    *(uint32_t*)(Dlo + idx) = low;
                }
            }
        }
    } else {
#pragma unroll
        for (int mt = 0; mt < 2; mt++) {
#pragma unroll
            for (int nt = 0; nt < 8; nt++) {
                const int col = bn + wn * 64 + nt * 8 + t * 2;
                const int row0 = bm + wm * 32 + mt * 16 + g;
                float2 v0 = make_float2(acc[mt][nt][0], acc[mt][nt][1]);
                float2 v1 = make_float2(acc[mt][nt][2], acc[mt][nt][3]);
                if (bias) {
                    float2 bb = *(const float2*)(bias + col);
                    v0.x += bb.x; v0.y += bb.y;
                    v1.x += bb.x; v1.y += bb.y;
                }
                *(float2*)(C + (long long)row0 * Dsz + col) = v0;
                *(float2*)(C + (long long)(row0 + 8) * Dsz + col) = v1;
            }
        }
    }
}

__global__ __launch_bounds__(256, 2)
void qkv_mma_kernel() {
    const unsigned short* Whi = g_whi + (long long)blockIdx.z * Dsz * Dsz;
    const unsigned short* Wlo = g_wlo + (long long)blockIdx.z * Dsz * Dsz;
    unsigned short* Dhi = (blockIdx.z == 0) ? g_Qhi : (blockIdx.z == 1) ? g_Khi : g_Vhi;
    unsigned short* Dlo = (blockIdx.z == 0) ? g_Qlo : (blockIdx.z == 1) ? g_Klo : g_Vlo;
    gemm_mma(g_xhi, g_xlo, Whi, Wlo, nullptr, nullptr, Dhi, Dlo);
}

__global__ __launch_bounds__(256, 2)
void out_mma_kernel(const float* __restrict__ bo, float* __restrict__ out) {
    const unsigned short* Whi = g_whi + 3ll * Dsz * Dsz;
    const unsigned short* Wlo = g_wlo + 3ll * Dsz * Dsz;
    gemm_mma(g_chi, g_clo, Whi, Wlo, out, bo, nullptr, nullptr);
}

// ---------------------------------------------------------------------------
// Tensor-core flash attention (split-bf16), causal — unchanged from Round 7.
// ---------------------------------------------------------------------------
#define AP 144
#define AMAT (128 * AP)
#define SM_Q 0
#define SM_KV 36864
#define KVBUF (4 * AMAT)
#define SM_STATM (SM_KV + 2 * KVBUF)
#define SM_STATS (SM_STATM + 1024)
#define ATT_SMEM (SM_STATS + 1024)

__global__ __launch_bounds__(256)
void attn_mma_kernel() {
    extern __shared__ char smem[];
    const uint32_t sb = smem_to_u32(smem);
    const int tid = threadIdx.x;
    const int wid = tid >> 5;
    const int lane = tid & 31;
    const int wm = wid & 3;
    const int wn = wid >> 2;
    const int g = lane >> 2, t = lane & 3;
    const int mtx = lane >> 3, r8 = lane & 7;
    const int a_rowoff = (mtx & 1) * 8 + r8;
    const int a_segoff = (mtx >> 1);
    const int b_rowoff = (mtx >> 1) * 8 + r8;
    const int b_segoff = (mtx & 1);

    const int qb = (Ssz / 128 - 1) - blockIdx.x;
    const int q0 = qb * 128;
    const int bh = blockIdx.y;
    const int b = bh >> 4, h = bh & 15;
    const long long base = (long long)bh * Ssz * DKk;

    for (int i = tid; i < 1024; i += 256) {
        int r = i >> 3, c = i & 7;
        *(uint4*)(smem + SM_Q + r * AP + c * 16) =
            *(const uint4*)(g_Qhi + base + (long long)(q0 + r) * DKk + c * 8);
        *(uint4*)(smem + SM_Q + AMAT + r * AP + c * 16) =
            *(const uint4*)(g_Qlo + base + (long long)(q0 + r) * DKk + c * 8);
    }

    auto kv_load = [&](int kt, int buf) {
        const long long rb = base + (long long)kt * 128 * DKk;
        const unsigned short* srcs[4] = {g_Khi, g_Klo, g_Vhi, g_Vlo};
#pragma unroll
        for (int m = 0; m < 4; m++) {
            for (int i = tid; i < 1024; i += 256) {
                int r = i >> 3, c = i & 7;
                cp_async16(sb + SM_KV + buf * KVBUF + m * AMAT + r * AP + c * 16,
                           srcs[m] + rb + r * DKk + c * 8);
            }
        }
        CP_COMMIT();
    };
    kv_load(0, 0);

    float oacc[2][8][4] = {};
    float mrow[4], lrow[4];
#pragma unroll
    for (int r = 0; r < 4; r++) { mrow[r] = -1e30f; lrow[r] = 0.0f; }

    float* statm = (float*)(smem + SM_STATM);
    float* stats = (float*)(smem + SM_STATS);

    const int nkt = qb + 1;
    for (int kt = 0; kt < nkt; kt++) {
        CP_WAIT0();
        __syncthreads();
        if (kt + 1 < nkt) kv_load(kt + 1, (kt + 1) & 1);

        const uint32_t kb = sb + SM_KV + (kt & 1) * KVBUF;
        const uint32_t qh_b = sb + SM_Q;
        const uint32_t ql_b = qh_b + AMAT;

        // ---- S = Q K^T (split) ----
        float sacc[2][8][4] = {};
#pragma unroll
        for (int ks = 0; ks < 4; ks++) {
            uint32_t ah[2][4], al[2][4];
#pragma unroll
            for (int mt = 0; mt < 2; mt++) {
                uint32_t ao = (uint32_t)(wm * 32 + mt * 16 + a_rowoff) * AP +
                              (uint32_t)(ks * 2 + a_segoff) * 16;
                ldsm4(ah[mt], qh_b + ao);
                ldsm4(al[mt], ql_b + ao);
            }
#pragma unroll
            for (int np = 0; np < 4; np++) {
                uint32_t bo = (uint32_t)(wn * 64 + np * 16 + b_rowoff) * AP +
                              (uint32_t)(ks * 2 + b_segoff) * 16;
                uint32_t kh[4], kl[4];
                ldsm4(kh, kb + bo);
                ldsm4(kl, kb + AMAT + bo);
#pragma unroll
                for (int half = 0; half < 2; half++) {
                    const int nt = np * 2 + half;
#pragma unroll
                    for (int mt = 0; mt < 2; mt++) {
                        mma16816(sacc[mt][nt], ah[mt], &kh[half * 2]);
                        mma16816(sacc[mt][nt], ah[mt], &kl[half * 2]);
                        mma16816(sacc[mt][nt], al[mt], &kh[half * 2]);
                    }
                }
            }
        }

        // ---- scale + causal mask ----
        const bool diag = (kt == qb);
#pragma unroll
        for (int mt = 0; mt < 2; mt++)
#pragma unroll
            for (int nt = 0; nt < 8; nt++)
#pragma unroll
                for (int c = 0; c < 4; c++) {
                    float v = sacc[mt][nt][c] * 0.125f;
                    if (diag) {
                        int kidx = wn * 64 + nt * 8 + t * 2 + (c & 1);
                        int qidx = wm * 32 + mt * 16 + (c >> 1) * 8 + g;
                        if (kidx > qidx) v = -1e30f;
                    }
                    sacc[mt][nt][c] = v;
                }

        // ---- online softmax (cross-warp over wn pair) ----
        float pm[4];
#pragma unroll
        for (int r = 0; r < 4; r++) pm[r] = -1e30f;
#pragma unroll
        for (int mt = 0; mt < 2; mt++)
#pragma unroll
            for (int nt = 0; nt < 8; nt++) {
                pm[mt * 2 + 0] = fmaxf(pm[mt * 2 + 0],
                                       fmaxf(sacc[mt][nt][0], sacc[mt][nt][1]));
                pm[mt * 2 + 1] = fmaxf(pm[mt * 2 + 1],
                                       fmaxf(sacc[mt][nt][2], sacc[mt][nt][3]));
            }
#pragma unroll
        for (int r = 0; r < 4; r++) {
            pm[r] = fmaxf(pm[r], __shfl_xor_sync(0xffffffffu, pm[r], 1));
            pm[r] = fmaxf(pm[r], __shfl_xor_sync(0xffffffffu, pm[r], 2));
        }
        if (t == 0) {
#pragma unroll
            for (int r = 0; r < 4; r++) {
                int rowid = wm * 32 + (r >> 1) * 16 + (r & 1) * 8 + g;
                statm[wn * 128 + rowid] = pm[r];
            }
        }
        __syncthreads();
        float alpha[4];
#pragma unroll
        for (int r = 0; r < 4; r++) {
            int rowid = wm * 32 + (r >> 1) * 16 + (r & 1) * 8 + g;
            float rm = fmaxf(pm[r], statm[(wn ^ 1) * 128 + rowid]);
            float mn = fmaxf(mrow[r], rm);
            alpha[r] = __expf(mrow[r] - mn);
            mrow[r] = mn;
        }
        float psum[4] = {0.f, 0.f, 0.f, 0.f};
#pragma unroll
        for (int mt = 0; mt < 2; mt++)
#pragma unroll
            for (int nt = 0; nt < 8; nt++)
#pragma unroll
                for (int c = 0; c < 4; c++) {
                    int r = mt * 2 + (c >> 1);
                    float p = __expf(sacc[mt][nt][c] - mrow[r]);
                    sacc[mt][nt][c] = p;
                    psum[r] += p;
                }
#pragma unroll
        for (int r = 0; r < 4; r++) {
            psum[r] += __shfl_xor_sync(0xffffffffu, psum[r], 1);
            psum[r] += __shfl_xor_sync(0xffffffffu, psum[r], 2);
        }
        if (t == 0) {
#pragma unroll
            for (int r = 0; r < 4; r++) {
                int rowid = wm * 32 + (r >> 1) * 16 + (r & 1) * 8 + g;
                stats[wn * 128 + rowid] = psum[r];
            }
        }
        __syncthreads();
#pragma unroll
        for (int r = 0; r < 4; r++) {
            int rowid = wm * 32 + (r >> 1) * 16 + (r & 1) * 8 + g;
            float tot = psum[r] + stats[(wn ^ 1) * 128 + rowid];
            lrow[r] = lrow[r] * alpha[r] + tot;
        }
#pragma unroll
        for (int mt = 0; mt < 2; mt++)
#pragma unroll
            for (int nt = 0; nt < 8; nt++)
#pragma unroll
                for (int c = 0; c < 4; c++)
                    oacc[mt][nt][c] *= alpha[mt * 2 + (c >> 1)];

        // ---- O += P V (split), warp's 64 keys, full d range ----
        const uint32_t vh_b = kb + 2 * AMAT;
        const uint32_t vl_b = kb + 3 * AMAT;
#pragma unroll
        for (int ks = 0; ks < 4; ks++) {
            uint32_t ph[2][4], pl[2][4];
#pragma unroll
            for (int mt = 0; mt < 2; mt++) {
                const float* s0 = sacc[mt][2 * ks];
                const float* s1 = sacc[mt][2 * ks + 1];
                split2(s0[0], s0[1], ph[mt][0], pl[mt][0]);
                split2(s0[2], s0[3], ph[mt][1], pl[mt][1]);
                split2(s1[0], s1[1], ph[mt][2], pl[mt][2]);
                split2(s1[2], s1[3], ph[mt][3], pl[mt][3]);
            }
#pragma unroll
            for (int dp = 0; dp < 4; dp++) {
                uint32_t vo = (uint32_t)(wn * 64 + ks * 16 + (mtx & 1) * 8 + r8) * AP +
                              (uint32_t)(dp * 16 + (mtx >> 1) * 8) * 2;
                uint32_t vh[4], vl[4];
                ldsm4t(vh, vh_b + vo);
                ldsm4t(vl, vl_b + vo);
#pragma unroll
                for (int half = 0; half < 2; half++) {
                    const int nt = dp * 2 + half;
#pragma unroll
                    for (int mt = 0; mt < 2; mt++) {
                        mma16816(oacc[mt][nt], ph[mt], &vh[half * 2]);
                        mma16816(oacc[mt][nt], ph[mt], &vl[half * 2]);
                        mma16816(oacc[mt][nt], pl[mt], &vh[half * 2]);
                    }
                }
            }
        }
    }

    // ---- epilogue: sum partial O across wn pair, normalize, write ctx ----
    __syncthreads();
    float* Oex = (float*)smem;   // [128][64] = 32 KB
    if (wn == 1) {
#pragma unroll
        for (int mt = 0; mt < 2; mt++)
#pragma unroll
            for (int nt = 0; nt < 8; nt++)
#pragma unroll
                for (int c = 0; c < 4; c++) {
                    int row = wm * 32 + mt * 16 + (c >> 1) * 8 + g;
                    int col = nt * 8 + t * 2 + (c & 1);
                    Oex[row * 64 + col] = oacc[mt][nt][c];
                }
    }
    __syncthreads();
    if (wn == 0) {
        float inv[4];
#pragma unroll
        for (int r = 0; r < 4; r++) inv[r] = 1.0f / lrow[r];
#pragma unroll
        for (int mt = 0; mt < 2; mt++)
#pragma unroll
            for (int nt = 0; nt < 8; nt++)
#pragma unroll
                for (int hh = 0; hh < 2; hh++) {
                    int row = wm * 32 + mt * 16 + hh * 8 + g;
                    int col = nt * 8 + t * 2;
                    float v0 = (oacc[mt][nt][hh * 2 + 0] + Oex[row * 64 + col]) *
                               inv[mt * 2 + hh];
                    float v1 = (oacc[mt][nt][hh * 2 + 1] + Oex[row * 64 + col + 1]) *
                               inv[mt * 2 + hh];
                    long long dst = ((long long)(b * Ssz + q0 + row)) * Dsz +
                                    h * DKk + col;
                    uint32_t hiw, low;
                    split2(v0, v1, hiw, low);
                    *(uint32_t*)(g_chi + dst) = hiw;
                    *(uint32_t*)(g_clo + dst) = low;
                }
    }
}

// ---------------------------------------------------------------------------
extern "C" void kernel_launch(void* const* d_in, const int* in_sizes, int n_in,
                              void* d_out, int out_size) {
    const float* x  = (const float*)d_in[0];
    const float* wq = (const float*)d_in[1];
    const float* wk = (const float*)d_in[2];
    const float* wv = (const float*)d_in[3];
    const float* wo = (const float*)d_in[4];
    const float* bo = (const float*)d_in[5];
    float* out = (float*)d_out;

    cudaFuncSetAttribute(qkv_mma_kernel,
                         cudaFuncAttributeMaxDynamicSharedMemorySize, GEMM_SMEM_TOTAL);
    cudaFuncSetAttribute(out_mma_kernel,
                         cudaFuncAttributeMaxDynamicSharedMemorySize, GEMM_SMEM_TOTAL);
    cudaFuncSetAttribute(attn_mma_kernel,
                         cudaFuncAttributeMaxDynamicSharedMemorySize, ATT_SMEM);

    unsigned short *xhi, *xlo, *whi, *wlo;
    cudaGetSymbolAddress((void**)&xhi, g_xhi);
    cudaGetSymbolAddress((void**)&xlo, g_xlo);
    cudaGetSymbolAddress((void**)&whi, g_whi);
    cudaGetSymbolAddress((void**)&wlo, g_wlo);

    const int n4x = Mrows * Dsz / 4;
    const int n4w = Dsz * Dsz / 4;

    convert_split_kernel<<<(n4x + 255) / 256, 256>>>(
        (const float4*)x, (uint2*)xhi, (uint2*)xlo, n4x);
    convert_split_kernel<<<(n4w + 255) / 256, 256>>>(
        (const float4*)wq, (uint2*)(whi + 0ll * Dsz * Dsz), (uint2*)(wlo + 0ll * Dsz * Dsz), n4w);
    convert_split_kernel<<<(n4w + 255) / 256, 256>>>(
        (const float4*)wk, (uint2*)(whi + 1ll * Dsz * Dsz), (uint2*)(wlo + 1ll * Dsz * Dsz), n4w);
    convert_split_kernel<<<(n4w + 255) / 256, 256>>>(
        (const float4*)wv, (uint2*)(whi + 2ll * Dsz * Dsz), (uint2*)(wlo + 2ll * Dsz * Dsz), n4w);
    convert_split_kernel<<<(n4w + 255) / 256, 256>>>(
        (const float4*)wo, (uint2*)(whi + 3ll * Dsz * Dsz), (uint2*)(wlo + 3ll * Dsz * Dsz), n4w);

    dim3 g1(Dsz / 128, Mrows / 128, 3);
    qkv_mma_kernel<<<g1, 256, GEMM_SMEM_TOTAL>>>();

    dim3 g2(Ssz / 128, Bsz * Hh);
    attn_mma_kernel<<<g2, 256, ATT_SMEM>>>();

    dim3 g3(Dsz / 128, Mrows / 128);
    out_mma_kernel<<<g3, 256, GEMM_SMEM_TOTAL>>>(bo, out);
}

// round 9
// speedup vs baseline: 3.8759x; 1.1933x over previous
#include <cuda_runtime.h>
#include <cuda_bf16.h>
#include <cuda_fp16.h>
#include <math.h>
#include <cstdint>

// Problem constants
#define Bsz 4
#define Ssz 2048
#define Dsz 1024
#define Hh  16
#define DKk 64
#define Mrows (Bsz * Ssz)   // 8192

// ---------------------------------------------------------------------------
// Scratch (device globals)
// g_xh  : x as fp16                      g_whi/g_wlo : weights fp16 hi/lo
// g_ch  : ctx as fp16 (written by attn)
// g_Q/K/Vhi+lo : bf16 split [b,h,s,dk] for attention
// ---------------------------------------------------------------------------
__device__ unsigned short g_xh[(long long)Mrows * Dsz];
__device__ unsigned short g_ch[(long long)Mrows * Dsz];
__device__ unsigned short g_whi[4ll * Dsz * Dsz];
__device__ unsigned short g_wlo[4ll * Dsz * Dsz];
__device__ unsigned short g_Qhi[(long long)Mrows * Dsz];
__device__ unsigned short g_Qlo[(long long)Mrows * Dsz];
__device__ unsigned short g_Khi[(long long)Mrows * Dsz];
__device__ unsigned short g_Klo[(long long)Mrows * Dsz];
__device__ unsigned short g_Vhi[(long long)Mrows * Dsz];
__device__ unsigned short g_Vlo[(long long)Mrows * Dsz];

// ---------------------------------------------------------------------------
// PTX helpers (portable ISA: ldmatrix / mma.sync / cp.async, sm_80+)
// ---------------------------------------------------------------------------
__device__ __forceinline__ uint32_t smem_to_u32(const void* p) {
    uint32_t a;
    asm("{ .reg .u64 t; cvta.to.shared.u64 t, %1; cvt.u32.u64 %0, t; }"
        : "=r"(a) : "l"(p));
    return a;
}
__device__ __forceinline__ void ldsm4(uint32_t* r, uint32_t addr) {
    asm volatile("ldmatrix.sync.aligned.m8n8.x4.shared.b16 {%0,%1,%2,%3}, [%4];"
                 : "=r"(r[0]), "=r"(r[1]), "=r"(r[2]), "=r"(r[3]) : "r"(addr));
}
__device__ __forceinline__ void ldsm4t(uint32_t* r, uint32_t addr) {
    asm volatile("ldmatrix.sync.aligned.m8n8.x4.trans.shared.b16 {%0,%1,%2,%3}, [%4];"
                 : "=r"(r[0]), "=r"(r[1]), "=r"(r[2]), "=r"(r[3]) : "r"(addr));
}
// bf16 mma (attention)
__device__ __forceinline__ void mma16816(float* d, const uint32_t* a,
                                         const uint32_t* b) {
    asm volatile(
        "mma.sync.aligned.m16n8k16.row.col.f32.bf16.bf16.f32 "
        "{%0,%1,%2,%3}, {%4,%5,%6,%7}, {%8,%9}, {%0,%1,%2,%3};"
        : "+f"(d[0]), "+f"(d[1]), "+f"(d[2]), "+f"(d[3])
        : "r"(a[0]), "r"(a[1]), "r"(a[2]), "r"(a[3]), "r"(b[0]), "r"(b[1]));
}
// fp16 mma (projection GEMMs)
__device__ __forceinline__ void mma16816h(float* d, const uint32_t* a,
                                          const uint32_t* b) {
    asm volatile(
        "mma.sync.aligned.m16n8k16.row.col.f32.f16.f16.f32 "
        "{%0,%1,%2,%3}, {%4,%5,%6,%7}, {%8,%9}, {%0,%1,%2,%3};"
        : "+f"(d[0]), "+f"(d[1]), "+f"(d[2]), "+f"(d[3])
        : "r"(a[0]), "r"(a[1]), "r"(a[2]), "r"(a[3]), "r"(b[0]), "r"(b[1]));
}
__device__ __forceinline__ void cp_async16(uint32_t saddr, const void* g) {
    asm volatile("cp.async.cg.shared.global [%0], [%1], 16;"
                 :: "r"(saddr), "l"(g));
}
#define CP_COMMIT() asm volatile("cp.async.commit_group;" ::: "memory")
#define CP_WAIT0()  asm volatile("cp.async.wait_group 0;" ::: "memory")

__device__ __forceinline__ uint32_t packbf(float lo, float hi) {
    uint32_t r;
    asm("cvt.rn.bf16x2.f32 %0, %1, %2;" : "=r"(r) : "f"(hi), "f"(lo));
    return r;
}
__device__ __forceinline__ float bf_round(float v) {
    return __bfloat162float(__float2bfloat16(v));
}
__device__ __forceinline__ void split2(float v0, float v1,
                                       uint32_t& hi, uint32_t& lo) {
    hi = packbf(v0, v1);
    lo = packbf(v0 - bf_round(v0), v1 - bf_round(v1));
}
__device__ __forceinline__ uint32_t packh(float a, float b) {
    __half2 h = __floats2half2_rn(a, b);
    return *reinterpret_cast<uint32_t*>(&h);
}
__device__ __forceinline__ float h_round(float v) {
    return __half2float(__float2half_rn(v));
}

// ---------------------------------------------------------------------------
// Conversion kernels
// ---------------------------------------------------------------------------
__global__ __launch_bounds__(256)
void convert_f16_kernel(const float4* __restrict__ src,
                        uint2* __restrict__ dst, int n4) {
    int i = blockIdx.x * blockDim.x + threadIdx.x;
    if (i >= n4) return;
    float4 v = src[i];
    dst[i] = make_uint2(packh(v.x, v.y), packh(v.z, v.w));
}
__global__ __launch_bounds__(256)
void convert_split_f16_kernel(const float4* __restrict__ src,
                              uint2* __restrict__ hi, uint2* __restrict__ lo,
                              int n4) {
    int i = blockIdx.x * blockDim.x + threadIdx.x;
    if (i >= n4) return;
    float4 v = src[i];
    hi[i] = make_uint2(packh(v.x, v.y), packh(v.z, v.w));
    lo[i] = make_uint2(packh(v.x - h_round(v.x), v.y - h_round(v.y)),
                       packh(v.z - h_round(v.z), v.w - h_round(v.w)));
}

// ---------------------------------------------------------------------------
// fp16 2-term NT GEMM: C = A_fp16 . (W_hi + W_lo)^T   (CTA 128x128, BK=32)
// 8 warps 4m x 2n; 2 MMAs per microtile per k16; 3 smem matrices per buffer.
// ---------------------------------------------------------------------------
#define ROWB 80
#define MATB (128 * ROWB)
#define GEMM_SMEM_TOTAL (2 * 3 * MATB)   // 61440 B
#define NCHUNK (Dsz / 32)

__device__ __forceinline__ void gemm_mma(const unsigned short* __restrict__ Ah,
                                         const unsigned short* __restrict__ Whi,
                                         const unsigned short* __restrict__ Wlo,
                                         float* __restrict__ C,
                                         const float* __restrict__ bias,
                                         unsigned short* __restrict__ Dhi,
                                         unsigned short* __restrict__ Dlo) {
    extern __shared__ char smem[];
    const uint32_t sbase = smem_to_u32(smem);
    const int tid = threadIdx.x;
    const int wid = tid >> 5;
    const int lane = tid & 31;
    const int wm = wid & 3;
    const int wn = wid >> 2;
    const int bm = blockIdx.y * 128;
    const int bn = blockIdx.x * 128;

    const int s0 = tid, s1 = tid + 256;
    const int r0g = s0 >> 2, c0g = (s0 & 3) * 8;
    const int r1g = s1 >> 2, c1g = (s1 & 3) * 8;

    const unsigned short* gp[3] = {Ah, Whi, Wlo};
    const long long rowbase[3] = {
        (long long)(bm + r0g) * Dsz,
        (long long)(bn + r0g) * Dsz, (long long)(bn + r0g) * Dsz};
    const long long rowbase1[3] = {
        (long long)(bm + r1g) * Dsz,
        (long long)(bn + r1g) * Dsz, (long long)(bn + r1g) * Dsz};

    float acc[2][8][4] = {};

    auto load_chunk = [&](int c, int buf) {
        const int k0 = c * 32;
        const uint32_t b = sbase + buf * 3 * MATB;
#pragma unroll
        for (int m = 0; m < 3; m++) {
            cp_async16(b + m * MATB + r0g * ROWB + (s0 & 3) * 16,
                       gp[m] + rowbase[m] + k0 + c0g);
            cp_async16(b + m * MATB + r1g * ROWB + (s1 & 3) * 16,
                       gp[m] + rowbase1[m] + k0 + c1g);
        }
        CP_COMMIT();
    };

    const int mtx = lane >> 3;
    const int r8 = lane & 7;
    const int a_rowoff = (mtx & 1) * 8 + r8;
    const int a_segoff = (mtx >> 1);
    const int b_rowoff = (mtx >> 1) * 8 + r8;
    const int b_segoff = (mtx & 1);

    auto compute = [&](int buf) {
        const uint32_t ahb = sbase + buf * 3 * MATB;
        const uint32_t bhb = ahb + MATB;
        const uint32_t blb = ahb + 2 * MATB;
#pragma unroll
        for (int ks = 0; ks < 2; ks++) {
            uint32_t ah[2][4];
#pragma unroll
            for (int mt = 0; mt < 2; mt++) {
                uint32_t ao = (uint32_t)(wm * 32 + mt * 16 + a_rowoff) * ROWB +
                              (uint32_t)(ks * 2 + a_segoff) * 16;
                ldsm4(ah[mt], ahb + ao);
            }
#pragma unroll
            for (int np = 0; np < 4; np++) {
                uint32_t bo = (uint32_t)(wn * 64 + np * 16 + b_rowoff) * ROWB +
                              (uint32_t)(ks * 2 + b_segoff) * 16;
                uint32_t bh[4], bl[4];
                ldsm4(bh, bhb + bo);
                ldsm4(bl, blb + bo);
#pragma unroll
                for (int half = 0; half < 2; half++) {
                    const int nt = np * 2 + half;
#pragma unroll
                    for (int mt = 0; mt < 2; mt++) {
                        mma16816h(acc[mt][nt], ah[mt], &bh[half * 2]);
                        mma16816h(acc[mt][nt], ah[mt], &bl[half * 2]);
                    }
                }
            }
        }
    };

    load_chunk(0, 0);
    for (int c = 0; c < NCHUNK; c++) {
        CP_WAIT0();
        __syncthreads();
        if (c + 1 < NCHUNK) load_chunk(c + 1, (c + 1) & 1);
        compute(c & 1);
    }

    const int g = lane >> 2, t = lane & 3;
    if (Dhi) {
        // bf16-split epilogue in [b,h,s,dk] layout (for attention)
#pragma unroll
        for (int mt = 0; mt < 2; mt++) {
#pragma unroll
            for (int nt = 0; nt < 8; nt++) {
                const int col = bn + wn * 64 + nt * 8 + t * 2;
                const int hd = col >> 6, d = col & 63;
#pragma unroll
                for (int hh = 0; hh < 2; hh++) {
                    const int row = bm + wm * 32 + mt * 16 + hh * 8 + g;
                    const int b = row >> 11, s = row & 2047;
                    const long long idx =
                        ((long long)(b * Hh + hd) * Ssz + s) * DKk + d;
                    uint32_t hiw, low;
                    split2(acc[mt][nt][hh * 2 + 0], acc[mt][nt][hh * 2 + 1],
                           hiw, low);
                    *(uint32_t*)(Dhi + idx) = hiw;
                    *(uint32_t*)(Dlo + idx) = low;
                }
            }
        }
    } else {
#pragma unroll
        for (int mt = 0; mt < 2; mt++) {
#pragma unroll
            for (int nt = 0; nt < 8; nt++) {
                const int col = bn + wn * 64 + nt * 8 + t * 2;
                const int row0 = bm + wm * 32 + mt * 16 + g;
                float2 v0 = make_float2(acc[mt][nt][0], acc[mt][nt][1]);
                float2 v1 = make_float2(acc[mt][nt][2], acc[mt][nt][3]);
                if (bias) {
                    float2 bb = *(const float2*)(bias + col);
                    v0.x += bb.x; v0.y += bb.y;
                    v1.x += bb.x; v1.y += bb.y;
                }
                *(float2*)(C + (long long)row0 * Dsz + col) = v0;
                *(float2*)(C + (long long)(row0 + 8) * Dsz + col) = v1;
            }
        }
    }
}

__global__ __launch_bounds__(256, 2)
void qkv_mma_kernel() {
    const unsigned short* Whi = g_whi + (long long)blockIdx.z * Dsz * Dsz;
    const unsigned short* Wlo = g_wlo + (long long)blockIdx.z * Dsz * Dsz;
    unsigned short* Dhi = (blockIdx.z == 0) ? g_Qhi : (blockIdx.z == 1) ? g_Khi : g_Vhi;
    unsigned short* Dlo = (blockIdx.z == 0) ? g_Qlo : (blockIdx.z == 1) ? g_Klo : g_Vlo;
    gemm_mma(g_xh, Whi, Wlo, nullptr, nullptr, Dhi, Dlo);
}

__global__ __launch_bounds__(256, 2)
void out_mma_kernel(const float* __restrict__ bo, float* __restrict__ out) {
    const unsigned short* Whi = g_whi + 3ll * Dsz * Dsz;
    const unsigned short* Wlo = g_wlo + 3ll * Dsz * Dsz;
    gemm_mma(g_ch, Whi, Wlo, out, bo, nullptr, nullptr);
}

// ---------------------------------------------------------------------------
// Tensor-core flash attention (split-bf16), causal — compute unchanged;
// epilogue now writes ctx as plain fp16 (error absorbed by out-GEMM model).
// ---------------------------------------------------------------------------
#define AP 144
#define AMAT (128 * AP)
#define SM_Q 0
#define SM_KV 36864
#define KVBUF (4 * AMAT)
#define SM_STATM (SM_KV + 2 * KVBUF)
#define SM_STATS (SM_STATM + 1024)
#define ATT_SMEM (SM_STATS + 1024)

__global__ __launch_bounds__(256)
void attn_mma_kernel() {
    extern __shared__ char smem[];
    const uint32_t sb = smem_to_u32(smem);
    const int tid = threadIdx.x;
    const int wid = tid >> 5;
    const int lane = tid & 31;
    const int wm = wid & 3;
    const int wn = wid >> 2;
    const int g = lane >> 2, t = lane & 3;
    const int mtx = lane >> 3, r8 = lane & 7;
    const int a_rowoff = (mtx & 1) * 8 + r8;
    const int a_segoff = (mtx >> 1);
    const int b_rowoff = (mtx >> 1) * 8 + r8;
    const int b_segoff = (mtx & 1);

    const int qb = (Ssz / 128 - 1) - blockIdx.x;
    const int q0 = qb * 128;
    const int bh = blockIdx.y;
    const int b = bh >> 4, h = bh & 15;
    const long long base = (long long)bh * Ssz * DKk;

    for (int i = tid; i < 1024; i += 256) {
        int r = i >> 3, c = i & 7;
        *(uint4*)(smem + SM_Q + r * AP + c * 16) =
            *(const uint4*)(g_Qhi + base + (long long)(q0 + r) * DKk + c * 8);
        *(uint4*)(smem + SM_Q + AMAT + r * AP + c * 16) =
            *(const uint4*)(g_Qlo + base + (long long)(q0 + r) * DKk + c * 8);
    }

    auto kv_load = [&](int kt, int buf) {
        const long long rb = base + (long long)kt * 128 * DKk;
        const unsigned short* srcs[4] = {g_Khi, g_Klo, g_Vhi, g_Vlo};
#pragma unroll
        for (int m = 0; m < 4; m++) {
            for (int i = tid; i < 1024; i += 256) {
                int r = i >> 3, c = i & 7;
                cp_async16(sb + SM_KV + buf * KVBUF + m * AMAT + r * AP + c * 16,
                           srcs[m] + rb + r * DKk + c * 8);
            }
        }
        CP_COMMIT();
    };
    kv_load(0, 0);

    float oacc[2][8][4] = {};
    float mrow[4], lrow[4];
#pragma unroll
    for (int r = 0; r < 4; r++) { mrow[r] = -1e30f; lrow[r] = 0.0f; }

    float* statm = (float*)(smem + SM_STATM);
    float* stats = (float*)(smem + SM_STATS);

    const int nkt = qb + 1;
    for (int kt = 0; kt < nkt; kt++) {
        CP_WAIT0();
        __syncthreads();
        if (kt + 1 < nkt) kv_load(kt + 1, (kt + 1) & 1);

        const uint32_t kb = sb + SM_KV + (kt & 1) * KVBUF;
        const uint32_t qh_b = sb + SM_Q;
        const uint32_t ql_b = qh_b + AMAT;

        // ---- S = Q K^T (split bf16) ----
        float sacc[2][8][4] = {};
#pragma unroll
        for (int ks = 0; ks < 4; ks++) {
            uint32_t ah[2][4], al[2][4];
#pragma unroll
            for (int mt = 0; mt < 2; mt++) {
                uint32_t ao = (uint32_t)(wm * 32 + mt * 16 + a_rowoff) * AP +
                              (uint32_t)(ks * 2 + a_segoff) * 16;
                ldsm4(ah[mt], qh_b + ao);
                ldsm4(al[mt], ql_b + ao);
            }
#pragma unroll
            for (int np = 0; np < 4; np++) {
                uint32_t bo = (uint32_t)(wn * 64 + np * 16 + b_rowoff) * AP +
                              (uint32_t)(ks * 2 + b_segoff) * 16;
                uint32_t kh[4], kl[4];
                ldsm4(kh, kb + bo);
                ldsm4(kl, kb + AMAT + bo);
#pragma unroll
                for (int half = 0; half < 2; half++) {
                    const int nt = np * 2 + half;
#pragma unroll
                    for (int mt = 0; mt < 2; mt++) {
                        mma16816(sacc[mt][nt], ah[mt], &kh[half * 2]);
                        mma16816(sacc[mt][nt], ah[mt], &kl[half * 2]);
                        mma16816(sacc[mt][nt], al[mt], &kh[half * 2]);
                    }
                }
            }
        }

        // ---- scale + causal mask ----
        const bool diag = (kt == qb);
#pragma unroll
        for (int mt = 0; mt < 2; mt++)
#pragma unroll
            for (int nt = 0; nt < 8; nt++)
#pragma unroll
                for (int c = 0; c < 4; c++) {
                    float v = sacc[mt][nt][c] * 0.125f;
                    if (diag) {
                        int kidx = wn * 64 + nt * 8 + t * 2 + (c & 1);
                        int qidx = wm * 32 + mt * 16 + (c >> 1) * 8 + g;
                        if (kidx > qidx) v = -1e30f;
                    }
                    sacc[mt][nt][c] = v;
                }

        // ---- online softmax (cross-warp over wn pair) ----
        float pm[4];
#pragma unroll
        for (int r = 0; r < 4; r++) pm[r] = -1e30f;
#pragma unroll
        for (int mt = 0; mt < 2; mt++)
#pragma unroll
            for (int nt = 0; nt < 8; nt++) {
                pm[mt * 2 + 0] = fmaxf(pm[mt * 2 + 0],
                                       fmaxf(sacc[mt][nt][0], sacc[mt][nt][1]));
                pm[mt * 2 + 1] = fmaxf(pm[mt * 2 + 1],
                                       fmaxf(sacc[mt][nt][2], sacc[mt][nt][3]));
            }
#pragma unroll
        for (int r = 0; r < 4; r++) {
            pm[r] = fmaxf(pm[r], __shfl_xor_sync(0xffffffffu, pm[r], 1));
            pm[r] = fmaxf(pm[r], __shfl_xor_sync(0xffffffffu, pm[r], 2));
        }
        if (t == 0) {
#pragma unroll
            for (int r = 0; r < 4; r++) {
                int rowid = wm * 32 + (r >> 1) * 16 + (r & 1) * 8 + g;
                statm[wn * 128 + rowid] = pm[r];
            }
        }
        __syncthreads();
        float alpha[4];
#pragma unroll
        for (int r = 0; r < 4; r++) {
            int rowid = wm * 32 + (r >> 1) * 16 + (r & 1) * 8 + g;
            float rm = fmaxf(pm[r], statm[(wn ^ 1) * 128 + rowid]);
            float mn = fmaxf(mrow[r], rm);
            alpha[r] = __expf(mrow[r] - mn);
            mrow[r] = mn;
        }
        float psum[4] = {0.f, 0.f, 0.f, 0.f};
#pragma unroll
        for (int mt = 0; mt < 2; mt++)
#pragma unroll
            for (int nt = 0; nt < 8; nt++)
#pragma unroll
                for (int c = 0; c < 4; c++) {
                    int r = mt * 2 + (c >> 1);
                    float p = __expf(sacc[mt][nt][c] - mrow[r]);
                    sacc[mt][nt][c] = p;
                    psum[r] += p;
                }
#pragma unroll
        for (int r = 0; r < 4; r++) {
            psum[r] += __shfl_xor_sync(0xffffffffu, psum[r], 1);
            psum[r] += __shfl_xor_sync(0xffffffffu, psum[r], 2);
        }
        if (t == 0) {
#pragma unroll
            for (int r = 0; r < 4; r++) {
                int rowid = wm * 32 + (r >> 1) * 16 + (r & 1) * 8 + g;
                stats[wn * 128 + rowid] = psum[r];
            }
        }
        __syncthreads();
#pragma unroll
        for (int r = 0; r < 4; r++) {
            int rowid = wm * 32 + (r >> 1) * 16 + (r & 1) * 8 + g;
            float tot = psum[r] + stats[(wn ^ 1) * 128 + rowid];
            lrow[r] = lrow[r] * alpha[r] + tot;
        }
#pragma unroll
        for (int mt = 0; mt < 2; mt++)
#pragma unroll
            for (int nt = 0; nt < 8; nt++)
#pragma unroll
                for (int c = 0; c < 4; c++)
                    oacc[mt][nt][c] *= alpha[mt * 2 + (c >> 1)];

        // ---- O += P V (split bf16), warp's 64 keys, full d range ----
        const uint32_t vh_b = kb + 2 * AMAT;
        const uint32_t vl_b = kb + 3 * AMAT;
#pragma unroll
        for (int ks = 0; ks < 4; ks++) {
            uint32_t ph[2][4], pl[2][4];
#pragma unroll
            for (int mt = 0; mt < 2; mt++) {
                const float* s0 = sacc[mt][2 * ks];
                const float* s1 = sacc[mt][2 * ks + 1];
                split2(s0[0], s0[1], ph[mt][0], pl[mt][0]);
                split2(s0[2], s0[3], ph[mt][1], pl[mt][1]);
                split2(s1[0], s1[1], ph[mt][2], pl[mt][2]);
                split2(s1[2], s1[3], ph[mt][3], pl[mt][3]);
            }
#pragma unroll
            for (int dp = 0; dp < 4; dp++) {
                uint32_t vo = (uint32_t)(wn * 64 + ks * 16 + (mtx & 1) * 8 + r8) * AP +
                              (uint32_t)(dp * 16 + (mtx >> 1) * 8) * 2;
                uint32_t vh[4], vl[4];
                ldsm4t(vh, vh_b + vo);
                ldsm4t(vl, vl_b + vo);
#pragma unroll
                for (int half = 0; half < 2; half++) {
                    const int nt = dp * 2 + half;
#pragma unroll
                    for (int mt = 0; mt < 2; mt++) {
                        mma16816(oacc[mt][nt], ph[mt], &vh[half * 2]);
                        mma16816(oacc[mt][nt], ph[mt], &vl[half * 2]);
                        mma16816(oacc[mt][nt], pl[mt], &vh[half * 2]);
                    }
                }
            }
        }
    }

    // ---- epilogue: sum partial O across wn pair, normalize, write fp16 ctx
    __syncthreads();
    float* Oex = (float*)smem;   // [128][64] = 32 KB
    if (wn == 1) {
#pragma unroll
        for (int mt = 0; mt < 2; mt++)
#pragma unroll
            for (int nt = 0; nt < 8; nt++)
#pragma unroll
                for (int c = 0; c < 4; c++) {
                    int row = wm * 32 + mt * 16 + (c >> 1) * 8 + g;
                    int col = nt * 8 + t * 2 + (c & 1);
                    Oex[row * 64 + col] = oacc[mt][nt][c];
                }
    }
    __syncthreads();
    if (wn == 0) {
        float inv[4];
#pragma unroll
        for (int r = 0; r < 4; r++) inv[r] = 1.0f / lrow[r];
#pragma unroll
        for (int mt = 0; mt < 2; mt++)
#pragma unroll
            for (int nt = 0; nt < 8; nt++)
#pragma unroll
                for (int hh = 0; hh < 2; hh++) {
                    int row = wm * 32 + mt * 16 + hh * 8 + g;
                    int col = nt * 8 + t * 2;
                    float v0 = (oacc[mt][nt][hh * 2 + 0] + Oex[row * 64 + col]) *
                               inv[mt * 2 + hh];
                    float v1 = (oacc[mt][nt][hh * 2 + 1] + Oex[row * 64 + col + 1]) *
                               inv[mt * 2 + hh];
                    long long dst = ((long long)(b * Ssz + q0 + row)) * Dsz +
                                    h * DKk + col;
                    *(uint32_t*)(g_ch + dst) = packh(v0, v1);
                }
    }
}

// ---------------------------------------------------------------------------
extern "C" void kernel_launch(void* const* d_in, const int* in_sizes, int n_in,
                              void* d_out, int out_size) {
    const float* x  = (const float*)d_in[0];
    const float* wq = (const float*)d_in[1];
    const float* wk = (const float*)d_in[2];
    const float* wv = (const float*)d_in[3];
    const float* wo = (const float*)d_in[4];
    const float* bo = (const float*)d_in[5];
    float* out = (float*)d_out;

    cudaFuncSetAttribute(qkv_mma_kernel,
                         cudaFuncAttributeMaxDynamicSharedMemorySize, GEMM_SMEM_TOTAL);
    cudaFuncSetAttribute(out_mma_kernel,
                         cudaFuncAttributeMaxDynamicSharedMemorySize, GEMM_SMEM_TOTAL);
    cudaFuncSetAttribute(attn_mma_kernel,
                         cudaFuncAttributeMaxDynamicSharedMemorySize, ATT_SMEM);

    unsigned short *xh, *whi, *wlo;
    cudaGetSymbolAddress((void**)&xh, g_xh);
    cudaGetSymbolAddress((void**)&whi, g_whi);
    cudaGetSymbolAddress((void**)&wlo, g_wlo);

    const int n4x = Mrows * Dsz / 4;
    const int n4w = Dsz * Dsz / 4;

    convert_f16_kernel<<<(n4x + 255) / 256, 256>>>(
        (const float4*)x, (uint2*)xh, n4x);
    convert_split_f16_kernel<<<(n4w + 255) / 256, 256>>>(
        (const float4*)wq, (uint2*)(whi + 0ll * Dsz * Dsz), (uint2*)(wlo + 0ll * Dsz * Dsz), n4w);
    convert_split_f16_kernel<<<(n4w + 255) / 256, 256>>>(
        (const float4*)wk, (uint2*)(whi + 1ll * Dsz * Dsz), (uint2*)(wlo + 1ll * Dsz * Dsz), n4w);
    convert_split_f16_kernel<<<(n4w + 255) / 256, 256>>>(
        (const float4*)wv, (uint2*)(whi + 2ll * Dsz * Dsz), (uint2*)(wlo + 2ll * Dsz * Dsz), n4w);
    convert_split_f16_kernel<<<(n4w + 255) / 256, 256>>>(
        (const float4*)wo, (uint2*)(whi + 3ll * Dsz * Dsz), (uint2*)(wlo + 3ll * Dsz * Dsz), n4w);

    dim3 g1(Dsz / 128, Mrows / 128, 3);
    qkv_mma_kernel<<<g1, 256, GEMM_SMEM_TOTAL>>>();

    dim3 g2(Ssz / 128, Bsz * Hh);
    attn_mma_kernel<<<g2, 256, ATT_SMEM>>>();

    dim3 g3(Dsz / 128, Mrows / 128);
    out_mma_kernel<<<g3, 256, GEMM_SMEM_TOTAL>>>(bo, out);
}

// round 12
// speedup vs baseline: 4.4165x; 1.1395x over previous
#include <cuda_runtime.h>
#include <cuda_bf16.h>
#include <cuda_fp16.h>
#include <math.h>
#include <cstdint>

// Problem constants
#define Bsz 4
#define Ssz 2048
#define Dsz 1024
#define Hh  16
#define DKk 64
#define Mrows (Bsz * Ssz)   // 8192

// ---------------------------------------------------------------------------
// Scratch (device globals)
// g_xh : x fp16          g_whi/g_wlo : weights fp16 hi/lo
// g_ch : ctx fp16        g_Qh : Q fp16 plain [b,h,s,dk]
// g_K/Vhi+lo : K,V fp16 split [b,h,s,dk]
// ---------------------------------------------------------------------------
__device__ unsigned short g_xh[(long long)Mrows * Dsz];
__device__ unsigned short g_ch[(long long)Mrows * Dsz];
__device__ unsigned short g_whi[4ll * Dsz * Dsz];
__device__ unsigned short g_wlo[4ll * Dsz * Dsz];
__device__ unsigned short g_Qh[(long long)Mrows * Dsz];
__device__ unsigned short g_Khi[(long long)Mrows * Dsz];
__device__ unsigned short g_Klo[(long long)Mrows * Dsz];
__device__ unsigned short g_Vhi[(long long)Mrows * Dsz];
__device__ unsigned short g_Vlo[(long long)Mrows * Dsz];

// ---------------------------------------------------------------------------
// PTX helpers (portable ISA: ldmatrix / mma.sync / cp.async, sm_80+)
// ---------------------------------------------------------------------------
__device__ __forceinline__ uint32_t smem_to_u32(const void* p) {
    uint32_t a;
    asm("{ .reg .u64 t; cvta.to.shared.u64 t, %1; cvt.u32.u64 %0, t; }"
        : "=r"(a) : "l"(p));
    return a;
}
__device__ __forceinline__ void ldsm4(uint32_t* r, uint32_t addr) {
    asm volatile("ldmatrix.sync.aligned.m8n8.x4.shared.b16 {%0,%1,%2,%3}, [%4];"
                 : "=r"(r[0]), "=r"(r[1]), "=r"(r[2]), "=r"(r[3]) : "r"(addr));
}
__device__ __forceinline__ void ldsm4t(uint32_t* r, uint32_t addr) {
    asm volatile("ldmatrix.sync.aligned.m8n8.x4.trans.shared.b16 {%0,%1,%2,%3}, [%4];"
                 : "=r"(r[0]), "=r"(r[1]), "=r"(r[2]), "=r"(r[3]) : "r"(addr));
}
// fp16 mma
__device__ __forceinline__ void mma16816h(float* d, const uint32_t* a,
                                          const uint32_t* b) {
    asm volatile(
        "mma.sync.aligned.m16n8k16.row.col.f32.f16.f16.f32 "
        "{%0,%1,%2,%3}, {%4,%5,%6,%7}, {%8,%9}, {%0,%1,%2,%3};"
        : "+f"(d[0]), "+f"(d[1]), "+f"(d[2]), "+f"(d[3])
        : "r"(a[0]), "r"(a[1]), "r"(a[2]), "r"(a[3]), "r"(b[0]), "r"(b[1]));
}
__device__ __forceinline__ void cp_async16(uint32_t saddr, const void* g) {
    asm volatile("cp.async.cg.shared.global [%0], [%1], 16;"
                 :: "r"(saddr), "l"(g));
}
#define CP_COMMIT() asm volatile("cp.async.commit_group;" ::: "memory")
#define CP_WAIT0()  asm volatile("cp.async.wait_group 0;" ::: "memory")

__device__ __forceinline__ uint32_t packh(float a, float b) {
    __half2 h = __floats2half2_rn(a, b);
    return *reinterpret_cast<uint32_t*>(&h);
}
__device__ __forceinline__ float h_round(float v) {
    return __half2float(__float2half_rn(v));
}
__device__ __forceinline__ void splith2(float v0, float v1,
                                        uint32_t& hi, uint32_t& lo) {
    hi = packh(v0, v1);
    lo = packh(v0 - h_round(v0), v1 - h_round(v1));
}

// ---------------------------------------------------------------------------
// Conversion kernels
// ---------------------------------------------------------------------------
__global__ __launch_bounds__(256)
void convert_f16_kernel(const float4* __restrict__ src,
                        uint2* __restrict__ dst, int n4) {
    int i = blockIdx.x * blockDim.x + threadIdx.x;
    if (i >= n4) return;
    float4 v = src[i];
    dst[i] = make_uint2(packh(v.x, v.y), packh(v.z, v.w));
}
__global__ __launch_bounds__(256)
void convert_split_f16_kernel(const float4* __restrict__ src,
                              uint2* __restrict__ hi, uint2* __restrict__ lo,
                              int n4) {
    int i = blockIdx.x * blockDim.x + threadIdx.x;
    if (i >= n4) return;
    float4 v = src[i];
    uint32_t h01, l01, h23, l23;
    splith2(v.x, v.y, h01, l01);
    splith2(v.z, v.w, h23, l23);
    hi[i] = make_uint2(h01, h23);
    lo[i] = make_uint2(l01, l23);
}

// ---------------------------------------------------------------------------
// fp16 2-term NT GEMM: C = A_fp16 . (W_hi + W_lo)^T   (CTA 128x128, BK=32)
// Epilogue variants: fp32 C (+bias) | fp16 split (K/V) | fp16 plain (Q)
// ---------------------------------------------------------------------------
#define ROWB 80
#define MATB (128 * ROWB)
#define GEMM_SMEM_TOTAL (2 * 3 * MATB)   // 61440 B
#define NCHUNK (Dsz / 32)

__device__ __forceinline__ void gemm_mma(const unsigned short* __restrict__ Ah,
                                         const unsigned short* __restrict__ Whi,
                                         const unsigned short* __restrict__ Wlo,
                                         float* __restrict__ C,
                                         const float* __restrict__ bias,
                                         unsigned short* __restrict__ Dhi,
                                         unsigned short* __restrict__ Dlo) {
    extern __shared__ char smem[];
    const uint32_t sbase = smem_to_u32(smem);
    const int tid = threadIdx.x;
    const int wid = tid >> 5;
    const int lane = tid & 31;
    const int wm = wid & 3;
    const int wn = wid >> 2;
    const int bm = blockIdx.y * 128;
    const int bn = blockIdx.x * 128;

    const int s0 = tid, s1 = tid + 256;
    const int r0g = s0 >> 2, c0g = (s0 & 3) * 8;
    const int r1g = s1 >> 2, c1g = (s1 & 3) * 8;

    const unsigned short* gp[3] = {Ah, Whi, Wlo};
    const long long rowbase[3] = {
        (long long)(bm + r0g) * Dsz,
        (long long)(bn + r0g) * Dsz, (long long)(bn + r0g) * Dsz};
    const long long rowbase1[3] = {
        (long long)(bm + r1g) * Dsz,
        (long long)(bn + r1g) * Dsz, (long long)(bn + r1g) * Dsz};

    float acc[2][8][4] = {};

    auto load_chunk = [&](int c, int buf) {
        const int k0 = c * 32;
        const uint32_t b = sbase + buf * 3 * MATB;
#pragma unroll
        for (int m = 0; m < 3; m++) {
            cp_async16(b + m * MATB + r0g * ROWB + (s0 & 3) * 16,
                       gp[m] + rowbase[m] + k0 + c0g);
            cp_async16(b + m * MATB + r1g * ROWB + (s1 & 3) * 16,
                       gp[m] + rowbase1[m] + k0 + c1g);
        }
        CP_COMMIT();
    };

    const int mtx = lane >> 3;
    const int r8 = lane & 7;
    const int a_rowoff = (mtx & 1) * 8 + r8;
    const int a_segoff = (mtx >> 1);
    const int b_rowoff = (mtx >> 1) * 8 + r8;
    const int b_segoff = (mtx & 1);

    auto compute = [&](int buf) {
        const uint32_t ahb = sbase + buf * 3 * MATB;
        const uint32_t bhb = ahb + MATB;
        const uint32_t blb = ahb + 2 * MATB;
#pragma unroll
        for (int ks = 0; ks < 2; ks++) {
            uint32_t ah[2][4];
#pragma unroll
            for (int mt = 0; mt < 2; mt++) {
                uint32_t ao = (uint32_t)(wm * 32 + mt * 16 + a_rowoff) * ROWB +
                              (uint32_t)(ks * 2 + a_segoff) * 16;
                ldsm4(ah[mt], ahb + ao);
            }
#pragma unroll
            for (int np = 0; np < 4; np++) {
                uint32_t bo = (uint32_t)(wn * 64 + np * 16 + b_rowoff) * ROWB +
                              (uint32_t)(ks * 2 + b_segoff) * 16;
                uint32_t bh[4], bl[4];
                ldsm4(bh, bhb + bo);
                ldsm4(bl, blb + bo);
#pragma unroll
                for (int half = 0; half < 2; half++) {
                    const int nt = np * 2 + half;
#pragma unroll
                    for (int mt = 0; mt < 2; mt++) {
                        mma16816h(acc[mt][nt], ah[mt], &bh[half * 2]);
                        mma16816h(acc[mt][nt], ah[mt], &bl[half * 2]);
                    }
                }
            }
        }
    };

    load_chunk(0, 0);
    for (int c = 0; c < NCHUNK; c++) {
        CP_WAIT0();
        __syncthreads();
        if (c + 1 < NCHUNK) load_chunk(c + 1, (c + 1) & 1);
        compute(c & 1);
    }

    const int g = lane >> 2, t = lane & 3;
    if (Dhi) {
        // fp16 epilogue in [b,h,s,dk] layout: split (Dlo) or plain (Q)
#pragma unroll
        for (int mt = 0; mt < 2; mt++) {
#pragma unroll
            for (int nt = 0; nt < 8; nt++) {
                const int col = bn + wn * 64 + nt * 8 + t * 2;
                const int hd = col >> 6, d = col & 63;
#pragma unroll
                for (int hh = 0; hh < 2; hh++) {
                    const int row = bm + wm * 32 + mt * 16 + hh * 8 + g;
                    const int b = row >> 11, s = row & 2047;
                    const long long idx =
                        ((long long)(b * Hh + hd) * Ssz + s) * DKk + d;
                    float v0 = acc[mt][nt][hh * 2 + 0];
                    float v1 = acc[mt][nt][hh * 2 + 1];
                    if (Dlo) {
                        uint32_t hiw, low;
                        splith2(v0, v1, hiw, low);
                        *(uint32_t*)(Dhi + idx) = hiw;
                        *(uint32_t*)(Dlo + idx) = low;
                    } else {
                        *(uint32_t*)(Dhi + idx) = packh(v0, v1);
                    }
                }
            }
        }
    } else {
#pragma unroll
        for (int mt = 0; mt < 2; mt++) {
#pragma unroll
            for (int nt = 0; nt < 8; nt++) {
                const int col = bn + wn * 64 + nt * 8 + t * 2;
                const int row0 = bm + wm * 32 + mt * 16 + g;
                float2 v0 = make_float2(acc[mt][nt][0], acc[mt][nt][1]);
                float2 v1 = make_float2(acc[mt][nt][2], acc[mt][nt][3]);
                if (bias) {
                    float2 bb = *(const float2*)(bias + col);
                    v0.x += bb.x; v0.y += bb.y;
                    v1.x += bb.x; v1.y += bb.y;
                }
                *(float2*)(C + (long long)row0 * Dsz + col) = v0;
                *(float2*)(C + (long long)(row0 + 8) * Dsz + col) = v1;
            }
        }
    }
}

__global__ __launch_bounds__(256, 2)
void qkv_mma_kernel() {
    const unsigned short* Whi = g_whi + (long long)blockIdx.z * Dsz * Dsz;
    const unsigned short* Wlo = g_wlo + (long long)blockIdx.z * Dsz * Dsz;
    unsigned short* Dhi = (blockIdx.z == 0) ? g_Qh : (blockIdx.z == 1) ? g_Khi : g_Vhi;
    unsigned short* Dlo = (blockIdx.z == 0) ? nullptr : (blockIdx.z == 1) ? g_Klo : g_Vlo;
    gemm_mma(g_xh, Whi, Wlo, nullptr, nullptr, Dhi, Dlo);
}

__global__ __launch_bounds__(256, 2)
void out_mma_kernel(const float* __restrict__ bo, float* __restrict__ out) {
    const unsigned short* Whi = g_whi + 3ll * Dsz * Dsz;
    const unsigned short* Wlo = g_wlo + 3ll * Dsz * Dsz;
    gemm_mma(g_ch, Whi, Wlo, out, bo, nullptr, nullptr);
}

// ---------------------------------------------------------------------------
// Tensor-core flash attention, causal — fp16 2-term everywhere.
// S = Qfp16 . (Khi+Klo)^T ; O += Pfp16 . (Vhi+Vlo)
// CTA: 128 queries; 8 warps 4m x 2n.
// ---------------------------------------------------------------------------
#define AP 144
#define AMAT (128 * AP)
#define SM_Q 0                        // 1 matrix (Q fp16): AMAT
#define SM_KV AMAT                    // 2 buffers x 4 matrices (Khi,Klo,Vhi,Vlo)
#define KVBUF (4 * AMAT)
#define SM_STATM (SM_KV + 2 * KVBUF)  // float [2][128]
#define SM_STATS (SM_STATM + 1024)
#define ATT_SMEM (SM_STATS + 1024)    // 165888 + 2048 = 167936 B

__global__ __launch_bounds__(256)
void attn_mma_kernel() {
    extern __shared__ char smem[];
    const uint32_t sb = smem_to_u32(smem);
    const int tid = threadIdx.x;
    const int wid = tid >> 5;
    const int lane = tid & 31;
    const int wm = wid & 3;
    const int wn = wid >> 2;
    const int g = lane >> 2, t = lane & 3;
    const int mtx = lane >> 3, r8 = lane & 7;
    const int a_rowoff = (mtx & 1) * 8 + r8;
    const int a_segoff = (mtx >> 1);
    const int b_rowoff = (mtx >> 1) * 8 + r8;
    const int b_segoff = (mtx & 1);

    const int qb = (Ssz / 128 - 1) - blockIdx.x;
    const int q0 = qb * 128;
    const int bh = blockIdx.y;
    const int b = bh >> 4, h = bh & 15;
    const long long base = (long long)bh * Ssz * DKk;

    // Load Q (plain fp16) into smem
    for (int i = tid; i < 1024; i += 256) {
        int r = i >> 3, c = i & 7;
        *(uint4*)(smem + SM_Q + r * AP + c * 16) =
            *(const uint4*)(g_Qh + base + (long long)(q0 + r) * DKk + c * 8);
    }

    auto kv_load = [&](int kt, int buf) {
        const long long rb = base + (long long)kt * 128 * DKk;
        const unsigned short* srcs[4] = {g_Khi, g_Klo, g_Vhi, g_Vlo};
#pragma unroll
        for (int m = 0; m < 4; m++) {
            for (int i = tid; i < 1024; i += 256) {
                int r = i >> 3, c = i & 7;
                cp_async16(sb + SM_KV + buf * KVBUF + m * AMAT + r * AP + c * 16,
                           srcs[m] + rb + r * DKk + c * 8);
            }
        }
        CP_COMMIT();
    };
    kv_load(0, 0);

    float oacc[2][8][4] = {};
    float mrow[4], lrow[4];
#pragma unroll
    for (int r = 0; r < 4; r++) { mrow[r] = -1e30f; lrow[r] = 0.0f; }

    float* statm = (float*)(smem + SM_STATM);
    float* stats = (float*)(smem + SM_STATS);

    const int nkt = qb + 1;
    for (int kt = 0; kt < nkt; kt++) {
        CP_WAIT0();
        __syncthreads();
        if (kt + 1 < nkt) kv_load(kt + 1, (kt + 1) & 1);

        const uint32_t kb = sb + SM_KV + (kt & 1) * KVBUF;   // Khi
        const uint32_t qh_b = sb + SM_Q;

        // ---- S = Q (Khi+Klo)^T, fp16 ----
        float sacc[2][8][4] = {};
#pragma unroll
        for (int ks = 0; ks < 4; ks++) {
            uint32_t ah[2][4];
#pragma unroll
            for (int mt = 0; mt < 2; mt++) {
                uint32_t ao = (uint32_t)(wm * 32 + mt * 16 + a_rowoff) * AP +
                              (uint32_t)(ks * 2 + a_segoff) * 16;
                ldsm4(ah[mt], qh_b + ao);
            }
#pragma unroll
            for (int np = 0; np < 4; np++) {
                uint32_t bo = (uint32_t)(wn * 64 + np * 16 + b_rowoff) * AP +
                              (uint32_t)(ks * 2 + b_segoff) * 16;
                uint32_t kh[4], kl[4];
                ldsm4(kh, kb + bo);
                ldsm4(kl, kb + AMAT + bo);
#pragma unroll
                for (int half = 0; half < 2; half++) {
                    const int nt = np * 2 + half;
#pragma unroll
                    for (int mt = 0; mt < 2; mt++) {
                        mma16816h(sacc[mt][nt], ah[mt], &kh[half * 2]);
                        mma16816h(sacc[mt][nt], ah[mt], &kl[half * 2]);
                    }
                }
            }
        }

        // ---- scale + causal mask ----
        const bool diag = (kt == qb);
#pragma unroll
        for (int mt = 0; mt < 2; mt++)
#pragma unroll
            for (int nt = 0; nt < 8; nt++)
#pragma unroll
                for (int c = 0; c < 4; c++) {
                    float v = sacc[mt][nt][c] * 0.125f;
                    if (diag) {
                        int kidx = wn * 64 + nt * 8 + t * 2 + (c & 1);
                        int qidx = wm * 32 + mt * 16 + (c >> 1) * 8 + g;
                        if (kidx > qidx) v = -1e30f;
                    }
                    sacc[mt][nt][c] = v;
                }

        // ---- online softmax (cross-warp over wn pair) ----
        float pm[4];
#pragma unroll
        for (int r = 0; r < 4; r++) pm[r] = -1e30f;
#pragma unroll
        for (int mt = 0; mt < 2; mt++)
#pragma unroll
            for (int nt = 0; nt < 8; nt++) {
                pm[mt * 2 + 0] = fmaxf(pm[mt * 2 + 0],
                                       fmaxf(sacc[mt][nt][0], sacc[mt][nt][1]));
                pm[mt * 2 + 1] = fmaxf(pm[mt * 2 + 1],
                                       fmaxf(sacc[mt][nt][2], sacc[mt][nt][3]));
            }
#pragma unroll
        for (int r = 0; r < 4; r++) {
            pm[r] = fmaxf(pm[r], __shfl_xor_sync(0xffffffffu, pm[r], 1));
            pm[r] = fmaxf(pm[r], __shfl_xor_sync(0xffffffffu, pm[r], 2));
        }
        if (t == 0) {
#pragma unroll
            for (int r = 0; r < 4; r++) {
                int rowid = wm * 32 + (r >> 1) * 16 + (r & 1) * 8 + g;
                statm[wn * 128 + rowid] = pm[r];
            }
        }
        __syncthreads();
        float alpha[4];
#pragma unroll
        for (int r = 0; r < 4; r++) {
            int rowid = wm * 32 + (r >> 1) * 16 + (r & 1) * 8 + g;
            float rm = fmaxf(pm[r], statm[(wn ^ 1) * 128 + rowid]);
            float mn = fmaxf(mrow[r], rm);
            alpha[r] = __expf(mrow[r] - mn);
            mrow[r] = mn;
        }
        float psum[4] = {0.f, 0.f, 0.f, 0.f};
#pragma unroll
        for (int mt = 0; mt < 2; mt++)
#pragma unroll
            for (int nt = 0; nt < 8; nt++)
#pragma unroll
                for (int c = 0; c < 4; c++) {
                    int r = mt * 2 + (c >> 1);
                    float p = __expf(sacc[mt][nt][c] - mrow[r]);
                    sacc[mt][nt][c] = p;
                    psum[r] += p;
                }
#pragma unroll
        for (int r = 0; r < 4; r++) {
            psum[r] += __shfl_xor_sync(0xffffffffu, psum[r], 1);
            psum[r] += __shfl_xor_sync(0xffffffffu, psum[r], 2);
        }
        if (t == 0) {
#pragma unroll
            for (int r = 0; r < 4; r++) {
                int rowid = wm * 32 + (r >> 1) * 16 + (r & 1) * 8 + g;
                stats[wn * 128 + rowid] = psum[r];
            }
        }
        __syncthreads();
#pragma unroll
        for (int r = 0; r < 4; r++) {
            int rowid = wm * 32 + (r >> 1) * 16 + (r & 1) * 8 + g;
            float tot = psum[r] + stats[(wn ^ 1) * 128 + rowid];
            lrow[r] = lrow[r] * alpha[r] + tot;
        }
#pragma unroll
        for (int mt = 0; mt < 2; mt++)
#pragma unroll
            for (int nt = 0; nt < 8; nt++)
#pragma unroll
                for (int c = 0; c < 4; c++)
                    oacc[mt][nt][c] *= alpha[mt * 2 + (c >> 1)];

        // ---- O += P (Vhi+Vlo), fp16 P, full d range ----
        const uint32_t vh_b = kb + 2 * AMAT;
        const uint32_t vl_b = kb + 3 * AMAT;
#pragma unroll
        for (int ks = 0; ks < 4; ks++) {
            uint32_t ph[2][4];
#pragma unroll
            for (int mt = 0; mt < 2; mt++) {
                const float* s0 = sacc[mt][2 * ks];
                const float* s1 = sacc[mt][2 * ks + 1];
                ph[mt][0] = packh(s0[0], s0[1]);
                ph[mt][1] = packh(s0[2], s0[3]);
                ph[mt][2] = packh(s1[0], s1[1]);
                ph[mt][3] = packh(s1[2], s1[3]);
            }
#pragma unroll
            for (int dp = 0; dp < 4; dp++) {
                uint32_t vo = (uint32_t)(wn * 64 + ks * 16 + (mtx & 1) * 8 + r8) * AP +
                              (uint32_t)(dp * 16 + (mtx >> 1) * 8) * 2;
                uint32_t vh[4], vl[4];
                ldsm4t(vh, vh_b + vo);
                ldsm4t(vl, vl_b + vo);
#pragma unroll
                for (int half = 0; half < 2; half++) {
                    const int nt = dp * 2 + half;
#pragma unroll
                    for (int mt = 0; mt < 2; mt++) {
                        mma16816h(oacc[mt][nt], ph[mt], &vh[half * 2]);
                        mma16816h(oacc[mt][nt], ph[mt], &vl[half * 2]);
                    }
                }
            }
        }
    }

    // ---- epilogue: sum partial O across wn pair, normalize, write fp16 ctx
    __syncthreads();
    float* Oex = (float*)smem;   // [128][64] = 32 KB
    if (wn == 1) {
#pragma unroll
        for (int mt = 0; mt < 2; mt++)
#pragma unroll
            for (int nt = 0; nt < 8; nt++)
#pragma unroll
                for (int c = 0; c < 4; c++) {
                    int row = wm * 32 + mt * 16 + (c >> 1) * 8 + g;
                    int col = nt * 8 + t * 2 + (c & 1);
                    Oex[row * 64 + col] = oacc[mt][nt][c];
                }
    }
    __syncthreads();
    if (wn == 0) {
        float inv[4];
#pragma unroll
        for (int r = 0; r < 4; r++) inv[r] = 1.0f / lrow[r];
#pragma unroll
        for (int mt = 0; mt < 2; mt++)
#pragma unroll
            for (int nt = 0; nt < 8; nt++)
#pragma unroll
                for (int hh = 0; hh < 2; hh++) {
                    int row = wm * 32 + mt * 16 + hh * 8 + g;
                    int col = nt * 8 + t * 2;
                    float v0 = (oacc[mt][nt][hh * 2 + 0] + Oex[row * 64 + col]) *
                               inv[mt * 2 + hh];
                    float v1 = (oacc[mt][nt][hh * 2 + 1] + Oex[row * 64 + col + 1]) *
                               inv[mt * 2 + hh];
                    long long dst = ((long long)(b * Ssz + q0 + row)) * Dsz +
                                    h * DKk + col;
                    *(uint32_t*)(g_ch + dst) = packh(v0, v1);
                }
    }
}

// ---------------------------------------------------------------------------
extern "C" void kernel_launch(void* const* d_in, const int* in_sizes, int n_in,
                              void* d_out, int out_size) {
    const float* x  = (const float*)d_in[0];
    const float* wq = (const float*)d_in[1];
    const float* wk = (const float*)d_in[2];
    const float* wv = (const float*)d_in[3];
    const float* wo = (const float*)d_in[4];
    const float* bo = (const float*)d_in[5];
    float* out = (float*)d_out;

    cudaFuncSetAttribute(qkv_mma_kernel,
                         cudaFuncAttributeMaxDynamicSharedMemorySize, GEMM_SMEM_TOTAL);
    cudaFuncSetAttribute(out_mma_kernel,
                         cudaFuncAttributeMaxDynamicSharedMemorySize, GEMM_SMEM_TOTAL);
    cudaFuncSetAttribute(attn_mma_kernel,
                         cudaFuncAttributeMaxDynamicSharedMemorySize, ATT_SMEM);

    unsigned short *xh, *whi, *wlo;
    cudaGetSymbolAddress((void**)&xh, g_xh);
    cudaGetSymbolAddress((void**)&whi, g_whi);
    cudaGetSymbolAddress((void**)&wlo, g_wlo);

    const int n4x = Mrows * Dsz / 4;
    const int n4w = Dsz * Dsz / 4;

    convert_f16_kernel<<<(n4x + 255) / 256, 256>>>(
        (const float4*)x, (uint2*)xh, n4x);
    convert_split_f16_kernel<<<(n4w + 255) / 256, 256>>>(
        (const float4*)wq, (uint2*)(whi + 0ll * Dsz * Dsz), (uint2*)(wlo + 0ll * Dsz * Dsz), n4w);
    convert_split_f16_kernel<<<(n4w + 255) / 256, 256>>>(
        (const float4*)wk, (uint2*)(whi + 1ll * Dsz * Dsz), (uint2*)(wlo + 1ll * Dsz * Dsz), n4w);
    convert_split_f16_kernel<<<(n4w + 255) / 256, 256>>>(
        (const float4*)wv, (uint2*)(whi + 2ll * Dsz * Dsz), (uint2*)(wlo + 2ll * Dsz * Dsz), n4w);
    convert_split_f16_kernel<<<(n4w + 255) / 256, 256>>>(
        (const float4*)wo, (uint2*)(whi + 3ll * Dsz * Dsz), (uint2*)(wlo + 3ll * Dsz * Dsz), n4w);

    dim3 g1(Dsz / 128, Mrows / 128, 3);
    qkv_mma_kernel<<<g1, 256, GEMM_SMEM_TOTAL>>>();

    dim3 g2(Ssz / 128, Bsz * Hh);
    attn_mma_kernel<<<g2, 256, ATT_SMEM>>>();

    dim3 g3(Dsz / 128, Mrows / 128);
    out_mma_kernel<<<g3, 256, GEMM_SMEM_TOTAL>>>(bo, out);
}

// round 13
// speedup vs baseline: 5.4713x; 1.2389x over previous
#include <cuda_runtime.h>
#include <cuda_bf16.h>
#include <cuda_fp16.h>
#include <math.h>
#include <cstdint>

// Problem constants
#define Bsz 4
#define Ssz 2048
#define Dsz 1024
#define Hh  16
#define DKk 64
#define Mrows (Bsz * Ssz)   // 8192

// ---------------------------------------------------------------------------
// Scratch (device globals)
// g_xh : x fp16            g_whi/g_wlo : wq,wk,wv fp16 hi/lo; wo plain in whi[3]
// g_ch : ctx fp16          g_Qh/g_Kh/g_Vh : Q,K,V plain fp16 [b,h,s,dk]
// ---------------------------------------------------------------------------
__device__ unsigned short g_xh[(long long)Mrows * Dsz];
__device__ unsigned short g_ch[(long long)Mrows * Dsz];
__device__ unsigned short g_whi[4ll * Dsz * Dsz];
__device__ unsigned short g_wlo[3ll * Dsz * Dsz];
__device__ unsigned short g_Qh[(long long)Mrows * Dsz];
__device__ unsigned short g_Kh[(long long)Mrows * Dsz];
__device__ unsigned short g_Vh[(long long)Mrows * Dsz];

// ---------------------------------------------------------------------------
// PTX helpers (portable ISA: ldmatrix / mma.sync / cp.async, sm_80+)
// ---------------------------------------------------------------------------
__device__ __forceinline__ uint32_t smem_to_u32(const void* p) {
    uint32_t a;
    asm("{ .reg .u64 t; cvta.to.shared.u64 t, %1; cvt.u32.u64 %0, t; }"
        : "=r"(a) : "l"(p));
    return a;
}
__device__ __forceinline__ void ldsm4(uint32_t* r, uint32_t addr) {
    asm volatile("ldmatrix.sync.aligned.m8n8.x4.shared.b16 {%0,%1,%2,%3}, [%4];"
                 : "=r"(r[0]), "=r"(r[1]), "=r"(r[2]), "=r"(r[3]) : "r"(addr));
}
__device__ __forceinline__ void ldsm4t(uint32_t* r, uint32_t addr) {
    asm volatile("ldmatrix.sync.aligned.m8n8.x4.trans.shared.b16 {%0,%1,%2,%3}, [%4];"
                 : "=r"(r[0]), "=r"(r[1]), "=r"(r[2]), "=r"(r[3]) : "r"(addr));
}
__device__ __forceinline__ void mma16816h(float* d, const uint32_t* a,
                                          const uint32_t* b) {
    asm volatile(
        "mma.sync.aligned.m16n8k16.row.col.f32.f16.f16.f32 "
        "{%0,%1,%2,%3}, {%4,%5,%6,%7}, {%8,%9}, {%0,%1,%2,%3};"
        : "+f"(d[0]), "+f"(d[1]), "+f"(d[2]), "+f"(d[3])
        : "r"(a[0]), "r"(a[1]), "r"(a[2]), "r"(a[3]), "r"(b[0]), "r"(b[1]));
}
__device__ __forceinline__ void cp_async16(uint32_t saddr, const void* g) {
    asm volatile("cp.async.cg.shared.global [%0], [%1], 16;"
                 :: "r"(saddr), "l"(g));
}
#define CP_COMMIT() asm volatile("cp.async.commit_group;" ::: "memory")
#define CP_WAIT0()  asm volatile("cp.async.wait_group 0;" ::: "memory")

__device__ __forceinline__ uint32_t packh(float a, float b) {
    __half2 h = __floats2half2_rn(a, b);
    return *reinterpret_cast<uint32_t*>(&h);
}
__device__ __forceinline__ float h_round(float v) {
    return __half2float(__float2half_rn(v));
}
__device__ __forceinline__ void splith2(float v0, float v1,
                                        uint32_t& hi, uint32_t& lo) {
    hi = packh(v0, v1);
    lo = packh(v0 - h_round(v0), v1 - h_round(v1));
}

// ---------------------------------------------------------------------------
// Conversion kernels
// ---------------------------------------------------------------------------
__global__ __launch_bounds__(256)
void convert_f16_kernel(const float4* __restrict__ src,
                        uint2* __restrict__ dst, int n4) {
    int i = blockIdx.x * blockDim.x + threadIdx.x;
    if (i >= n4) return;
    float4 v = src[i];
    dst[i] = make_uint2(packh(v.x, v.y), packh(v.z, v.w));
}
__global__ __launch_bounds__(256)
void convert_split_f16_kernel(const float4* __restrict__ src,
                              uint2* __restrict__ hi, uint2* __restrict__ lo,
                              int n4) {
    int i = blockIdx.x * blockDim.x + threadIdx.x;
    if (i >= n4) return;
    float4 v = src[i];
    uint32_t h01, l01, h23, l23;
    splith2(v.x, v.y, h01, l01);
    splith2(v.z, v.w, h23, l23);
    hi[i] = make_uint2(h01, h23);
    lo[i] = make_uint2(l01, l23);
}

// ---------------------------------------------------------------------------
// fp16 NT GEMM (CTA 128x128, BK=32). SPLIT_W: W as hi+lo (2 MMAs/k16) or
// plain (1 MMA). Epilogues: fp32 C (+bias) | fp16 plain [b,h,s,dk] (QKV)
// ---------------------------------------------------------------------------
#define ROWB 80
#define MATB (128 * ROWB)
#define GEMM_SMEM_SPLIT (2 * 3 * MATB)   // 61440 B
#define GEMM_SMEM_PLAIN (2 * 2 * MATB)   // 40960 B
#define NCHUNK (Dsz / 32)

template <bool SPLIT_W>
__device__ __forceinline__ void gemm_mma(const unsigned short* __restrict__ Ah,
                                         const unsigned short* __restrict__ Whi,
                                         const unsigned short* __restrict__ Wlo,
                                         float* __restrict__ C,
                                         const float* __restrict__ bias,
                                         unsigned short* __restrict__ Dhi) {
    extern __shared__ char smem[];
    const uint32_t sbase = smem_to_u32(smem);
    const int tid = threadIdx.x;
    const int wid = tid >> 5;
    const int lane = tid & 31;
    const int wm = wid & 3;
    const int wn = wid >> 2;
    const int bm = blockIdx.y * 128;
    const int bn = blockIdx.x * 128;
    constexpr int NMAT = SPLIT_W ? 3 : 2;

    const int s0 = tid, s1 = tid + 256;
    const int r0g = s0 >> 2, c0g = (s0 & 3) * 8;
    const int r1g = s1 >> 2, c1g = (s1 & 3) * 8;

    const unsigned short* gp[3] = {Ah, Whi, Wlo};
    const long long rowbase[3] = {
        (long long)(bm + r0g) * Dsz,
        (long long)(bn + r0g) * Dsz, (long long)(bn + r0g) * Dsz};
    const long long rowbase1[3] = {
        (long long)(bm + r1g) * Dsz,
        (long long)(bn + r1g) * Dsz, (long long)(bn + r1g) * Dsz};

    float acc[2][8][4] = {};

    auto load_chunk = [&](int c, int buf) {
        const int k0 = c * 32;
        const uint32_t b = sbase + buf * NMAT * MATB;
#pragma unroll
        for (int m = 0; m < NMAT; m++) {
            cp_async16(b + m * MATB + r0g * ROWB + (s0 & 3) * 16,
                       gp[m] + rowbase[m] + k0 + c0g);
            cp_async16(b + m * MATB + r1g * ROWB + (s1 & 3) * 16,
                       gp[m] + rowbase1[m] + k0 + c1g);
        }
        CP_COMMIT();
    };

    const int mtx = lane >> 3;
    const int r8 = lane & 7;
    const int a_rowoff = (mtx & 1) * 8 + r8;
    const int a_segoff = (mtx >> 1);
    const int b_rowoff = (mtx >> 1) * 8 + r8;
    const int b_segoff = (mtx & 1);

    auto compute = [&](int buf) {
        const uint32_t ahb = sbase + buf * NMAT * MATB;
        const uint32_t bhb = ahb + MATB;
        const uint32_t blb = ahb + 2 * MATB;
#pragma unroll
        for (int ks = 0; ks < 2; ks++) {
            uint32_t ah[2][4];
#pragma unroll
            for (int mt = 0; mt < 2; mt++) {
                uint32_t ao = (uint32_t)(wm * 32 + mt * 16 + a_rowoff) * ROWB +
                              (uint32_t)(ks * 2 + a_segoff) * 16;
                ldsm4(ah[mt], ahb + ao);
            }
#pragma unroll
            for (int np = 0; np < 4; np++) {
                uint32_t bo = (uint32_t)(wn * 64 + np * 16 + b_rowoff) * ROWB +
                              (uint32_t)(ks * 2 + b_segoff) * 16;
                uint32_t bh[4], bl[4];
                ldsm4(bh, bhb + bo);
                if (SPLIT_W) ldsm4(bl, blb + bo);
#pragma unroll
                for (int half = 0; half < 2; half++) {
                    const int nt = np * 2 + half;
#pragma unroll
                    for (int mt = 0; mt < 2; mt++) {
                        mma16816h(acc[mt][nt], ah[mt], &bh[half * 2]);
                        if (SPLIT_W)
                            mma16816h(acc[mt][nt], ah[mt], &bl[half * 2]);
                    }
                }
            }
        }
    };

    load_chunk(0, 0);
    for (int c = 0; c < NCHUNK; c++) {
        CP_WAIT0();
        __syncthreads();
        if (c + 1 < NCHUNK) load_chunk(c + 1, (c + 1) & 1);
        compute(c & 1);
    }

    const int g = lane >> 2, t = lane & 3;
    if (Dhi) {
        // plain fp16 epilogue in [b,h,s,dk] layout
#pragma unroll
        for (int mt = 0; mt < 2; mt++) {
#pragma unroll
            for (int nt = 0; nt < 8; nt++) {
                const int col = bn + wn * 64 + nt * 8 + t * 2;
                const int hd = col >> 6, d = col & 63;
#pragma unroll
                for (int hh = 0; hh < 2; hh++) {
                    const int row = bm + wm * 32 + mt * 16 + hh * 8 + g;
                    const int b = row >> 11, s = row & 2047;
                    const long long idx =
                        ((long long)(b * Hh + hd) * Ssz + s) * DKk + d;
                    *(uint32_t*)(Dhi + idx) =
                        packh(acc[mt][nt][hh * 2 + 0], acc[mt][nt][hh * 2 + 1]);
                }
            }
        }
    } else {
#pragma unroll
        for (int mt = 0; mt < 2; mt++) {
#pragma unroll
            for (int nt = 0; nt < 8; nt++) {
                const int col = bn + wn * 64 + nt * 8 + t * 2;
                const int row0 = bm + wm * 32 + mt * 16 + g;
                float2 v0 = make_float2(acc[mt][nt][0], acc[mt][nt][1]);
                float2 v1 = make_float2(acc[mt][nt][2], acc[mt][nt][3]);
                if (bias) {
                    float2 bb = *(const float2*)(bias + col);
                    v0.x += bb.x; v0.y += bb.y;
                    v1.x += bb.x; v1.y += bb.y;
                }
                *(float2*)(C + (long long)row0 * Dsz + col) = v0;
                *(float2*)(C + (long long)(row0 + 8) * Dsz + col) = v1;
            }
        }
    }
}

__global__ __launch_bounds__(256, 2)
void qkv_mma_kernel() {
    const unsigned short* Whi = g_whi + (long long)blockIdx.z * Dsz * Dsz;
    const unsigned short* Wlo = g_wlo + (long long)blockIdx.z * Dsz * Dsz;
    unsigned short* Dhi = (blockIdx.z == 0) ? g_Qh : (blockIdx.z == 1) ? g_Kh : g_Vh;
    gemm_mma<true>(g_xh, Whi, Wlo, nullptr, nullptr, Dhi);
}

__global__ __launch_bounds__(256, 2)
void out_mma_kernel(const float* __restrict__ bo, float* __restrict__ out) {
    const unsigned short* Whi = g_whi + 3ll * Dsz * Dsz;
    gemm_mma<false>(g_ch, Whi, nullptr, out, bo, nullptr);
}

// ---------------------------------------------------------------------------
// Tensor-core flash attention, causal — plain fp16 K and V (1 MMA each per
// k16 in S and PV). CTA: 128 queries; 8 warps 4m x 2n.
// ---------------------------------------------------------------------------
#define AP 144
#define AMAT (128 * AP)
#define SM_Q 0                        // Q fp16: 1 matrix
#define SM_KV AMAT                    // 2 buffers x 2 matrices (K, V)
#define KVBUF (2 * AMAT)
#define SM_STATM (SM_KV + 2 * KVBUF)  // 92160: float [2][128]
#define SM_STATS (SM_STATM + 1024)
#define ATT_SMEM (SM_STATS + 1024)    // 94208 B

__global__ __launch_bounds__(256)
void attn_mma_kernel() {
    extern __shared__ char smem[];
    const uint32_t sb = smem_to_u32(smem);
    const int tid = threadIdx.x;
    const int wid = tid >> 5;
    const int lane = tid & 31;
    const int wm = wid & 3;
    const int wn = wid >> 2;
    const int g = lane >> 2, t = lane & 3;
    const int mtx = lane >> 3, r8 = lane & 7;
    const int a_rowoff = (mtx & 1) * 8 + r8;
    const int a_segoff = (mtx >> 1);
    const int b_rowoff = (mtx >> 1) * 8 + r8;
    const int b_segoff = (mtx & 1);

    const int qb = (Ssz / 128 - 1) - blockIdx.x;
    const int q0 = qb * 128;
    const int bh = blockIdx.y;
    const int b = bh >> 4, h = bh & 15;
    const long long base = (long long)bh * Ssz * DKk;

    // Load Q (plain fp16) into smem
    for (int i = tid; i < 1024; i += 256) {
        int r = i >> 3, c = i & 7;
        *(uint4*)(smem + SM_Q + r * AP + c * 16) =
            *(const uint4*)(g_Qh + base + (long long)(q0 + r) * DKk + c * 8);
    }

    auto kv_load = [&](int kt, int buf) {
        const long long rb = base + (long long)kt * 128 * DKk;
        const unsigned short* srcs[2] = {g_Kh, g_Vh};
#pragma unroll
        for (int m = 0; m < 2; m++) {
            for (int i = tid; i < 1024; i += 256) {
                int r = i >> 3, c = i & 7;
                cp_async16(sb + SM_KV + buf * KVBUF + m * AMAT + r * AP + c * 16,
                           srcs[m] + rb + r * DKk + c * 8);
            }
        }
        CP_COMMIT();
    };
    kv_load(0, 0);

    float oacc[2][8][4] = {};
    float mrow[4], lrow[4];
#pragma unroll
    for (int r = 0; r < 4; r++) { mrow[r] = -1e30f; lrow[r] = 0.0f; }

    float* statm = (float*)(smem + SM_STATM);
    float* stats = (float*)(smem + SM_STATS);

    const int nkt = qb + 1;
    for (int kt = 0; kt < nkt; kt++) {
        CP_WAIT0();
        __syncthreads();
        if (kt + 1 < nkt) kv_load(kt + 1, (kt + 1) & 1);

        const uint32_t kb = sb + SM_KV + (kt & 1) * KVBUF;   // K
        const uint32_t qh_b = sb + SM_Q;

        // ---- S = Q K^T, plain fp16 ----
        float sacc[2][8][4] = {};
#pragma unroll
        for (int ks = 0; ks < 4; ks++) {
            uint32_t ah[2][4];
#pragma unroll
            for (int mt = 0; mt < 2; mt++) {
                uint32_t ao = (uint32_t)(wm * 32 + mt * 16 + a_rowoff) * AP +
                              (uint32_t)(ks * 2 + a_segoff) * 16;
                ldsm4(ah[mt], qh_b + ao);
            }
#pragma unroll
            for (int np = 0; np < 4; np++) {
                uint32_t bo = (uint32_t)(wn * 64 + np * 16 + b_rowoff) * AP +
                              (uint32_t)(ks * 2 + b_segoff) * 16;
                uint32_t kh[4];
                ldsm4(kh, kb + bo);
#pragma unroll
                for (int half = 0; half < 2; half++) {
                    const int nt = np * 2 + half;
#pragma unroll
                    for (int mt = 0; mt < 2; mt++)
                        mma16816h(sacc[mt][nt], ah[mt], &kh[half * 2]);
                }
            }
        }

        // ---- scale + causal mask ----
        const bool diag = (kt == qb);
#pragma unroll
        for (int mt = 0; mt < 2; mt++)
#pragma unroll
            for (int nt = 0; nt < 8; nt++)
#pragma unroll
                for (int c = 0; c < 4; c++) {
                    float v = sacc[mt][nt][c] * 0.125f;
                    if (diag) {
                        int kidx = wn * 64 + nt * 8 + t * 2 + (c & 1);
                        int qidx = wm * 32 + mt * 16 + (c >> 1) * 8 + g;
                        if (kidx > qidx) v = -1e30f;
                    }
                    sacc[mt][nt][c] = v;
                }

        // ---- online softmax (cross-warp over wn pair) ----
        float pm[4];
#pragma unroll
        for (int r = 0; r < 4; r++) pm[r] = -1e30f;
#pragma unroll
        for (int mt = 0; mt < 2; mt++)
#pragma unroll
            for (int nt = 0; nt < 8; nt++) {
                pm[mt * 2 + 0] = fmaxf(pm[mt * 2 + 0],
                                       fmaxf(sacc[mt][nt][0], sacc[mt][nt][1]));
                pm[mt * 2 + 1] = fmaxf(pm[mt * 2 + 1],
                                       fmaxf(sacc[mt][nt][2], sacc[mt][nt][3]));
            }
#pragma unroll
        for (int r = 0; r < 4; r++) {
            pm[r] = fmaxf(pm[r], __shfl_xor_sync(0xffffffffu, pm[r], 1));
            pm[r] = fmaxf(pm[r], __shfl_xor_sync(0xffffffffu, pm[r], 2));
        }
        if (t == 0) {
#pragma unroll
            for (int r = 0; r < 4; r++) {
                int rowid = wm * 32 + (r >> 1) * 16 + (r & 1) * 8 + g;
                statm[wn * 128 + rowid] = pm[r];
            }
        }
        __syncthreads();
        float alpha[4];
#pragma unroll
        for (int r = 0; r < 4; r++) {
            int rowid = wm * 32 + (r >> 1) * 16 + (r & 1) * 8 + g;
            float rm = fmaxf(pm[r], statm[(wn ^ 1) * 128 + rowid]);
            float mn = fmaxf(mrow[r], rm);
            alpha[r] = __expf(mrow[r] - mn);
            mrow[r] = mn;
        }
        float psum[4] = {0.f, 0.f, 0.f, 0.f};
#pragma unroll
        for (int mt = 0; mt < 2; mt++)
#pragma unroll
            for (int nt = 0; nt < 8; nt++)
#pragma unroll
                for (int c = 0; c < 4; c++) {
                    int r = mt * 2 + (c >> 1);
                    float p = __expf(sacc[mt][nt][c] - mrow[r]);
                    sacc[mt][nt][c] = p;
                    psum[r] += p;
                }
#pragma unroll
        for (int r = 0; r < 4; r++) {
            psum[r] += __shfl_xor_sync(0xffffffffu, psum[r], 1);
            psum[r] += __shfl_xor_sync(0xffffffffu, psum[r], 2);
        }
        if (t == 0) {
#pragma unroll
            for (int r = 0; r < 4; r++) {
                int rowid = wm * 32 + (r >> 1) * 16 + (r & 1) * 8 + g;
                stats[wn * 128 + rowid] = psum[r];
            }
        }
        __syncthreads();
#pragma unroll
        for (int r = 0; r < 4; r++) {
            int rowid = wm * 32 + (r >> 1) * 16 + (r & 1) * 8 + g;
            float tot = psum[r] + stats[(wn ^ 1) * 128 + rowid];
            lrow[r] = lrow[r] * alpha[r] + tot;
        }
#pragma unroll
        for (int mt = 0; mt < 2; mt++)
#pragma unroll
            for (int nt = 0; nt < 8; nt++)
#pragma unroll
                for (int c = 0; c < 4; c++)
                    oacc[mt][nt][c] *= alpha[mt * 2 + (c >> 1)];

        // ---- O += P V, plain fp16, full d range ----
        const uint32_t vh_b = kb + AMAT;
#pragma unroll
        for (int ks = 0; ks < 4; ks++) {
            uint32_t ph[2][4];
#pragma unroll
            for (int mt = 0; mt < 2; mt++) {
                const float* s0 = sacc[mt][2 * ks];
                const float* s1 = sacc[mt][2 * ks + 1];
                ph[mt][0] = packh(s0[0], s0[1]);
                ph[mt][1] = packh(s0[2], s0[3]);
                ph[mt][2] = packh(s1[0], s1[1]);
                ph[mt][3] = packh(s1[2], s1[3]);
            }
#pragma unroll
            for (int dp = 0; dp < 4; dp++) {
                uint32_t vo = (uint32_t)(wn * 64 + ks * 16 + (mtx & 1) * 8 + r8) * AP +
                              (uint32_t)(dp * 16 + (mtx >> 1) * 8) * 2;
                uint32_t vh[4];
                ldsm4t(vh, vh_b + vo);
#pragma unroll
                for (int half = 0; half < 2; half++) {
                    const int nt = dp * 2 + half;
#pragma unroll
                    for (int mt = 0; mt < 2; mt++)
                        mma16816h(oacc[mt][nt], ph[mt], &vh[half * 2]);
                }
            }
        }
    }

    // ---- epilogue: sum partial O across wn pair, normalize, write fp16 ctx
    __syncthreads();
    float* Oex = (float*)smem;   // [128][64] = 32 KB
    if (wn == 1) {
#pragma unroll
        for (int mt = 0; mt < 2; mt++)
#pragma unroll
            for (int nt = 0; nt < 8; nt++)
#pragma unroll
                for (int c = 0; c < 4; c++) {
                    int row = wm * 32 + mt * 16 + (c >> 1) * 8 + g;
                    int col = nt * 8 + t * 2 + (c & 1);
                    Oex[row * 64 + col] = oacc[mt][nt][c];
                }
    }
    __syncthreads();
    if (wn == 0) {
        float inv[4];
#pragma unroll
        for (int r = 0; r < 4; r++) inv[r] = 1.0f / lrow[r];
#pragma unroll
        for (int mt = 0; mt < 2; mt++)
#pragma unroll
            for (int nt = 0; nt < 8; nt++)
#pragma unroll
                for (int hh = 0; hh < 2; hh++) {
                    int row = wm * 32 + mt * 16 + hh * 8 + g;
                    int col = nt * 8 + t * 2;
                    float v0 = (oacc[mt][nt][hh * 2 + 0] + Oex[row * 64 + col]) *
                               inv[mt * 2 + hh];
                    float v1 = (oacc[mt][nt][hh * 2 + 1] + Oex[row * 64 + col + 1]) *
                               inv[mt * 2 + hh];
                    long long dst = ((long long)(b * Ssz + q0 + row)) * Dsz +
                                    h * DKk + col;
                    *(uint32_t*)(g_ch + dst) = packh(v0, v1);
                }
    }
}

// ---------------------------------------------------------------------------
extern "C" void kernel_launch(void* const* d_in, const int* in_sizes, int n_in,
                              void* d_out, int out_size) {
    const float* x  = (const float*)d_in[0];
    const float* wq = (const float*)d_in[1];
    const float* wk = (const float*)d_in[2];
    const float* wv = (const float*)d_in[3];
    const float* wo = (const float*)d_in[4];
    const float* bo = (const float*)d_in[5];
    float* out = (float*)d_out;

    cudaFuncSetAttribute(qkv_mma_kernel,
                         cudaFuncAttributeMaxDynamicSharedMemorySize, GEMM_SMEM_SPLIT);
    cudaFuncSetAttribute(out_mma_kernel,
                         cudaFuncAttributeMaxDynamicSharedMemorySize, GEMM_SMEM_PLAIN);
    cudaFuncSetAttribute(attn_mma_kernel,
                         cudaFuncAttributeMaxDynamicSharedMemorySize, ATT_SMEM);

    unsigned short *xh, *whi, *wlo;
    cudaGetSymbolAddress((void**)&xh, g_xh);
    cudaGetSymbolAddress((void**)&whi, g_whi);
    cudaGetSymbolAddress((void**)&wlo, g_wlo);

    const int n4x = Mrows * Dsz / 4;
    const int n4w = Dsz * Dsz / 4;

    convert_f16_kernel<<<(n4x + 255) / 256, 256>>>(
        (const float4*)x, (uint2*)xh, n4x);
    convert_split_f16_kernel<<<(n4w + 255) / 256, 256>>>(
        (const float4*)wq, (uint2*)(whi + 0ll * Dsz * Dsz), (uint2*)(wlo + 0ll * Dsz * Dsz), n4w);
    convert_split_f16_kernel<<<(n4w + 255) / 256, 256>>>(
        (const float4*)wk, (uint2*)(whi + 1ll * Dsz * Dsz), (uint2*)(wlo + 1ll * Dsz * Dsz), n4w);
    convert_split_f16_kernel<<<(n4w + 255) / 256, 256>>>(
        (const float4*)wv, (uint2*)(whi + 2ll * Dsz * Dsz), (uint2*)(wlo + 2ll * Dsz * Dsz), n4w);
    convert_f16_kernel<<<(n4w + 255) / 256, 256>>>(
        (const float4*)wo, (uint2*)(whi + 3ll * Dsz * Dsz), n4w);

    dim3 g1(Dsz / 128, Mrows / 128, 3);
    qkv_mma_kernel<<<g1, 256, GEMM_SMEM_SPLIT>>>();

    dim3 g2(Ssz / 128, Bsz * Hh);
    attn_mma_kernel<<<g2, 256, ATT_SMEM>>>();

    dim3 g3(Dsz / 128, Mrows / 128);
    out_mma_kernel<<<g3, 256, GEMM_SMEM_PLAIN>>>(bo, out);
}

// round 14
// speedup vs baseline: 7.0122x; 1.2816x over previous
#include <cuda_runtime.h>
#include <cuda_fp16.h>
#include <math.h>
#include <cstdint>

// Problem constants
#define Bsz 4
#define Ssz 2048
#define Dsz 1024
#define Hh  16
#define DKk 64
#define Mrows (Bsz * Ssz)   // 8192

// ---------------------------------------------------------------------------
// Scratch (device globals) — everything plain fp16 now
// g_xh : x    g_wh : wq,wk,wv,wo    g_ch : ctx    g_Q/K/Vh : [b,h,s,dk]
// ---------------------------------------------------------------------------
__device__ unsigned short g_xh[(long long)Mrows * Dsz];
__device__ unsigned short g_ch[(long long)Mrows * Dsz];
__device__ unsigned short g_wh[4ll * Dsz * Dsz];
__device__ unsigned short g_Qh[(long long)Mrows * Dsz];
__device__ unsigned short g_Kh[(long long)Mrows * Dsz];
__device__ unsigned short g_Vh[(long long)Mrows * Dsz];

// ---------------------------------------------------------------------------
// PTX helpers (portable ISA: ldmatrix / mma.sync / cp.async, sm_80+)
// ---------------------------------------------------------------------------
__device__ __forceinline__ uint32_t smem_to_u32(const void* p) {
    uint32_t a;
    asm("{ .reg .u64 t; cvta.to.shared.u64 t, %1; cvt.u32.u64 %0, t; }"
        : "=r"(a) : "l"(p));
    return a;
}
__device__ __forceinline__ void ldsm4(uint32_t* r, uint32_t addr) {
    asm volatile("ldmatrix.sync.aligned.m8n8.x4.shared.b16 {%0,%1,%2,%3}, [%4];"
                 : "=r"(r[0]), "=r"(r[1]), "=r"(r[2]), "=r"(r[3]) : "r"(addr));
}
__device__ __forceinline__ void ldsm4t(uint32_t* r, uint32_t addr) {
    asm volatile("ldmatrix.sync.aligned.m8n8.x4.trans.shared.b16 {%0,%1,%2,%3}, [%4];"
                 : "=r"(r[0]), "=r"(r[1]), "=r"(r[2]), "=r"(r[3]) : "r"(addr));
}
__device__ __forceinline__ void mma16816h(float* d, const uint32_t* a,
                                          const uint32_t* b) {
    asm volatile(
        "mma.sync.aligned.m16n8k16.row.col.f32.f16.f16.f32 "
        "{%0,%1,%2,%3}, {%4,%5,%6,%7}, {%8,%9}, {%0,%1,%2,%3};"
        : "+f"(d[0]), "+f"(d[1]), "+f"(d[2]), "+f"(d[3])
        : "r"(a[0]), "r"(a[1]), "r"(a[2]), "r"(a[3]), "r"(b[0]), "r"(b[1]));
}
__device__ __forceinline__ void cp_async16(uint32_t saddr, const void* g) {
    asm volatile("cp.async.cg.shared.global [%0], [%1], 16;"
                 :: "r"(saddr), "l"(g));
}
#define CP_COMMIT() asm volatile("cp.async.commit_group;" ::: "memory")
#define CP_WAIT0()  asm volatile("cp.async.wait_group 0;" ::: "memory")

__device__ __forceinline__ uint32_t packh(float a, float b) {
    __half2 h = __floats2half2_rn(a, b);
    return *reinterpret_cast<uint32_t*>(&h);
}

// ---------------------------------------------------------------------------
// Conversion kernel (fp32 -> plain fp16)
// ---------------------------------------------------------------------------
__global__ __launch_bounds__(256)
void convert_f16_kernel(const float4* __restrict__ src,
                        uint2* __restrict__ dst, int n4) {
    int i = blockIdx.x * blockDim.x + threadIdx.x;
    if (i >= n4) return;
    float4 v = src[i];
    dst[i] = make_uint2(packh(v.x, v.y), packh(v.z, v.w));
}

// ---------------------------------------------------------------------------
// Plain fp16 NT GEMM (CTA 128x128, BK=32, 1 MMA per microtile per k16).
// Epilogues: fp32 C (+bias) | fp16 plain [b,h,s,dk] (QKV)
// ---------------------------------------------------------------------------
#define ROWB 80
#define MATB (128 * ROWB)
#define GEMM_SMEM (2 * 2 * MATB)   // 40960 B
#define NCHUNK (Dsz / 32)

__device__ __forceinline__ void gemm_mma(const unsigned short* __restrict__ Ah,
                                         const unsigned short* __restrict__ Wh,
                                         float* __restrict__ C,
                                         const float* __restrict__ bias,
                                         unsigned short* __restrict__ Dhi) {
    extern __shared__ char smem[];
    const uint32_t sbase = smem_to_u32(smem);
    const int tid = threadIdx.x;
    const int wid = tid >> 5;
    const int lane = tid & 31;
    const int wm = wid & 3;
    const int wn = wid >> 2;
    const int bm = blockIdx.y * 128;
    const int bn = blockIdx.x * 128;

    const int s0 = tid, s1 = tid + 256;
    const int r0g = s0 >> 2, c0g = (s0 & 3) * 8;
    const int r1g = s1 >> 2, c1g = (s1 & 3) * 8;

    const unsigned short* gp[2] = {Ah, Wh};
    const long long rowbase[2] = {
        (long long)(bm + r0g) * Dsz, (long long)(bn + r0g) * Dsz};
    const long long rowbase1[2] = {
        (long long)(bm + r1g) * Dsz, (long long)(bn + r1g) * Dsz};

    float acc[2][8][4] = {};

    auto load_chunk = [&](int c, int buf) {
        const int k0 = c * 32;
        const uint32_t b = sbase + buf * 2 * MATB;
#pragma unroll
        for (int m = 0; m < 2; m++) {
            cp_async16(b + m * MATB + r0g * ROWB + (s0 & 3) * 16,
                       gp[m] + rowbase[m] + k0 + c0g);
            cp_async16(b + m * MATB + r1g * ROWB + (s1 & 3) * 16,
                       gp[m] + rowbase1[m] + k0 + c1g);
        }
        CP_COMMIT();
    };

    const int mtx = lane >> 3;
    const int r8 = lane & 7;
    const int a_rowoff = (mtx & 1) * 8 + r8;
    const int a_segoff = (mtx >> 1);
    const int b_rowoff = (mtx >> 1) * 8 + r8;
    const int b_segoff = (mtx & 1);

    auto compute = [&](int buf) {
        const uint32_t ahb = sbase + buf * 2 * MATB;
        const uint32_t bhb = ahb + MATB;
#pragma unroll
        for (int ks = 0; ks < 2; ks++) {
            uint32_t ah[2][4];
#pragma unroll
            for (int mt = 0; mt < 2; mt++) {
                uint32_t ao = (uint32_t)(wm * 32 + mt * 16 + a_rowoff) * ROWB +
                              (uint32_t)(ks * 2 + a_segoff) * 16;
                ldsm4(ah[mt], ahb + ao);
            }
#pragma unroll
            for (int np = 0; np < 4; np++) {
                uint32_t bo = (uint32_t)(wn * 64 + np * 16 + b_rowoff) * ROWB +
                              (uint32_t)(ks * 2 + b_segoff) * 16;
                uint32_t bh[4];
                ldsm4(bh, bhb + bo);
#pragma unroll
                for (int half = 0; half < 2; half++) {
                    const int nt = np * 2 + half;
#pragma unroll
                    for (int mt = 0; mt < 2; mt++)
                        mma16816h(acc[mt][nt], ah[mt], &bh[half * 2]);
                }
            }
        }
    };

    load_chunk(0, 0);
    for (int c = 0; c < NCHUNK; c++) {
        CP_WAIT0();
        __syncthreads();
        if (c + 1 < NCHUNK) load_chunk(c + 1, (c + 1) & 1);
        compute(c & 1);
    }

    const int g = lane >> 2, t = lane & 3;
    if (Dhi) {
        // plain fp16 epilogue in [b,h,s,dk] layout
#pragma unroll
        for (int mt = 0; mt < 2; mt++) {
#pragma unroll
            for (int nt = 0; nt < 8; nt++) {
                const int col = bn + wn * 64 + nt * 8 + t * 2;
                const int hd = col >> 6, d = col & 63;
#pragma unroll
                for (int hh = 0; hh < 2; hh++) {
                    const int row = bm + wm * 32 + mt * 16 + hh * 8 + g;
                    const int b = row >> 11, s = row & 2047;
                    const long long idx =
                        ((long long)(b * Hh + hd) * Ssz + s) * DKk + d;
                    *(uint32_t*)(Dhi + idx) =
                        packh(acc[mt][nt][hh * 2 + 0], acc[mt][nt][hh * 2 + 1]);
                }
            }
        }
    } else {
#pragma unroll
        for (int mt = 0; mt < 2; mt++) {
#pragma unroll
            for (int nt = 0; nt < 8; nt++) {
                const int col = bn + wn * 64 + nt * 8 + t * 2;
                const int row0 = bm + wm * 32 + mt * 16 + g;
                float2 v0 = make_float2(acc[mt][nt][0], acc[mt][nt][1]);
                float2 v1 = make_float2(acc[mt][nt][2], acc[mt][nt][3]);
                if (bias) {
                    float2 bb = *(const float2*)(bias + col);
                    v0.x += bb.x; v0.y += bb.y;
                    v1.x += bb.x; v1.y += bb.y;
                }
                *(float2*)(C + (long long)row0 * Dsz + col) = v0;
                *(float2*)(C + (long long)(row0 + 8) * Dsz + col) = v1;
            }
        }
    }
}

__global__ __launch_bounds__(256, 2)
void qkv_mma_kernel() {
    const unsigned short* Wh = g_wh + (long long)blockIdx.z * Dsz * Dsz;
    unsigned short* Dhi = (blockIdx.z == 0) ? g_Qh : (blockIdx.z == 1) ? g_Kh : g_Vh;
    gemm_mma(g_xh, Wh, nullptr, nullptr, Dhi);
}

__global__ __launch_bounds__(256, 2)
void out_mma_kernel(const float* __restrict__ bo, float* __restrict__ out) {
    const unsigned short* Wh = g_wh + 3ll * Dsz * Dsz;
    gemm_mma(g_ch, Wh, out, bo, nullptr);
}

// ---------------------------------------------------------------------------
// Tensor-core flash attention, causal — plain fp16 throughout (unchanged
// from Round 13). CTA: 128 queries; 8 warps 4m x 2n.
// ---------------------------------------------------------------------------
#define AP 144
#define AMAT (128 * AP)
#define SM_Q 0
#define SM_KV AMAT
#define KVBUF (2 * AMAT)
#define SM_STATM (SM_KV + 2 * KVBUF)
#define SM_STATS (SM_STATM + 1024)
#define ATT_SMEM (SM_STATS + 1024)    // 94208 B

__global__ __launch_bounds__(256)
void attn_mma_kernel() {
    extern __shared__ char smem[];
    const uint32_t sb = smem_to_u32(smem);
    const int tid = threadIdx.x;
    const int wid = tid >> 5;
    const int lane = tid & 31;
    const int wm = wid & 3;
    const int wn = wid >> 2;
    const int g = lane >> 2, t = lane & 3;
    const int mtx = lane >> 3, r8 = lane & 7;
    const int a_rowoff = (mtx & 1) * 8 + r8;
    const int a_segoff = (mtx >> 1);
    const int b_rowoff = (mtx >> 1) * 8 + r8;
    const int b_segoff = (mtx & 1);

    const int qb = (Ssz / 128 - 1) - blockIdx.x;
    const int q0 = qb * 128;
    const int bh = blockIdx.y;
    const int b = bh >> 4, h = bh & 15;
    const long long base = (long long)bh * Ssz * DKk;

    for (int i = tid; i < 1024; i += 256) {
        int r = i >> 3, c = i & 7;
        *(uint4*)(smem + SM_Q + r * AP + c * 16) =
            *(const uint4*)(g_Qh + base + (long long)(q0 + r) * DKk + c * 8);
    }

    auto kv_load = [&](int kt, int buf) {
        const long long rb = base + (long long)kt * 128 * DKk;
        const unsigned short* srcs[2] = {g_Kh, g_Vh};
#pragma unroll
        for (int m = 0; m < 2; m++) {
            for (int i = tid; i < 1024; i += 256) {
                int r = i >> 3, c = i & 7;
                cp_async16(sb + SM_KV + buf * KVBUF + m * AMAT + r * AP + c * 16,
                           srcs[m] + rb + r * DKk + c * 8);
            }
        }
        CP_COMMIT();
    };
    kv_load(0, 0);

    float oacc[2][8][4] = {};
    float mrow[4], lrow[4];
#pragma unroll
    for (int r = 0; r < 4; r++) { mrow[r] = -1e30f; lrow[r] = 0.0f; }

    float* statm = (float*)(smem + SM_STATM);
    float* stats = (float*)(smem + SM_STATS);

    const int nkt = qb + 1;
    for (int kt = 0; kt < nkt; kt++) {
        CP_WAIT0();
        __syncthreads();
        if (kt + 1 < nkt) kv_load(kt + 1, (kt + 1) & 1);

        const uint32_t kb = sb + SM_KV + (kt & 1) * KVBUF;
        const uint32_t qh_b = sb + SM_Q;

        // ---- S = Q K^T ----
        float sacc[2][8][4] = {};
#pragma unroll
        for (int ks = 0; ks < 4; ks++) {
            uint32_t ah[2][4];
#pragma unroll
            for (int mt = 0; mt < 2; mt++) {
                uint32_t ao = (uint32_t)(wm * 32 + mt * 16 + a_rowoff) * AP +
                              (uint32_t)(ks * 2 + a_segoff) * 16;
                ldsm4(ah[mt], qh_b + ao);
            }
#pragma unroll
            for (int np = 0; np < 4; np++) {
                uint32_t bo = (uint32_t)(wn * 64 + np * 16 + b_rowoff) * AP +
                              (uint32_t)(ks * 2 + b_segoff) * 16;
                uint32_t kh[4];
                ldsm4(kh, kb + bo);
#pragma unroll
                for (int half = 0; half < 2; half++) {
                    const int nt = np * 2 + half;
#pragma unroll
                    for (int mt = 0; mt < 2; mt++)
                        mma16816h(sacc[mt][nt], ah[mt], &kh[half * 2]);
                }
            }
        }

        // ---- scale + causal mask ----
        const bool diag = (kt == qb);
#pragma unroll
        for (int mt = 0; mt < 2; mt++)
#pragma unroll
            for (int nt = 0; nt < 8; nt++)
#pragma unroll
                for (int c = 0; c < 4; c++) {
                    float v = sacc[mt][nt][c] * 0.125f;
                    if (diag) {
                        int kidx = wn * 64 + nt * 8 + t * 2 + (c & 1);
                        int qidx = wm * 32 + mt * 16 + (c >> 1) * 8 + g;
                        if (kidx > qidx) v = -1e30f;
                    }
                    sacc[mt][nt][c] = v;
                }

        // ---- online softmax (cross-warp over wn pair) ----
        float pm[4];
#pragma unroll
        for (int r = 0; r < 4; r++) pm[r] = -1e30f;
#pragma unroll
        for (int mt = 0; mt < 2; mt++)
#pragma unroll
            for (int nt = 0; nt < 8; nt++) {
                pm[mt * 2 + 0] = fmaxf(pm[mt * 2 + 0],
                                       fmaxf(sacc[mt][nt][0], sacc[mt][nt][1]));
                pm[mt * 2 + 1] = fmaxf(pm[mt * 2 + 1],
                                       fmaxf(sacc[mt][nt][2], sacc[mt][nt][3]));
            }
#pragma unroll
        for (int r = 0; r < 4; r++) {
            pm[r] = fmaxf(pm[r], __shfl_xor_sync(0xffffffffu, pm[r], 1));
            pm[r] = fmaxf(pm[r], __shfl_xor_sync(0xffffffffu, pm[r], 2));
        }
        if (t == 0) {
#pragma unroll
            for (int r = 0; r < 4; r++) {
                int rowid = wm * 32 + (r >> 1) * 16 + (r & 1) * 8 + g;
                statm[wn * 128 + rowid] = pm[r];
            }
        }
        __syncthreads();
        float alpha[4];
#pragma unroll
        for (int r = 0; r < 4; r++) {
            int rowid = wm * 32 + (r >> 1) * 16 + (r & 1) * 8 + g;
            float rm = fmaxf(pm[r], statm[(wn ^ 1) * 128 + rowid]);
            float mn = fmaxf(mrow[r], rm);
            alpha[r] = __expf(mrow[r] - mn);
            mrow[r] = mn;
        }
        float psum[4] = {0.f, 0.f, 0.f, 0.f};
#pragma unroll
        for (int mt = 0; mt < 2; mt++)
#pragma unroll
            for (int nt = 0; nt < 8; nt++)
#pragma unroll
                for (int c = 0; c < 4; c++) {
                    int r = mt * 2 + (c >> 1);
                    float p = __expf(sacc[mt][nt][c] - mrow[r]);
                    sacc[mt][nt][c] = p;
                    psum[r] += p;
                }
#pragma unroll
        for (int r = 0; r < 4; r++) {
            psum[r] += __shfl_xor_sync(0xffffffffu, psum[r], 1);
            psum[r] += __shfl_xor_sync(0xffffffffu, psum[r], 2);
        }
        if (t == 0) {
#pragma unroll
            for (int r = 0; r < 4; r++) {
                int rowid = wm * 32 + (r >> 1) * 16 + (r & 1) * 8 + g;
                stats[wn * 128 + rowid] = psum[r];
            }
        }
        __syncthreads();
#pragma unroll
        for (int r = 0; r < 4; r++) {
            int rowid = wm * 32 + (r >> 1) * 16 + (r & 1) * 8 + g;
            float tot = psum[r] + stats[(wn ^ 1) * 128 + rowid];
            lrow[r] = lrow[r] * alpha[r] + tot;
        }
#pragma unroll
        for (int mt = 0; mt < 2; mt++)
#pragma unroll
            for (int nt = 0; nt < 8; nt++)
#pragma unroll
                for (int c = 0; c < 4; c++)
                    oacc[mt][nt][c] *= alpha[mt * 2 + (c >> 1)];

        // ---- O += P V ----
        const uint32_t vh_b = kb + AMAT;
#pragma unroll
        for (int ks = 0; ks < 4; ks++) {
            uint32_t ph[2][4];
#pragma unroll
            for (int mt = 0; mt < 2; mt++) {
                const float* s0 = sacc[mt][2 * ks];
                const float* s1 = sacc[mt][2 * ks + 1];
                ph[mt][0] = packh(s0[0], s0[1]);
                ph[mt][1] = packh(s0[2], s0[3]);
                ph[mt][2] = packh(s1[0], s1[1]);
                ph[mt][3] = packh(s1[2], s1[3]);
            }
#pragma unroll
            for (int dp = 0; dp < 4; dp++) {
                uint32_t vo = (uint32_t)(wn * 64 + ks * 16 + (mtx & 1) * 8 + r8) * AP +
                              (uint32_t)(dp * 16 + (mtx >> 1) * 8) * 2;
                uint32_t vh[4];
                ldsm4t(vh, vh_b + vo);
#pragma unroll
                for (int half = 0; half < 2; half++) {
                    const int nt = dp * 2 + half;
#pragma unroll
                    for (int mt = 0; mt < 2; mt++)
                        mma16816h(oacc[mt][nt], ph[mt], &vh[half * 2]);
                }
            }
        }
    }

    // ---- epilogue: sum partial O across wn pair, normalize, write fp16 ctx
    __syncthreads();
    float* Oex = (float*)smem;   // [128][64] = 32 KB
    if (wn == 1) {
#pragma unroll
        for (int mt = 0; mt < 2; mt++)
#pragma unroll
            for (int nt = 0; nt < 8; nt++)
#pragma unroll
                for (int c = 0; c < 4; c++) {
                    int row = wm * 32 + mt * 16 + (c >> 1) * 8 + g;
                    int col = nt * 8 + t * 2 + (c & 1);
                    Oex[row * 64 + col] = oacc[mt][nt][c];
                }
    }
    __syncthreads();
    if (wn == 0) {
        float inv[4];
#pragma unroll
        for (int r = 0; r < 4; r++) inv[r] = 1.0f / lrow[r];
#pragma unroll
        for (int mt = 0; mt < 2; mt++)
#pragma unroll
            for (int nt = 0; nt < 8; nt++)
#pragma unroll
                for (int hh = 0; hh < 2; hh++) {
                    int row = wm * 32 + mt * 16 + hh * 8 + g;
                    int col = nt * 8 + t * 2;
                    float v0 = (oacc[mt][nt][hh * 2 + 0] + Oex[row * 64 + col]) *
                               inv[mt * 2 + hh];
                    float v1 = (oacc[mt][nt][hh * 2 + 1] + Oex[row * 64 + col + 1]) *
                               inv[mt * 2 + hh];
                    long long dst = ((long long)(b * Ssz + q0 + row)) * Dsz +
                                    h * DKk + col;
                    *(uint32_t*)(g_ch + dst) = packh(v0, v1);
                }
    }
}

// ---------------------------------------------------------------------------
extern "C" void kernel_launch(void* const* d_in, const int* in_sizes, int n_in,
                              void* d_out, int out_size) {
    const float* x  = (const float*)d_in[0];
    const float* wq = (const float*)d_in[1];
    const float* wk = (const float*)d_in[2];
    const float* wv = (const float*)d_in[3];
    const float* wo = (const float*)d_in[4];
    const float* bo = (const float*)d_in[5];
    float* out = (float*)d_out;

    cudaFuncSetAttribute(qkv_mma_kernel,
                         cudaFuncAttributeMaxDynamicSharedMemorySize, GEMM_SMEM);
    cudaFuncSetAttribute(out_mma_kernel,
                         cudaFuncAttributeMaxDynamicSharedMemorySize, GEMM_SMEM);
    cudaFuncSetAttribute(attn_mma_kernel,
                         cudaFuncAttributeMaxDynamicSharedMemorySize, ATT_SMEM);

    unsigned short *xh, *wh;
    cudaGetSymbolAddress((void**)&xh, g_xh);
    cudaGetSymbolAddress((void**)&wh, g_wh);

    const int n4x = Mrows * Dsz / 4;
    const int n4w = Dsz * Dsz / 4;

    convert_f16_kernel<<<(n4x + 255) / 256, 256>>>(
        (const float4*)x, (uint2*)xh, n4x);
    convert_f16_kernel<<<(n4w + 255) / 256, 256>>>(
        (const float4*)wq, (uint2*)(wh + 0ll * Dsz * Dsz), n4w);
    convert_f16_kernel<<<(n4w + 255) / 256, 256>>>(
        (const float4*)wk, (uint2*)(wh + 1ll * Dsz * Dsz), n4w);
    convert_f16_kernel<<<(n4w + 255) / 256, 256>>>(
        (const float4*)wv, (uint2*)(wh + 2ll * Dsz * Dsz), n4w);
    convert_f16_kernel<<<(n4w + 255) / 256, 256>>>(
        (const float4*)wo, (uint2*)(wh + 3ll * Dsz * Dsz), n4w);

    dim3 g1(Dsz / 128, Mrows / 128, 3);
    qkv_mma_kernel<<<g1, 256, GEMM_SMEM>>>();

    dim3 g2(Ssz / 128, Bsz * Hh);
    attn_mma_kernel<<<g2, 256, ATT_SMEM>>>();

    dim3 g3(Dsz / 128, Mrows / 128);
    out_mma_kernel<<<g3, 256, GEMM_SMEM>>>(bo, out);
}

// round 15
// speedup vs baseline: 7.2185x; 1.0294x over previous
#include <cuda_runtime.h>
#include <cuda_fp16.h>
#include <math.h>
#include <cstdint>

// Problem constants
#define Bsz 4
#define Ssz 2048
#define Dsz 1024
#define Hh  16
#define DKk 64
#define Mrows (Bsz * Ssz)   // 8192

// ---------------------------------------------------------------------------
// Scratch (device globals) — plain fp16 everywhere
// ---------------------------------------------------------------------------
__device__ unsigned short g_xh[(long long)Mrows * Dsz];
__device__ unsigned short g_ch[(long long)Mrows * Dsz];
__device__ unsigned short g_wh[4ll * Dsz * Dsz];
__device__ unsigned short g_Qh[(long long)Mrows * Dsz];
__device__ unsigned short g_Kh[(long long)Mrows * Dsz];
__device__ unsigned short g_Vh[(long long)Mrows * Dsz];

// ---------------------------------------------------------------------------
// PTX helpers (portable ISA: ldmatrix / mma.sync / cp.async, sm_80+)
// ---------------------------------------------------------------------------
__device__ __forceinline__ uint32_t smem_to_u32(const void* p) {
    uint32_t a;
    asm("{ .reg .u64 t; cvta.to.shared.u64 t, %1; cvt.u32.u64 %0, t; }"
        : "=r"(a) : "l"(p));
    return a;
}
__device__ __forceinline__ void ldsm4(uint32_t* r, uint32_t addr) {
    asm volatile("ldmatrix.sync.aligned.m8n8.x4.shared.b16 {%0,%1,%2,%3}, [%4];"
                 : "=r"(r[0]), "=r"(r[1]), "=r"(r[2]), "=r"(r[3]) : "r"(addr));
}
__device__ __forceinline__ void ldsm4t(uint32_t* r, uint32_t addr) {
    asm volatile("ldmatrix.sync.aligned.m8n8.x4.trans.shared.b16 {%0,%1,%2,%3}, [%4];"
                 : "=r"(r[0]), "=r"(r[1]), "=r"(r[2]), "=r"(r[3]) : "r"(addr));
}
__device__ __forceinline__ void mma16816h(float* d, const uint32_t* a,
                                          const uint32_t* b) {
    asm volatile(
        "mma.sync.aligned.m16n8k16.row.col.f32.f16.f16.f32 "
        "{%0,%1,%2,%3}, {%4,%5,%6,%7}, {%8,%9}, {%0,%1,%2,%3};"
        : "+f"(d[0]), "+f"(d[1]), "+f"(d[2]), "+f"(d[3])
        : "r"(a[0]), "r"(a[1]), "r"(a[2]), "r"(a[3]), "r"(b[0]), "r"(b[1]));
}
__device__ __forceinline__ void cp_async16(uint32_t saddr, const void* g) {
    asm volatile("cp.async.cg.shared.global [%0], [%1], 16;"
                 :: "r"(saddr), "l"(g));
}
#define CP_COMMIT() asm volatile("cp.async.commit_group;" ::: "memory")
#define CP_WAIT0()  asm volatile("cp.async.wait_group 0;" ::: "memory")

__device__ __forceinline__ uint32_t packh(float a, float b) {
    __half2 h = __floats2half2_rn(a, b);
    return *reinterpret_cast<uint32_t*>(&h);
}

// ---------------------------------------------------------------------------
// Conversion kernels
// ---------------------------------------------------------------------------
__global__ __launch_bounds__(256)
void convert_f16_kernel(const float4* __restrict__ src,
                        uint2* __restrict__ dst, int n4) {
    int i = blockIdx.x * blockDim.x + threadIdx.x;
    if (i >= n4) return;
    float4 v = src[i];
    dst[i] = make_uint2(packh(v.x, v.y), packh(v.z, v.w));
}
// 4 weight matrices in one launch (blockIdx.y selects)
__global__ __launch_bounds__(256)
void convert_w_kernel(const float4* __restrict__ wq, const float4* __restrict__ wk,
                      const float4* __restrict__ wv, const float4* __restrict__ wo,
                      int n4) {
    int i = blockIdx.x * blockDim.x + threadIdx.x;
    if (i >= n4) return;
    const float4* srcs[4] = {wq, wk, wv, wo};
    float4 v = srcs[blockIdx.y][i];
    uint2* dst = (uint2*)(g_wh + (long long)blockIdx.y * Dsz * Dsz);
    dst[i] = make_uint2(packh(v.x, v.y), packh(v.z, v.w));
}

// ---------------------------------------------------------------------------
// Plain fp16 NT GEMM (CTA 128x128, BK=32) — unchanged from Round 14.
// ---------------------------------------------------------------------------
#define ROWB 80
#define MATB (128 * ROWB)
#define GEMM_SMEM (2 * 2 * MATB)   // 40960 B
#define NCHUNK (Dsz / 32)

__device__ __forceinline__ void gemm_mma(const unsigned short* __restrict__ Ah,
                                         const unsigned short* __restrict__ Wh,
                                         float* __restrict__ C,
                                         const float* __restrict__ bias,
                                         unsigned short* __restrict__ Dhi) {
    extern __shared__ char smem[];
    const uint32_t sbase = smem_to_u32(smem);
    const int tid = threadIdx.x;
    const int wid = tid >> 5;
    const int lane = tid & 31;
    const int wm = wid & 3;
    const int wn = wid >> 2;
    const int bm = blockIdx.y * 128;
    const int bn = blockIdx.x * 128;

    const int s0 = tid, s1 = tid + 256;
    const int r0g = s0 >> 2, c0g = (s0 & 3) * 8;
    const int r1g = s1 >> 2, c1g = (s1 & 3) * 8;

    const unsigned short* gp[2] = {Ah, Wh};
    const long long rowbase[2] = {
        (long long)(bm + r0g) * Dsz, (long long)(bn + r0g) * Dsz};
    const long long rowbase1[2] = {
        (long long)(bm + r1g) * Dsz, (long long)(bn + r1g) * Dsz};

    float acc[2][8][4] = {};

    auto load_chunk = [&](int c, int buf) {
        const int k0 = c * 32;
        const uint32_t b = sbase + buf * 2 * MATB;
#pragma unroll
        for (int m = 0; m < 2; m++) {
            cp_async16(b + m * MATB + r0g * ROWB + (s0 & 3) * 16,
                       gp[m] + rowbase[m] + k0 + c0g);
            cp_async16(b + m * MATB + r1g * ROWB + (s1 & 3) * 16,
                       gp[m] + rowbase1[m] + k0 + c1g);
        }
        CP_COMMIT();
    };

    const int mtx = lane >> 3;
    const int r8 = lane & 7;
    const int a_rowoff = (mtx & 1) * 8 + r8;
    const int a_segoff = (mtx >> 1);
    const int b_rowoff = (mtx >> 1) * 8 + r8;
    const int b_segoff = (mtx & 1);

    auto compute = [&](int buf) {
        const uint32_t ahb = sbase + buf * 2 * MATB;
        const uint32_t bhb = ahb + MATB;
#pragma unroll
        for (int ks = 0; ks < 2; ks++) {
            uint32_t ah[2][4];
#pragma unroll
            for (int mt = 0; mt < 2; mt++) {
                uint32_t ao = (uint32_t)(wm * 32 + mt * 16 + a_rowoff) * ROWB +
                              (uint32_t)(ks * 2 + a_segoff) * 16;
                ldsm4(ah[mt], ahb + ao);
            }
#pragma unroll
            for (int np = 0; np < 4; np++) {
                uint32_t bo = (uint32_t)(wn * 64 + np * 16 + b_rowoff) * ROWB +
                              (uint32_t)(ks * 2 + b_segoff) * 16;
                uint32_t bh[4];
                ldsm4(bh, bhb + bo);
#pragma unroll
                for (int half = 0; half < 2; half++) {
                    const int nt = np * 2 + half;
#pragma unroll
                    for (int mt = 0; mt < 2; mt++)
                        mma16816h(acc[mt][nt], ah[mt], &bh[half * 2]);
                }
            }
        }
    };

    load_chunk(0, 0);
    for (int c = 0; c < NCHUNK; c++) {
        CP_WAIT0();
        __syncthreads();
        if (c + 1 < NCHUNK) load_chunk(c + 1, (c + 1) & 1);
        compute(c & 1);
    }

    const int g = lane >> 2, t = lane & 3;
    if (Dhi) {
#pragma unroll
        for (int mt = 0; mt < 2; mt++) {
#pragma unroll
            for (int nt = 0; nt < 8; nt++) {
                const int col = bn + wn * 64 + nt * 8 + t * 2;
                const int hd = col >> 6, d = col & 63;
#pragma unroll
                for (int hh = 0; hh < 2; hh++) {
                    const int row = bm + wm * 32 + mt * 16 + hh * 8 + g;
                    const int b = row >> 11, s = row & 2047;
                    const long long idx =
                        ((long long)(b * Hh + hd) * Ssz + s) * DKk + d;
                    *(uint32_t*)(Dhi + idx) =
                        packh(acc[mt][nt][hh * 2 + 0], acc[mt][nt][hh * 2 + 1]);
                }
            }
        }
    } else {
#pragma unroll
        for (int mt = 0; mt < 2; mt++) {
#pragma unroll
            for (int nt = 0; nt < 8; nt++) {
                const int col = bn + wn * 64 + nt * 8 + t * 2;
                const int row0 = bm + wm * 32 + mt * 16 + g;
                float2 v0 = make_float2(acc[mt][nt][0], acc[mt][nt][1]);
                float2 v1 = make_float2(acc[mt][nt][2], acc[mt][nt][3]);
                if (bias) {
                    float2 bb = *(const float2*)(bias + col);
                    v0.x += bb.x; v0.y += bb.y;
                    v1.x += bb.x; v1.y += bb.y;
                }
                *(float2*)(C + (long long)row0 * Dsz + col) = v0;
                *(float2*)(C + (long long)(row0 + 8) * Dsz + col) = v1;
            }
        }
    }
}

__global__ __launch_bounds__(256, 2)
void qkv_mma_kernel() {
    const unsigned short* Wh = g_wh + (long long)blockIdx.z * Dsz * Dsz;
    unsigned short* Dhi = (blockIdx.z == 0) ? g_Qh : (blockIdx.z == 1) ? g_Kh : g_Vh;
    gemm_mma(g_xh, Wh, nullptr, nullptr, Dhi);
}

__global__ __launch_bounds__(256, 2)
void out_mma_kernel(const float* __restrict__ bo, float* __restrict__ out) {
    const unsigned short* Wh = g_wh + 3ll * Dsz * Dsz;
    gemm_mma(g_ch, Wh, out, bo, nullptr);
}

// ---------------------------------------------------------------------------
// Tensor-core flash attention, causal, plain fp16.
// Round 15: each warp owns 16 FULL query rows x all 128 keys ->
// warp-local softmax (no cross-warp smem/syncs), direct epilogue.
// CTA: 128 queries; 8 warps.
// ---------------------------------------------------------------------------
#define AP 144
#define AMAT (128 * AP)
#define SM_Q 0
#define SM_KV AMAT
#define KVBUF (2 * AMAT)
#define ATT_SMEM (SM_KV + 2 * KVBUF)   // 92160 B

__global__ __launch_bounds__(256)
void attn_mma_kernel() {
    extern __shared__ char smem[];
    const uint32_t sb = smem_to_u32(smem);
    const int tid = threadIdx.x;
    const int wid = tid >> 5;          // warp owns rows [wid*16, wid*16+16)
    const int lane = tid & 31;
    const int g = lane >> 2, t = lane & 3;
    const int mtx = lane >> 3, r8 = lane & 7;
    const int a_rowoff = (mtx & 1) * 8 + r8;
    const int a_segoff = (mtx >> 1);
    const int b_rowoff = (mtx >> 1) * 8 + r8;
    const int b_segoff = (mtx & 1);

    const int qb = (Ssz / 128 - 1) - blockIdx.x;
    const int q0 = qb * 128;
    const int bh = blockIdx.y;
    const int b = bh >> 4, h = bh & 15;
    const long long base = (long long)bh * Ssz * DKk;

    // Load Q (plain fp16) into smem
    for (int i = tid; i < 1024; i += 256) {
        int r = i >> 3, c = i & 7;
        *(uint4*)(smem + SM_Q + r * AP + c * 16) =
            *(const uint4*)(g_Qh + base + (long long)(q0 + r) * DKk + c * 8);
    }

    auto kv_load = [&](int kt, int buf) {
        const long long rb = base + (long long)kt * 128 * DKk;
        const unsigned short* srcs[2] = {g_Kh, g_Vh};
#pragma unroll
        for (int m = 0; m < 2; m++) {
            for (int i = tid; i < 1024; i += 256) {
                int r = i >> 3, c = i & 7;
                cp_async16(sb + SM_KV + buf * KVBUF + m * AMAT + r * AP + c * 16,
                           srcs[m] + rb + r * DKk + c * 8);
            }
        }
        CP_COMMIT();
    };
    kv_load(0, 0);

    float oacc[8][4] = {};             // 8 d-tiles x m16 frag
    float mrow[2], lrow[2];            // 2 rows per lane (g, g+8)
    mrow[0] = mrow[1] = -1e30f;
    lrow[0] = lrow[1] = 0.0f;

    const int nkt = qb + 1;
    for (int kt = 0; kt < nkt; kt++) {
        CP_WAIT0();
        __syncthreads();               // data visible to all warps; buffers safe
        if (kt + 1 < nkt) kv_load(kt + 1, (kt + 1) & 1);

        const uint32_t kb = sb + SM_KV + (kt & 1) * KVBUF;
        const uint32_t qh_b = sb + SM_Q;

        // ---- S = Q K^T : 16 n-tiles cover keys 0..127 ----
        float sacc[16][4] = {};
#pragma unroll
        for (int ks = 0; ks < 4; ks++) {
            uint32_t ah[4];
            uint32_t ao = (uint32_t)(wid * 16 + a_rowoff) * AP +
                          (uint32_t)(ks * 2 + a_segoff) * 16;
            ldsm4(ah, qh_b + ao);
#pragma unroll
            for (int np = 0; np < 8; np++) {
                uint32_t bo = (uint32_t)(np * 16 + b_rowoff) * AP +
                              (uint32_t)(ks * 2 + b_segoff) * 16;
                uint32_t kh[4];
                ldsm4(kh, kb + bo);
                mma16816h(sacc[np * 2 + 0], ah, &kh[0]);
                mma16816h(sacc[np * 2 + 1], ah, &kh[2]);
            }
        }

        // ---- scale + causal mask ----
        const bool diag = (kt == qb);
#pragma unroll
        for (int nt = 0; nt < 16; nt++)
#pragma unroll
            for (int c = 0; c < 4; c++) {
                float v = sacc[nt][c] * 0.125f;
                if (diag) {
                    int kidx = nt * 8 + t * 2 + (c & 1);
                    int qidx = wid * 16 + (c >> 1) * 8 + g;
                    if (kidx > qidx) v = -1e30f;
                }
                sacc[nt][c] = v;
            }

        // ---- warp-local online softmax (quad shuffles only) ----
        float pm[2] = {-1e30f, -1e30f};
#pragma unroll
        for (int nt = 0; nt < 16; nt++) {
            pm[0] = fmaxf(pm[0], fmaxf(sacc[nt][0], sacc[nt][1]));
            pm[1] = fmaxf(pm[1], fmaxf(sacc[nt][2], sacc[nt][3]));
        }
        float alpha[2];
#pragma unroll
        for (int r = 0; r < 2; r++) {
            pm[r] = fmaxf(pm[r], __shfl_xor_sync(0xffffffffu, pm[r], 1));
            pm[r] = fmaxf(pm[r], __shfl_xor_sync(0xffffffffu, pm[r], 2));
            float mn = fmaxf(mrow[r], pm[r]);
            alpha[r] = __expf(mrow[r] - mn);
            mrow[r] = mn;
        }
        float psum[2] = {0.f, 0.f};
#pragma unroll
        for (int nt = 0; nt < 16; nt++)
#pragma unroll
            for (int c = 0; c < 4; c++) {
                int r = c >> 1;
                float p = __expf(sacc[nt][c] - mrow[r]);
                sacc[nt][c] = p;
                psum[r] += p;
            }
#pragma unroll
        for (int r = 0; r < 2; r++) {
            psum[r] += __shfl_xor_sync(0xffffffffu, psum[r], 1);
            psum[r] += __shfl_xor_sync(0xffffffffu, psum[r], 2);
            lrow[r] = lrow[r] * alpha[r] + psum[r];
        }
#pragma unroll
        for (int nt = 0; nt < 8; nt++)
#pragma unroll
            for (int c = 0; c < 4; c++)
                oacc[nt][c] *= alpha[c >> 1];

        // ---- O += P V ----
        const uint32_t vh_b = kb + AMAT;
#pragma unroll
        for (int ks2 = 0; ks2 < 8; ks2++) {     // key chunks of 16
            uint32_t ph[4];
            const float* s0 = sacc[2 * ks2];
            const float* s1 = sacc[2 * ks2 + 1];
            ph[0] = packh(s0[0], s0[1]);
            ph[1] = packh(s0[2], s0[3]);
            ph[2] = packh(s1[0], s1[1]);
            ph[3] = packh(s1[2], s1[3]);
#pragma unroll
            for (int dp = 0; dp < 4; dp++) {
                uint32_t vo = (uint32_t)(ks2 * 16 + (mtx & 1) * 8 + r8) * AP +
                              (uint32_t)(dp * 16 + (mtx >> 1) * 8) * 2;
                uint32_t vh[4];
                ldsm4t(vh, vh_b + vo);
                mma16816h(oacc[dp * 2 + 0], ph, &vh[0]);
                mma16816h(oacc[dp * 2 + 1], ph, &vh[2]);
            }
        }
    }

    // ---- epilogue: normalize, write fp16 ctx (warp-local, no exchange) ----
    float inv[2] = {1.0f / lrow[0], 1.0f / lrow[1]};
#pragma unroll
    for (int nt = 0; nt < 8; nt++)
#pragma unroll
        for (int hh = 0; hh < 2; hh++) {
            int row = wid * 16 + hh * 8 + g;
            int col = nt * 8 + t * 2;
            float v0 = oacc[nt][hh * 2 + 0] * inv[hh];
            float v1 = oacc[nt][hh * 2 + 1] * inv[hh];
            long long dst = ((long long)(b * Ssz + q0 + row)) * Dsz +
                            h * DKk + col;
            *(uint32_t*)(g_ch + dst) = packh(v0, v1);
        }
}

// ---------------------------------------------------------------------------
extern "C" void kernel_launch(void* const* d_in, const int* in_sizes, int n_in,
                              void* d_out, int out_size) {
    const float* x  = (const float*)d_in[0];
    const float* wq = (const float*)d_in[1];
    const float* wk = (const float*)d_in[2];
    const float* wv = (const float*)d_in[3];
    const float* wo = (const float*)d_in[4];
    const float* bo = (const float*)d_in[5];
    float* out = (float*)d_out;

    cudaFuncSetAttribute(qkv_mma_kernel,
                         cudaFuncAttributeMaxDynamicSharedMemorySize, GEMM_SMEM);
    cudaFuncSetAttribute(out_mma_kernel,
                         cudaFuncAttributeMaxDynamicSharedMemorySize, GEMM_SMEM);
    cudaFuncSetAttribute(attn_mma_kernel,
                         cudaFuncAttributeMaxDynamicSharedMemorySize, ATT_SMEM);

    unsigned short* xh;
    cudaGetSymbolAddress((void**)&xh, g_xh);

    const int n4x = Mrows * Dsz / 4;
    const int n4w = Dsz * Dsz / 4;

    convert_f16_kernel<<<(n4x + 255) / 256, 256>>>(
        (const float4*)x, (uint2*)xh, n4x);
    dim3 gw((n4w + 255) / 256, 4);
    convert_w_kernel<<<gw, 256>>>((const float4*)wq, (const float4*)wk,
                                  (const float4*)wv, (const float4*)wo, n4w);

    dim3 g1(Dsz / 128, Mrows / 128, 3);
    qkv_mma_kernel<<<g1, 256, GEMM_SMEM>>>();

    dim3 g2(Ssz / 128, Bsz * Hh);
    attn_mma_kernel<<<g2, 256, ATT_SMEM>>>();

    dim3 g3(Dsz / 128, Mrows / 128);
    out_mma_kernel<<<g3, 256, GEMM_SMEM>>>(bo, out);
}

// round 16
// speedup vs baseline: 7.7870x; 1.0788x over previous
#include <cuda_runtime.h>
#include <cuda_fp16.h>
#include <math.h>
#include <cstdint>

// Problem constants
#define Bsz 4
#define Ssz 2048
#define Dsz 1024
#define Hh  16
#define DKk 64
#define Mrows (Bsz * Ssz)   // 8192

// ---------------------------------------------------------------------------
// Scratch (device globals) — plain fp16 everywhere
// ---------------------------------------------------------------------------
__device__ unsigned short g_xh[(long long)Mrows * Dsz];
__device__ unsigned short g_ch[(long long)Mrows * Dsz];
__device__ unsigned short g_wh[4ll * Dsz * Dsz];
__device__ unsigned short g_Qh[(long long)Mrows * Dsz];
__device__ unsigned short g_Kh[(long long)Mrows * Dsz];
__device__ unsigned short g_Vh[(long long)Mrows * Dsz];

// ---------------------------------------------------------------------------
// PTX helpers (portable ISA: ldmatrix / mma.sync / cp.async, sm_80+)
// ---------------------------------------------------------------------------
__device__ __forceinline__ uint32_t smem_to_u32(const void* p) {
    uint32_t a;
    asm("{ .reg .u64 t; cvta.to.shared.u64 t, %1; cvt.u32.u64 %0, t; }"
        : "=r"(a) : "l"(p));
    return a;
}
__device__ __forceinline__ void ldsm4(uint32_t* r, uint32_t addr) {
    asm volatile("ldmatrix.sync.aligned.m8n8.x4.shared.b16 {%0,%1,%2,%3}, [%4];"
                 : "=r"(r[0]), "=r"(r[1]), "=r"(r[2]), "=r"(r[3]) : "r"(addr));
}
__device__ __forceinline__ void ldsm4t(uint32_t* r, uint32_t addr) {
    asm volatile("ldmatrix.sync.aligned.m8n8.x4.trans.shared.b16 {%0,%1,%2,%3}, [%4];"
                 : "=r"(r[0]), "=r"(r[1]), "=r"(r[2]), "=r"(r[3]) : "r"(addr));
}
__device__ __forceinline__ void mma16816h(float* d, const uint32_t* a,
                                          const uint32_t* b) {
    asm volatile(
        "mma.sync.aligned.m16n8k16.row.col.f32.f16.f16.f32 "
        "{%0,%1,%2,%3}, {%4,%5,%6,%7}, {%8,%9}, {%0,%1,%2,%3};"
        : "+f"(d[0]), "+f"(d[1]), "+f"(d[2]), "+f"(d[3])
        : "r"(a[0]), "r"(a[1]), "r"(a[2]), "r"(a[3]), "r"(b[0]), "r"(b[1]));
}
__device__ __forceinline__ void cp_async16(uint32_t saddr, const void* g) {
    asm volatile("cp.async.cg.shared.global [%0], [%1], 16;"
                 :: "r"(saddr), "l"(g));
}
#define CP_COMMIT() asm volatile("cp.async.commit_group;" ::: "memory")
#define CP_WAIT0()  asm volatile("cp.async.wait_group 0;" ::: "memory")

__device__ __forceinline__ uint32_t packh(float a, float b) {
    __half2 h = __floats2half2_rn(a, b);
    return *reinterpret_cast<uint32_t*>(&h);
}

// ---------------------------------------------------------------------------
// Conversion kernels
// ---------------------------------------------------------------------------
__global__ __launch_bounds__(256)
void convert_f16_kernel(const float4* __restrict__ src,
                        uint2* __restrict__ dst, int n4) {
    int i = blockIdx.x * blockDim.x + threadIdx.x;
    if (i >= n4) return;
    float4 v = src[i];
    dst[i] = make_uint2(packh(v.x, v.y), packh(v.z, v.w));
}
__global__ __launch_bounds__(256)
void convert_w_kernel(const float4* __restrict__ wq, const float4* __restrict__ wk,
                      const float4* __restrict__ wv, const float4* __restrict__ wo,
                      int n4) {
    int i = blockIdx.x * blockDim.x + threadIdx.x;
    if (i >= n4) return;
    const float4* srcs[4] = {wq, wk, wv, wo};
    float4 v = srcs[blockIdx.y][i];
    uint2* dst = (uint2*)(g_wh + (long long)blockIdx.y * Dsz * Dsz);
    dst[i] = make_uint2(packh(v.x, v.y), packh(v.z, v.w));
}

// ---------------------------------------------------------------------------
// Plain fp16 NT GEMM (CTA 128x128, BK=32) — unchanged.
// ---------------------------------------------------------------------------
#define ROWB 80
#define MATB (128 * ROWB)
#define GEMM_SMEM (2 * 2 * MATB)   // 40960 B
#define NCHUNK (Dsz / 32)

__device__ __forceinline__ void gemm_mma(const unsigned short* __restrict__ Ah,
                                         const unsigned short* __restrict__ Wh,
                                         float* __restrict__ C,
                                         const float* __restrict__ bias,
                                         unsigned short* __restrict__ Dhi) {
    extern __shared__ char smem[];
    const uint32_t sbase = smem_to_u32(smem);
    const int tid = threadIdx.x;
    const int wid = tid >> 5;
    const int lane = tid & 31;
    const int wm = wid & 3;
    const int wn = wid >> 2;
    const int bm = blockIdx.y * 128;
    const int bn = blockIdx.x * 128;

    const int s0 = tid, s1 = tid + 256;
    const int r0g = s0 >> 2, c0g = (s0 & 3) * 8;
    const int r1g = s1 >> 2, c1g = (s1 & 3) * 8;

    const unsigned short* gp[2] = {Ah, Wh};
    const long long rowbase[2] = {
        (long long)(bm + r0g) * Dsz, (long long)(bn + r0g) * Dsz};
    const long long rowbase1[2] = {
        (long long)(bm + r1g) * Dsz, (long long)(bn + r1g) * Dsz};

    float acc[2][8][4] = {};

    auto load_chunk = [&](int c, int buf) {
        const int k0 = c * 32;
        const uint32_t b = sbase + buf * 2 * MATB;
#pragma unroll
        for (int m = 0; m < 2; m++) {
            cp_async16(b + m * MATB + r0g * ROWB + (s0 & 3) * 16,
                       gp[m] + rowbase[m] + k0 + c0g);
            cp_async16(b + m * MATB + r1g * ROWB + (s1 & 3) * 16,
                       gp[m] + rowbase1[m] + k0 + c1g);
        }
        CP_COMMIT();
    };

    const int mtx = lane >> 3;
    const int r8 = lane & 7;
    const int a_rowoff = (mtx & 1) * 8 + r8;
    const int a_segoff = (mtx >> 1);
    const int b_rowoff = (mtx >> 1) * 8 + r8;
    const int b_segoff = (mtx & 1);

    auto compute = [&](int buf) {
        const uint32_t ahb = sbase + buf * 2 * MATB;
        const uint32_t bhb = ahb + MATB;
#pragma unroll
        for (int ks = 0; ks < 2; ks++) {
            uint32_t ah[2][4];
#pragma unroll
            for (int mt = 0; mt < 2; mt++) {
                uint32_t ao = (uint32_t)(wm * 32 + mt * 16 + a_rowoff) * ROWB +
                              (uint32_t)(ks * 2 + a_segoff) * 16;
                ldsm4(ah[mt], ahb + ao);
            }
#pragma unroll
            for (int np = 0; np < 4; np++) {
                uint32_t bo = (uint32_t)(wn * 64 + np * 16 + b_rowoff) * ROWB +
                              (uint32_t)(ks * 2 + b_segoff) * 16;
                uint32_t bh[4];
                ldsm4(bh, bhb + bo);
#pragma unroll
                for (int half = 0; half < 2; half++) {
                    const int nt = np * 2 + half;
#pragma unroll
                    for (int mt = 0; mt < 2; mt++)
                        mma16816h(acc[mt][nt], ah[mt], &bh[half * 2]);
                }
            }
        }
    };

    load_chunk(0, 0);
    for (int c = 0; c < NCHUNK; c++) {
        CP_WAIT0();
        __syncthreads();
        if (c + 1 < NCHUNK) load_chunk(c + 1, (c + 1) & 1);
        compute(c & 1);
    }

    const int g = lane >> 2, t = lane & 3;
    if (Dhi) {
#pragma unroll
        for (int mt = 0; mt < 2; mt++) {
#pragma unroll
            for (int nt = 0; nt < 8; nt++) {
                const int col = bn + wn * 64 + nt * 8 + t * 2;
                const int hd = col >> 6, d = col & 63;
#pragma unroll
                for (int hh = 0; hh < 2; hh++) {
                    const int row = bm + wm * 32 + mt * 16 + hh * 8 + g;
                    const int b = row >> 11, s = row & 2047;
                    const long long idx =
                        ((long long)(b * Hh + hd) * Ssz + s) * DKk + d;
                    *(uint32_t*)(Dhi + idx) =
                        packh(acc[mt][nt][hh * 2 + 0], acc[mt][nt][hh * 2 + 1]);
                }
            }
        }
    } else {
#pragma unroll
        for (int mt = 0; mt < 2; mt++) {
#pragma unroll
            for (int nt = 0; nt < 8; nt++) {
                const int col = bn + wn * 64 + nt * 8 + t * 2;
                const int row0 = bm + wm * 32 + mt * 16 + g;
                float2 v0 = make_float2(acc[mt][nt][0], acc[mt][nt][1]);
                float2 v1 = make_float2(acc[mt][nt][2], acc[mt][nt][3]);
                if (bias) {
                    float2 bb = *(const float2*)(bias + col);
                    v0.x += bb.x; v0.y += bb.y;
                    v1.x += bb.x; v1.y += bb.y;
                }
                *(float2*)(C + (long long)row0 * Dsz + col) = v0;
                *(float2*)(C + (long long)(row0 + 8) * Dsz + col) = v1;
            }
        }
    }
}

__global__ __launch_bounds__(256, 2)
void qkv_mma_kernel() {
    const unsigned short* Wh = g_wh + (long long)blockIdx.z * Dsz * Dsz;
    unsigned short* Dhi = (blockIdx.z == 0) ? g_Qh : (blockIdx.z == 1) ? g_Kh : g_Vh;
    gemm_mma(g_xh, Wh, nullptr, nullptr, Dhi);
}

__global__ __launch_bounds__(256, 2)
void out_mma_kernel(const float* __restrict__ bo, float* __restrict__ out) {
    const unsigned short* Wh = g_wh + 3ll * Dsz * Dsz;
    gemm_mma(g_ch, Wh, out, bo, nullptr);
}

// ---------------------------------------------------------------------------
// Tensor-core flash attention, causal, plain fp16. Warp owns 16 query rows.
// Round 16: early P->fp16 pack (kills sacc liveness in PV phase) +
// __launch_bounds__(256,2) -> <=128 regs -> 2 CTAs/SM.
// ---------------------------------------------------------------------------
#define AP 144
#define AMAT (128 * AP)
#define SM_Q 0
#define SM_KV AMAT
#define KVBUF (2 * AMAT)
#define ATT_SMEM (SM_KV + 2 * KVBUF)   // 92160 B

__global__ __launch_bounds__(256, 2)
void attn_mma_kernel() {
    extern __shared__ char smem[];
    const uint32_t sb = smem_to_u32(smem);
    const int tid = threadIdx.x;
    const int wid = tid >> 5;          // warp owns rows [wid*16, wid*16+16)
    const int lane = tid & 31;
    const int g = lane >> 2, t = lane & 3;
    const int mtx = lane >> 3, r8 = lane & 7;
    const int a_rowoff = (mtx & 1) * 8 + r8;
    const int a_segoff = (mtx >> 1);
    const int b_rowoff = (mtx >> 1) * 8 + r8;
    const int b_segoff = (mtx & 1);

    const int qb = (Ssz / 128 - 1) - blockIdx.x;
    const int q0 = qb * 128;
    const int bh = blockIdx.y;
    const int b = bh >> 4, h = bh & 15;
    const long long base = (long long)bh * Ssz * DKk;

    // Load Q (plain fp16) into smem
    for (int i = tid; i < 1024; i += 256) {
        int r = i >> 3, c = i & 7;
        *(uint4*)(smem + SM_Q + r * AP + c * 16) =
            *(const uint4*)(g_Qh + base + (long long)(q0 + r) * DKk + c * 8);
    }

    auto kv_load = [&](int kt, int buf) {
        const long long rb = base + (long long)kt * 128 * DKk;
        const unsigned short* srcs[2] = {g_Kh, g_Vh};
#pragma unroll
        for (int m = 0; m < 2; m++) {
            for (int i = tid; i < 1024; i += 256) {
                int r = i >> 3, c = i & 7;
                cp_async16(sb + SM_KV + buf * KVBUF + m * AMAT + r * AP + c * 16,
                           srcs[m] + rb + r * DKk + c * 8);
            }
        }
        CP_COMMIT();
    };
    kv_load(0, 0);

    float oacc[8][4] = {};
    float mrow[2], lrow[2];
    mrow[0] = mrow[1] = -1e30f;
    lrow[0] = lrow[1] = 0.0f;

    const int nkt = qb + 1;
    for (int kt = 0; kt < nkt; kt++) {
        CP_WAIT0();
        __syncthreads();
        if (kt + 1 < nkt) kv_load(kt + 1, (kt + 1) & 1);

        const uint32_t kb = sb + SM_KV + (kt & 1) * KVBUF;
        const uint32_t qh_b = sb + SM_Q;

        // ---- S = Q K^T : 16 n-tiles cover keys 0..127 ----
        float sacc[16][4] = {};
#pragma unroll
        for (int ks = 0; ks < 4; ks++) {
            uint32_t ah[4];
            uint32_t ao = (uint32_t)(wid * 16 + a_rowoff) * AP +
                          (uint32_t)(ks * 2 + a_segoff) * 16;
            ldsm4(ah, qh_b + ao);
#pragma unroll
            for (int np = 0; np < 8; np++) {
                uint32_t bo = (uint32_t)(np * 16 + b_rowoff) * AP +
                              (uint32_t)(ks * 2 + b_segoff) * 16;
                uint32_t kh[4];
                ldsm4(kh, kb + bo);
                mma16816h(sacc[np * 2 + 0], ah, &kh[0]);
                mma16816h(sacc[np * 2 + 1], ah, &kh[2]);
            }
        }

        // ---- scale + causal mask ----
        const bool diag = (kt == qb);
#pragma unroll
        for (int nt = 0; nt < 16; nt++)
#pragma unroll
            for (int c = 0; c < 4; c++) {
                float v = sacc[nt][c] * 0.125f;
                if (diag) {
                    int kidx = nt * 8 + t * 2 + (c & 1);
                    int qidx = wid * 16 + (c >> 1) * 8 + g;
                    if (kidx > qidx) v = -1e30f;
                }
                sacc[nt][c] = v;
            }

        // ---- warp-local row max ----
        float pm[2] = {-1e30f, -1e30f};
#pragma unroll
        for (int nt = 0; nt < 16; nt++) {
            pm[0] = fmaxf(pm[0], fmaxf(sacc[nt][0], sacc[nt][1]));
            pm[1] = fmaxf(pm[1], fmaxf(sacc[nt][2], sacc[nt][3]));
        }
        float alpha[2];
#pragma unroll
        for (int r = 0; r < 2; r++) {
            pm[r] = fmaxf(pm[r], __shfl_xor_sync(0xffffffffu, pm[r], 1));
            pm[r] = fmaxf(pm[r], __shfl_xor_sync(0xffffffffu, pm[r], 2));
            float mn = fmaxf(mrow[r], pm[r]);
            alpha[r] = __expf(mrow[r] - mn);
            mrow[r] = mn;
        }

        // ---- exp + row sum + immediate fp16 pack (kills sacc liveness) ----
        uint32_t ph[8][4];
        float psum[2] = {0.f, 0.f};
#pragma unroll
        for (int c2 = 0; c2 < 8; c2++) {
            float p00 = __expf(sacc[2 * c2 + 0][0] - mrow[0]);
            float p01 = __expf(sacc[2 * c2 + 0][1] - mrow[0]);
            float p02 = __expf(sacc[2 * c2 + 0][2] - mrow[1]);
            float p03 = __expf(sacc[2 * c2 + 0][3] - mrow[1]);
            float p10 = __expf(sacc[2 * c2 + 1][0] - mrow[0]);
            float p11 = __expf(sacc[2 * c2 + 1][1] - mrow[0]);
            float p12 = __expf(sacc[2 * c2 + 1][2] - mrow[1]);
            float p13 = __expf(sacc[2 * c2 + 1][3] - mrow[1]);
            psum[0] += (p00 + p01) + (p10 + p11);
            psum[1] += (p02 + p03) + (p12 + p13);
            ph[c2][0] = packh(p00, p01);
            ph[c2][1] = packh(p02, p03);
            ph[c2][2] = packh(p10, p11);
            ph[c2][3] = packh(p12, p13);
        }
#pragma unroll
        for (int r = 0; r < 2; r++) {
            psum[r] += __shfl_xor_sync(0xffffffffu, psum[r], 1);
            psum[r] += __shfl_xor_sync(0xffffffffu, psum[r], 2);
            lrow[r] = lrow[r] * alpha[r] + psum[r];
        }
#pragma unroll
        for (int nt = 0; nt < 8; nt++)
#pragma unroll
            for (int c = 0; c < 4; c++)
                oacc[nt][c] *= alpha[c >> 1];

        // ---- O += P V ----
        const uint32_t vh_b = kb + AMAT;
#pragma unroll
        for (int ks2 = 0; ks2 < 8; ks2++) {
#pragma unroll
            for (int dp = 0; dp < 4; dp++) {
                uint32_t vo = (uint32_t)(ks2 * 16 + (mtx & 1) * 8 + r8) * AP +
                              (uint32_t)(dp * 16 + (mtx >> 1) * 8) * 2;
                uint32_t vh[4];
                ldsm4t(vh, vh_b + vo);
                mma16816h(oacc[dp * 2 + 0], ph[ks2], &vh[0]);
                mma16816h(oacc[dp * 2 + 1], ph[ks2], &vh[2]);
            }
        }
    }

    // ---- epilogue: normalize, write fp16 ctx ----
    float inv[2] = {1.0f / lrow[0], 1.0f / lrow[1]};
#pragma unroll
    for (int nt = 0; nt < 8; nt++)
#pragma unroll
        for (int hh = 0; hh < 2; hh++) {
            int row = wid * 16 + hh * 8 + g;
            int col = nt * 8 + t * 2;
            float v0 = oacc[nt][hh * 2 + 0] * inv[hh];
            float v1 = oacc[nt][hh * 2 + 1] * inv[hh];
            long long dst = ((long long)(b * Ssz + q0 + row)) * Dsz +
                            h * DKk + col;
            *(uint32_t*)(g_ch + dst) = packh(v0, v1);
        }
}

// ---------------------------------------------------------------------------
extern "C" void kernel_launch(void* const* d_in, const int* in_sizes, int n_in,
                              void* d_out, int out_size) {
    const float* x  = (const float*)d_in[0];
    const float* wq = (const float*)d_in[1];
    const float* wk = (const float*)d_in[2];
    const float* wv = (const float*)d_in[3];
    const float* wo = (const float*)d_in[4];
    const float* bo = (const float*)d_in[5];
    float* out = (float*)d_out;

    cudaFuncSetAttribute(qkv_mma_kernel,
                         cudaFuncAttributeMaxDynamicSharedMemorySize, GEMM_SMEM);
    cudaFuncSetAttribute(out_mma_kernel,
                         cudaFuncAttributeMaxDynamicSharedMemorySize, GEMM_SMEM);
    cudaFuncSetAttribute(attn_mma_kernel,
                         cudaFuncAttributeMaxDynamicSharedMemorySize, ATT_SMEM);

    unsigned short* xh;
    cudaGetSymbolAddress((void**)&xh, g_xh);

    const int n4x = Mrows * Dsz / 4;
    const int n4w = Dsz * Dsz / 4;

    convert_f16_kernel<<<(n4x + 255) / 256, 256>>>(
        (const float4*)x, (uint2*)xh, n4x);
    dim3 gw((n4w + 255) / 256, 4);
    convert_w_kernel<<<gw, 256>>>((const float4*)wq, (const float4*)wk,
                                  (const float4*)wv, (const float4*)wo, n4w);

    dim3 g1(Dsz / 128, Mrows / 128, 3);
    qkv_mma_kernel<<<g1, 256, GEMM_SMEM>>>();

    dim3 g2(Ssz / 128, Bsz * Hh);
    attn_mma_kernel<<<g2, 256, ATT_SMEM>>>();

    dim3 g3(Dsz / 128, Mrows / 128);
    out_mma_kernel<<<g3, 256, GEMM_SMEM>>>(bo, out);
}